// round 4
// baseline (speedup 1.0000x reference)
#include <cuda_runtime.h>
#include <cuda_bf16.h>
#include <math.h>

#define Hd    1024
#define SEQ   256
#define NB    32
#define NROWS (NB*SEQ)     // 8192
#define MHID  4096
#define DEPTH 12

// ---------------- device scratch (no allocations allowed) ----------------
__device__ float g_x   [NROWS*Hd];
__device__ float g_xm  [NROWS*Hd];
__device__ float g_qkv [NROWS*3*Hd];
__device__ float g_attn[NROWS*Hd];
__device__ float g_mlp [NROWS*MHID];
__device__ float g_cm  [NB*6*Hd];
__device__ float g_cm2 [NB*2*Hd];
__device__ float g_te1 [NB*Hd];
__device__ float g_sc  [NB*Hd];

__device__ __forceinline__ float siluf(float x){ return x / (1.f + expf(-x)); }
__device__ __forceinline__ float geluf(float x){
  float t = 0.7978845608028654f * (x + 0.044715f * x*x*x);
  return 0.5f * x * (1.f + tanhf(t));
}

// ---------------- patch embed + 2D sincos pos ----------------
__global__ void __launch_bounds__(256) k_patch(const float* __restrict__ x,
                                               const float* __restrict__ pW,
                                               float* __restrict__ XT)
{
  int row = blockIdx.x;            // token row 0..8191
  int b = row >> 8, n = row & 255;
  int ph = n >> 4, pw = n & 15;
  __shared__ float xp[16];
  if (threadIdx.x < 16) {
    int f = threadIdx.x;
    int dy = f >> 3, dx = (f >> 2) & 1, c = f & 3;
    xp[f] = x[((b*32 + ph*2 + dy)*32 + (pw*2 + dx))*4 + c];
  }
  __syncthreads();
  #pragma unroll
  for (int i = 0; i < 4; ++i) {
    int col = threadIdx.x + i*256;
    float acc = 0.f;
    #pragma unroll
    for (int k = 0; k < 16; ++k) acc += xp[k] * pW[k*Hd + col];
    int j = col & 255, seg = col >> 8;
    float fr = expf(-logf(10000.f) * (float)j * (1.f/256.f));
    float a  = (seg < 2 ? (float)pw : (float)ph) * fr;
    float pos = ((seg & 1) == 0) ? sinf(a) : cosf(a);
    XT[(size_t)row*Hd + col] = acc + pos;
  }
}

// ---------------- timestep embed: te1 = silu(temb @ t_W1) ----------------
__global__ void __launch_bounds__(256) k_temb(const float* __restrict__ t,
                                              const float* __restrict__ W1,
                                              float* __restrict__ TE1)
{
  int b = blockIdx.x, tid = threadIdx.x;
  __shared__ float e[256];
  {
    int j = tid & 127;
    float fr = expf(-logf(10000.f) * (float)j * (1.f/128.f));
    float a = t[b] * fr;
    e[tid] = (tid < 128 ? cosf(a) : sinf(a)) * 1.41421356237f;
  }
  __syncthreads();
  #pragma unroll
  for (int i = 0; i < 4; ++i) {
    int col = tid + i*256;
    float acc = 0.f;
    for (int k = 0; k < 256; ++k) acc += e[k] * W1[k*Hd + col];
    TE1[b*Hd + col] = siluf(acc);
  }
}

// ---------------- c = te1 @ t_W2 + y_table[y]; store silu(c) ----------------
__global__ void __launch_bounds__(256) k_cfinal(const float* __restrict__ TE1,
                                                const float* __restrict__ W2,
                                                const float* __restrict__ ytab,
                                                const int* __restrict__ y,
                                                float* __restrict__ SCout)
{
  int b = blockIdx.x, tid = threadIdx.x;
  __shared__ float a[Hd];
  for (int k = tid; k < Hd; k += 256) a[k] = TE1[b*Hd + k];
  __syncthreads();
  int yi = y[b];
  #pragma unroll
  for (int i = 0; i < 4; ++i) {
    int col = tid + i*256;
    float acc = 0.f;
    for (int k = 0; k < Hd; ++k) acc += a[k] * W2[k*Hd + col];
    float c = acc + ytab[(size_t)yi*Hd + col];
    SCout[b*Hd + col] = siluf(c);
  }
}

// ---------------- conditioning GEMM: OUT[b,:] = silu_c[b,:] @ W (+bias) ----------------
__global__ void __launch_bounds__(256) k_cond(const float* __restrict__ SC,
                                              const float* __restrict__ W,
                                              const float* __restrict__ bias,
                                              float* __restrict__ OUT, int N)
{
  int b = blockIdx.y;
  int c0 = blockIdx.x*1024 + threadIdx.x;
  __shared__ float a[Hd];
  for (int k = threadIdx.x; k < Hd; k += 256) a[k] = SC[b*Hd + k];
  __syncthreads();
  float acc[4] = {0.f, 0.f, 0.f, 0.f};
  for (int k = 0; k < Hd; ++k) {
    float av = a[k];
    const float* wr = W + (size_t)k*N + c0;
    #pragma unroll
    for (int i = 0; i < 4; ++i) acc[i] += av * wr[i*256];
  }
  #pragma unroll
  for (int i = 0; i < 4; ++i) {
    int c = c0 + i*256;
    OUT[(size_t)b*N + c] = acc[i] + (bias ? bias[c] : 0.f);
  }
}

// ---------------- LN + modulate: Y = LN(X)*cm[b,scOff+..] + cm[b,shOff+..] ----------------
__global__ void __launch_bounds__(256) k_lnmod(const float* __restrict__ X,
                                               float* __restrict__ Y,
                                               const float* __restrict__ cm,
                                               int shOff, int scOff)
{
  int row = blockIdx.x, b = row >> 8, tid = threadIdx.x;
  const float* x = X + (size_t)row*Hd;
  float v[4]; float s = 0.f, s2 = 0.f;
  #pragma unroll
  for (int i = 0; i < 4; ++i) { float t = x[tid + i*256]; v[i] = t; s += t; s2 += t*t; }
  #pragma unroll
  for (int o = 16; o; o >>= 1) {
    s  += __shfl_xor_sync(0xffffffffu, s,  o);
    s2 += __shfl_xor_sync(0xffffffffu, s2, o);
  }
  __shared__ float ss[8], ss2[8];
  if ((tid & 31) == 0) { ss[tid>>5] = s; ss2[tid>>5] = s2; }
  __syncthreads();
  s = 0.f; s2 = 0.f;
  #pragma unroll
  for (int w = 0; w < 8; ++w) { s += ss[w]; s2 += ss2[w]; }
  float mean = s * (1.f/1024.f);
  float var  = s2 * (1.f/1024.f) - mean*mean;
  float r = rsqrtf(var + 1e-6f);
  const float* cb = cm + b*6*Hd;
  #pragma unroll
  for (int i = 0; i < 4; ++i) {
    int col = tid + i*256;
    Y[(size_t)row*Hd + col] = (v[i]-mean)*r*cb[scOff+col] + cb[shOff+col];
  }
}

// ---------------- main SGEMM: C[8192,N] (+epi) = A[8192,K] @ B[K,N] ----------------
// mode 0: C=acc   mode 1: C=gelu(acc)   mode 2: C += gate[b,col]*acc  (gate stride 6*Hd)
__global__ void __launch_bounds__(256) k_gemm(const float* __restrict__ A,
                                              const float* __restrict__ Bw,
                                              float* __restrict__ C, int K, int N,
                                              int mode, const float* __restrict__ gate)
{
  __shared__ float As[2][8][128];
  __shared__ float Bs[2][8][128];
  int tid = threadIdx.x;
  const float* Ab = A + (size_t)blockIdx.y*128*K;
  const float* Bb = Bw + blockIdx.x*128;
  int ar = tid >> 1, ac = (tid & 1) << 2;     // A: 128 rows x 8 k
  int bk = tid >> 5, bc = (tid & 31) << 2;    // B: 8 k x 128 cols
  int tx = tid & 15, ty = tid >> 4;
  float acc[8][8];
  #pragma unroll
  for (int i = 0; i < 8; ++i)
    #pragma unroll
    for (int j = 0; j < 8; ++j) acc[i][j] = 0.f;

  float4 av = *(const float4*)(Ab + (size_t)ar*K + ac);
  float4 bv = *(const float4*)(Bb + (size_t)bk*N + bc);
  As[0][ac+0][ar] = av.x; As[0][ac+1][ar] = av.y;
  As[0][ac+2][ar] = av.z; As[0][ac+3][ar] = av.w;
  *(float4*)&Bs[0][bk][bc] = bv;
  __syncthreads();

  int nk = K >> 3;
  for (int kt = 0; kt < nk; ++kt) {
    int cur = kt & 1;
    if (kt + 1 < nk) {
      av = *(const float4*)(Ab + (size_t)ar*K + ((kt+1)<<3) + ac);
      bv = *(const float4*)(Bb + (size_t)(((kt+1)<<3) + bk)*N + bc);
    }
    #pragma unroll
    for (int k = 0; k < 8; ++k) {
      float4 a0 = *(const float4*)&As[cur][k][ty*8];
      float4 a1 = *(const float4*)&As[cur][k][ty*8+4];
      float4 b0 = *(const float4*)&Bs[cur][k][tx*8];
      float4 b1 = *(const float4*)&Bs[cur][k][tx*8+4];
      float af[8] = {a0.x,a0.y,a0.z,a0.w,a1.x,a1.y,a1.z,a1.w};
      float bf[8] = {b0.x,b0.y,b0.z,b0.w,b1.x,b1.y,b1.z,b1.w};
      #pragma unroll
      for (int i = 0; i < 8; ++i)
        #pragma unroll
        for (int j = 0; j < 8; ++j) acc[i][j] += af[i]*bf[j];
    }
    if (kt + 1 < nk) {
      int nxt = cur ^ 1;
      As[nxt][ac+0][ar] = av.x; As[nxt][ac+1][ar] = av.y;
      As[nxt][ac+2][ar] = av.z; As[nxt][ac+3][ar] = av.w;
      *(float4*)&Bs[nxt][bk][bc] = bv;
      __syncthreads();
    }
  }

  int rb = blockIdx.y*128 + ty*8;
  int cb = blockIdx.x*128 + tx*8;
  if (mode == 0) {
    #pragma unroll
    for (int i = 0; i < 8; ++i) {
      float* cr = C + (size_t)(rb+i)*N + cb;
      #pragma unroll
      for (int j = 0; j < 8; ++j) cr[j] = acc[i][j];
    }
  } else if (mode == 1) {
    #pragma unroll
    for (int i = 0; i < 8; ++i) {
      float* cr = C + (size_t)(rb+i)*N + cb;
      #pragma unroll
      for (int j = 0; j < 8; ++j) cr[j] = geluf(acc[i][j]);
    }
  } else {
    #pragma unroll
    for (int i = 0; i < 8; ++i) {
      int r = rb + i; int b = r >> 8;
      const float* g = gate + (size_t)b*6*Hd;
      float* cr = C + (size_t)r*N + cb;
      #pragma unroll
      for (int j = 0; j < 8; ++j) cr[j] += g[cb+j]*acc[i][j];
    }
  }
}

// ---------------- attention: one CTA per (head, batch), flash over K ----------------
__global__ void __launch_bounds__(256) k_attn(const float* __restrict__ QKV,
                                              float* __restrict__ O)
{
  extern __shared__ float sm[];
  float* Ks = sm;                 // [256][64]
  float* Vs = sm + 256*64;        // [256][64]
  int hd = blockIdx.x, b = blockIdx.y;
  const float* base = QKV + (size_t)b*SEQ*3*Hd + hd*64;
  for (int i = threadIdx.x; i < 256*16; i += 256) {
    int r = i >> 4, d4 = (i & 15) << 2;
    *(float4*)&Ks[r*64 + d4] = *(const float4*)(base + (size_t)r*3*Hd + d4);        // k @ 0
    *(float4*)&Vs[r*64 + d4] = *(const float4*)(base + (size_t)r*3*Hd + 2*Hd + d4); // v @ 2h
  }
  int qi = threadIdx.x;
  float q[64];
  const float* qp = base + (size_t)qi*3*Hd + Hd;                                    // q @ h
  #pragma unroll
  for (int d = 0; d < 64; ++d) q[d] = qp[d]*0.125f;
  __syncthreads();
  float o[64];
  #pragma unroll
  for (int d = 0; d < 64; ++d) o[d] = 0.f;
  float m = -1e30f, l = 0.f;
  for (int k = 0; k < 256; ++k) {
    const float* kr = &Ks[k*64];
    float s = 0.f;
    #pragma unroll
    for (int d = 0; d < 64; ++d) s += q[d]*kr[d];
    float mn = fmaxf(m, s);
    float corr = expf(m - mn);
    float p = expf(s - mn);
    l = l*corr + p;
    const float* vr = &Vs[k*64];
    #pragma unroll
    for (int d = 0; d < 64; ++d) o[d] = o[d]*corr + p*vr[d];
    m = mn;
  }
  float inv = 1.f / l;
  float* op = O + (size_t)(b*SEQ + qi)*Hd + hd*64;
  #pragma unroll
  for (int d = 0; d < 64; ++d) op[d] = o[d]*inv;
}

// ---------------- final: LN+modulate, @ out_W + b, unpatchify ----------------
__global__ void __launch_bounds__(256) k_out(const float* __restrict__ X,
                                             const float* __restrict__ cm2,
                                             const float* __restrict__ oW,
                                             const float* __restrict__ ob,
                                             float* __restrict__ out)
{
  int row = blockIdx.x, b = row >> 8, n = row & 255, tid = threadIdx.x;
  const float* xr = X + (size_t)row*Hd;
  float v[4]; float s = 0.f, s2 = 0.f;
  #pragma unroll
  for (int i = 0; i < 4; ++i) { float t = xr[tid + i*256]; v[i] = t; s += t; s2 += t*t; }
  #pragma unroll
  for (int o = 16; o; o >>= 1) {
    s  += __shfl_xor_sync(0xffffffffu, s,  o);
    s2 += __shfl_xor_sync(0xffffffffu, s2, o);
  }
  __shared__ float ss[8], ss2[8];
  if ((tid & 31) == 0) { ss[tid>>5] = s; ss2[tid>>5] = s2; }
  __syncthreads();
  s = 0.f; s2 = 0.f;
  #pragma unroll
  for (int w = 0; w < 8; ++w) { s += ss[w]; s2 += ss2[w]; }
  float mean = s*(1.f/1024.f), var = s2*(1.f/1024.f) - mean*mean;
  float r = rsqrtf(var + 1e-6f);
  __shared__ float xm[Hd];
  const float* c2 = cm2 + b*2*Hd;
  #pragma unroll
  for (int i = 0; i < 4; ++i) {
    int col = tid + i*256;
    xm[col] = (v[i]-mean)*r*c2[Hd+col] + c2[col];
  }
  __syncthreads();
  int oi = tid >> 4, part = tid & 15;
  float acc = 0.f;
  const float* xp = xm + part*64;
  #pragma unroll
  for (int k = 0; k < 64; ++k) acc += xp[k]*oW[(part*64 + k)*16 + oi];
  __shared__ float red[256];
  red[tid] = acc;
  __syncthreads();
  if (part == 0) {
    float sum = 0.f;
    #pragma unroll
    for (int p = 0; p < 16; ++p) sum += red[oi*16 + p];
    sum += ob[oi];
    int ph = n >> 4, pw = n & 15;
    int p1 = oi >> 3, p2 = (oi >> 2) & 1, c = oi & 3;
    out[((b*32 + ph*2 + p1)*32 + (pw*2 + p2))*4 + c] = sum;
  }
}

// ---------------- host ----------------
extern "C" void kernel_launch(void* const* d_in, const int* in_sizes, int n_in,
                              void* d_out, int out_size)
{
  const float* x        = (const float*)d_in[0];
  const float* t        = (const float*)d_in[1];
  const int*   y        = (const int*)  d_in[2];
  const float* patch_W  = (const float*)d_in[3];
  const float* y_table  = (const float*)d_in[4];
  const float* t_W1     = (const float*)d_in[5];
  const float* t_W2     = (const float*)d_in[6];
  const float* adaln_W  = (const float*)d_in[7];
  const float* qkv_W    = (const float*)d_in[8];
  const float* proj_W   = (const float*)d_in[9];
  const float* mlp1_W   = (const float*)d_in[10];
  const float* mlp2_W   = (const float*)d_in[11];
  const float* out_mod_W= (const float*)d_in[12];
  const float* out_mod_b= (const float*)d_in[13];
  const float* out_W    = (const float*)d_in[14];
  const float* out_b    = (const float*)d_in[15];
  float* out = (float*)d_out;

  float *px, *pxm, *pqkv, *pattn, *pmlp, *pcm, *pcm2, *pte1, *psc;
  cudaGetSymbolAddress((void**)&px,   g_x);
  cudaGetSymbolAddress((void**)&pxm,  g_xm);
  cudaGetSymbolAddress((void**)&pqkv, g_qkv);
  cudaGetSymbolAddress((void**)&pattn,g_attn);
  cudaGetSymbolAddress((void**)&pmlp, g_mlp);
  cudaGetSymbolAddress((void**)&pcm,  g_cm);
  cudaGetSymbolAddress((void**)&pcm2, g_cm2);
  cudaGetSymbolAddress((void**)&pte1, g_te1);
  cudaGetSymbolAddress((void**)&psc,  g_sc);

  cudaFuncSetAttribute(k_attn, cudaFuncAttributeMaxDynamicSharedMemorySize, 131072);

  k_patch <<<NROWS, 256>>>(x, patch_W, px);
  k_temb  <<<NB, 256>>>(t, t_W1, pte1);
  k_cfinal<<<NB, 256>>>(pte1, t_W2, y_table, y, psc);

  for (int L = 0; L < DEPTH; ++L) {
    k_cond <<<dim3(6, NB), 256>>>(psc, adaln_W + (size_t)L*Hd*6*Hd, nullptr, pcm, 6*Hd);
    k_lnmod<<<NROWS, 256>>>(px, pxm, pcm, 0, Hd);
    k_gemm <<<dim3(3*Hd/128, NROWS/128), 256>>>(pxm, qkv_W + (size_t)L*Hd*3*Hd, pqkv, Hd, 3*Hd, 0, nullptr);
    k_attn <<<dim3(16, NB), 256, 131072>>>(pqkv, pattn);
    k_gemm <<<dim3(Hd/128, NROWS/128), 256>>>(pattn, proj_W + (size_t)L*Hd*Hd, px, Hd, Hd, 2, pcm + 2*Hd);
    k_lnmod<<<NROWS, 256>>>(px, pxm, pcm, 3*Hd, 4*Hd);
    k_gemm <<<dim3(MHID/128, NROWS/128), 256>>>(pxm, mlp1_W + (size_t)L*Hd*MHID, pmlp, Hd, MHID, 1, nullptr);
    k_gemm <<<dim3(Hd/128, NROWS/128), 256>>>(pmlp, mlp2_W + (size_t)L*MHID*Hd, px, MHID, Hd, 2, pcm + 5*Hd);
  }

  k_cond<<<dim3(2, NB), 256>>>(psc, out_mod_W, out_mod_b, pcm2, 2*Hd);
  k_out <<<NROWS, 256>>>(px, pcm2, out_W, out_b, out);
}

// round 5
// speedup vs baseline: 1.9074x; 1.9074x over previous
#include <cuda_runtime.h>
#include <cuda_bf16.h>
#include <math.h>

#define Hd    1024
#define SEQ   256
#define NB    32
#define NROWS (NB*SEQ)     // 8192
#define MHID  4096
#define DEPTH 12

typedef unsigned int u32;
typedef __nv_bfloat16 bf16;

// ---------------- device scratch (no allocations allowed) ----------------
__device__ float g_x   [NROWS*Hd];
__device__ float g_xm  [NROWS*Hd];
__device__ float g_qkv [NROWS*3*Hd];
__device__ float g_attn[NROWS*Hd];
__device__ float g_mlp [NROWS*MHID];
__device__ float g_cm  [NB*6*Hd];
__device__ float g_cm2 [NB*2*Hd];
__device__ float g_te1 [NB*Hd];
__device__ float g_sc  [NB*Hd];

// split/transposed weight arenas: per layer, [N][K] bf16, hi and lo
// per-layer elems: qkv 3072*1024 + proj 1024*1024 + mlp1 4096*1024 + mlp2 1024*4096
#define PER_L   (12582912ULL)
#define OFF_QKV (0ULL)
#define OFF_PROJ (3145728ULL)
#define OFF_MLP1 (4194304ULL)
#define OFF_MLP2 (8388608ULL)
__device__ bf16 g_Wh[PER_L*DEPTH];
__device__ bf16 g_Wl[PER_L*DEPTH];

__device__ __forceinline__ float siluf(float x){ return x / (1.f + __expf(-x)); }
__device__ __forceinline__ float geluf(float x){
  float t = 0.7978845608028654f * (x + 0.044715f * x*x*x);
  return x / (1.f + __expf(-2.f * t));  // x * sigmoid(2t) == 0.5x(1+tanh t)
}

// ---------------- weight split + transpose: W[K][N] f32 -> Wt[N][K] bf16 hi/lo ----------------
__global__ void __launch_bounds__(256) k_wsplit(const float* __restrict__ W,
                                                bf16* __restrict__ Wh,
                                                bf16* __restrict__ Wl,
                                                int K, int N)
{
  __shared__ float tile[32][33];
  int tx = threadIdx.x, ty = threadIdx.y;
  int n0 = blockIdx.x*32, k0 = blockIdx.y*32;
  #pragma unroll
  for (int i = 0; i < 4; ++i)
    tile[ty + i*8][tx] = W[(size_t)(k0 + ty + i*8)*N + n0 + tx];
  __syncthreads();
  #pragma unroll
  for (int i = 0; i < 4; ++i) {
    float v = tile[tx][ty + i*8];
    bf16 h = __float2bfloat16_rn(v);
    bf16 l = __float2bfloat16_rn(v - __bfloat162float(h));
    size_t o = (size_t)(n0 + ty + i*8)*K + k0 + tx;
    Wh[o] = h; Wl[o] = l;
  }
}

// ---------------- patch embed + 2D sincos pos ----------------
__global__ void __launch_bounds__(256) k_patch(const float* __restrict__ x,
                                               const float* __restrict__ pW,
                                               float* __restrict__ XT)
{
  int row = blockIdx.x;
  int b = row >> 8, n = row & 255;
  int ph = n >> 4, pw = n & 15;
  __shared__ float xp[16];
  if (threadIdx.x < 16) {
    int f = threadIdx.x;
    int dy = f >> 3, dx = (f >> 2) & 1, c = f & 3;
    xp[f] = x[((b*32 + ph*2 + dy)*32 + (pw*2 + dx))*4 + c];
  }
  __syncthreads();
  #pragma unroll
  for (int i = 0; i < 4; ++i) {
    int col = threadIdx.x + i*256;
    float acc = 0.f;
    #pragma unroll
    for (int k = 0; k < 16; ++k) acc += xp[k] * pW[k*Hd + col];
    int j = col & 255, seg = col >> 8;
    float fr = expf(-logf(10000.f) * (float)j * (1.f/256.f));
    float a  = (seg < 2 ? (float)pw : (float)ph) * fr;
    float pos = ((seg & 1) == 0) ? sinf(a) : cosf(a);
    XT[(size_t)row*Hd + col] = acc + pos;
  }
}

// ---------------- timestep embed ----------------
__global__ void __launch_bounds__(256) k_temb(const float* __restrict__ t,
                                              const float* __restrict__ W1,
                                              float* __restrict__ TE1)
{
  int b = blockIdx.x, tid = threadIdx.x;
  __shared__ float e[256];
  {
    int j = tid & 127;
    float fr = expf(-logf(10000.f) * (float)j * (1.f/128.f));
    float a = t[b] * fr;
    e[tid] = (tid < 128 ? cosf(a) : sinf(a)) * 1.41421356237f;
  }
  __syncthreads();
  #pragma unroll
  for (int i = 0; i < 4; ++i) {
    int col = tid + i*256;
    float acc = 0.f;
    for (int k = 0; k < 256; ++k) acc += e[k] * W1[k*Hd + col];
    TE1[b*Hd + col] = acc / (1.f + expf(-acc));
  }
}

__global__ void __launch_bounds__(256) k_cfinal(const float* __restrict__ TE1,
                                                const float* __restrict__ W2,
                                                const float* __restrict__ ytab,
                                                const int* __restrict__ y,
                                                float* __restrict__ SCout)
{
  int b = blockIdx.x, tid = threadIdx.x;
  __shared__ float a[Hd];
  for (int k = tid; k < Hd; k += 256) a[k] = TE1[b*Hd + k];
  __syncthreads();
  int yi = y[b];
  #pragma unroll
  for (int i = 0; i < 4; ++i) {
    int col = tid + i*256;
    float acc = 0.f;
    for (int k = 0; k < Hd; ++k) acc += a[k] * W2[k*Hd + col];
    float c = acc + ytab[(size_t)yi*Hd + col];
    SCout[b*Hd + col] = c / (1.f + expf(-c));
  }
}

// ---------------- conditioning GEMM (batch-grouped): OUT[b,:] = silu_c[b,:] @ W (+bias) ----------------
__global__ void __launch_bounds__(256) k_cond(const float* __restrict__ SC,
                                              const float* __restrict__ W,
                                              const float* __restrict__ bias,
                                              float* __restrict__ OUT, int N)
{
  __shared__ float a[8][Hd];       // 32 KB
  int tid = threadIdx.x;
  int bg = blockIdx.y * 8;
  for (int idx = tid; idx < 8*Hd; idx += 256)
    a[idx >> 10][idx & 1023] = SC[(bg + (idx >> 10))*Hd + (idx & 1023)];
  __syncthreads();
  int c = blockIdx.x*256 + tid;
  float acc[8];
  #pragma unroll
  for (int b = 0; b < 8; ++b) acc[b] = 0.f;
  #pragma unroll 4
  for (int k = 0; k < Hd; ++k) {
    float w = W[(size_t)k*N + c];
    #pragma unroll
    for (int b = 0; b < 8; ++b) acc[b] += a[b][k]*w;
  }
  float bv = bias ? bias[c] : 0.f;
  #pragma unroll
  for (int b = 0; b < 8; ++b)
    OUT[(size_t)(bg + b)*N + c] = acc[b] + bv;
}

// ---------------- LN + modulate ----------------
__global__ void __launch_bounds__(256) k_lnmod(const float* __restrict__ X,
                                               float* __restrict__ Y,
                                               const float* __restrict__ cm,
                                               int shOff, int scOff)
{
  int row = blockIdx.x, b = row >> 8, tid = threadIdx.x;
  const float* x = X + (size_t)row*Hd;
  float v[4]; float s = 0.f, s2 = 0.f;
  #pragma unroll
  for (int i = 0; i < 4; ++i) { float t = x[tid + i*256]; v[i] = t; s += t; s2 += t*t; }
  #pragma unroll
  for (int o = 16; o; o >>= 1) {
    s  += __shfl_xor_sync(0xffffffffu, s,  o);
    s2 += __shfl_xor_sync(0xffffffffu, s2, o);
  }
  __shared__ float ss[8], ss2[8];
  if ((tid & 31) == 0) { ss[tid>>5] = s; ss2[tid>>5] = s2; }
  __syncthreads();
  s = 0.f; s2 = 0.f;
  #pragma unroll
  for (int w = 0; w < 8; ++w) { s += ss[w]; s2 += ss2[w]; }
  float mean = s * (1.f/1024.f);
  float var  = s2 * (1.f/1024.f) - mean*mean;
  float r = rsqrtf(var + 1e-6f);
  const float* cb = cm + b*6*Hd;
  #pragma unroll
  for (int i = 0; i < 4; ++i) {
    int col = tid + i*256;
    Y[(size_t)row*Hd + col] = (v[i]-mean)*r*cb[scOff+col] + cb[shOff+col];
  }
}

// ---------------- bf16x3 tensor-core GEMM ----------------
// C[8192,N](+epi) = A[8192,K]f32 @ Wt[N][K](hi+lo bf16)
// mode 0: C=acc   mode 1: C=gelu(acc)   mode 2: C += gate[b,col]*acc
#define BK   32
#define BKP  40      // padded row length (elems) -> 80B row stride, 16B aligned
#define STG  5120    // 128*40 elems per array
__device__ __forceinline__ void mma16816(float* c, const u32* a, const u32* b){
  asm volatile("mma.sync.aligned.m16n8k16.row.col.f32.bf16.bf16.f32 "
    "{%0,%1,%2,%3},{%4,%5,%6,%7},{%8,%9},{%0,%1,%2,%3};"
    : "+f"(c[0]), "+f"(c[1]), "+f"(c[2]), "+f"(c[3])
    : "r"(a[0]), "r"(a[1]), "r"(a[2]), "r"(a[3]), "r"(b[0]), "r"(b[1]));
}

__global__ void __launch_bounds__(256) k_gemm(const float* __restrict__ A,
                                              const bf16* __restrict__ Wh,
                                              const bf16* __restrict__ Wl,
                                              float* __restrict__ C, int K, int N,
                                              int mode, const float* __restrict__ gate)
{
  extern __shared__ bf16 sm[];
  // stage s: Ah = s*4*STG, Al = +STG, Bh = +2*STG, Bl = +3*STG
  int tid = threadIdx.x;
  int lane = tid & 31, warp = tid >> 5;
  int warpRow = (warp >> 1) * 32;     // 4 warps along M
  int warpCol = (warp & 1) * 64;      // 2 warps along N
  int grp = lane >> 2;                // 0..7
  int qd  = (lane & 3) << 1;          // 0,2,4,6

  const float* Ab = A + (size_t)blockIdx.y*128*K;
  const bf16* Bh0 = Wh + (size_t)blockIdx.x*128*K;
  const bf16* Bl0 = Wl + (size_t)blockIdx.x*128*K;

  float acc[2][8][4];
  #pragma unroll
  for (int i = 0; i < 2; ++i)
    #pragma unroll
    for (int j = 0; j < 8; ++j)
      #pragma unroll
      for (int q = 0; q < 4; ++q) acc[i][j][q] = 0.f;

  // global->smem loader indices
  int aRow = tid >> 1;                 // but we load 4 float4 per thread: j = tid + i*256
  (void)aRow;

  auto loadA = [&](int kt, float4* av){
    #pragma unroll
    for (int i = 0; i < 4; ++i) {
      int j = tid + i*256;             // 0..1023
      int r = j >> 3, c4 = (j & 7) << 2;
      av[i] = *(const float4*)(Ab + (size_t)r*K + kt*BK + c4);
    }
  };
  auto loadB = [&](int kt, uint4* bh, uint4* bl){
    #pragma unroll
    for (int i = 0; i < 2; ++i) {
      int j = tid + i*256;             // 0..511
      int r = j >> 2, c = (j & 3) << 3;
      bh[i] = *(const uint4*)(Bh0 + (size_t)r*K + kt*BK + c);
      bl[i] = *(const uint4*)(Bl0 + (size_t)r*K + kt*BK + c);
    }
  };
  auto storeA = [&](int buf, const float4* av){
    bf16* Ah = sm + buf*4*STG;
    bf16* Al = Ah + STG;
    #pragma unroll
    for (int i = 0; i < 4; ++i) {
      int j = tid + i*256;
      int r = j >> 3, c4 = (j & 7) << 2;
      float vs[4] = {av[i].x, av[i].y, av[i].z, av[i].w};
      #pragma unroll
      for (int q = 0; q < 4; ++q) {
        bf16 h = __float2bfloat16_rn(vs[q]);
        bf16 l = __float2bfloat16_rn(vs[q] - __bfloat162float(h));
        Ah[r*BKP + c4 + q] = h;
        Al[r*BKP + c4 + q] = l;
      }
    }
  };
  auto storeB = [&](int buf, const uint4* bh, const uint4* bl){
    bf16* Bh = sm + buf*4*STG + 2*STG;
    bf16* Bl = Bh + STG;
    #pragma unroll
    for (int i = 0; i < 2; ++i) {
      int j = tid + i*256;
      int r = j >> 2, c = (j & 3) << 3;
      *(uint4*)(Bh + r*BKP + c) = bh[i];
      *(uint4*)(Bl + r*BKP + c) = bl[i];
    }
  };

  float4 av[4]; uint4 bh[2], bl[2];
  loadA(0, av); loadB(0, bh, bl);
  storeA(0, av); storeB(0, bh, bl);
  __syncthreads();

  int nk = K / BK;
  for (int kt = 0; kt < nk; ++kt) {
    int buf = kt & 1;
    if (kt + 1 < nk) { loadA(kt+1, av); loadB(kt+1, bh, bl); }

    const bf16* Ah = sm + buf*4*STG;
    const bf16* Al = Ah + STG;
    const bf16* Bh = Ah + 2*STG;
    const bf16* Bl = Ah + 3*STG;
    #pragma unroll
    for (int ks = 0; ks < BK; ks += 16) {
      u32 afh[2][4], afl[2][4], bfh[8][2], bfl[8][2];
      #pragma unroll
      for (int i = 0; i < 2; ++i) {
        int r0 = warpRow + i*16 + grp;
        afh[i][0] = *(const u32*)(Ah + r0*BKP + ks + qd);
        afh[i][1] = *(const u32*)(Ah + (r0+8)*BKP + ks + qd);
        afh[i][2] = *(const u32*)(Ah + r0*BKP + ks + qd + 8);
        afh[i][3] = *(const u32*)(Ah + (r0+8)*BKP + ks + qd + 8);
        afl[i][0] = *(const u32*)(Al + r0*BKP + ks + qd);
        afl[i][1] = *(const u32*)(Al + (r0+8)*BKP + ks + qd);
        afl[i][2] = *(const u32*)(Al + r0*BKP + ks + qd + 8);
        afl[i][3] = *(const u32*)(Al + (r0+8)*BKP + ks + qd + 8);
      }
      #pragma unroll
      for (int j = 0; j < 8; ++j) {
        int n0 = warpCol + j*8 + grp;
        bfh[j][0] = *(const u32*)(Bh + n0*BKP + ks + qd);
        bfh[j][1] = *(const u32*)(Bh + n0*BKP + ks + qd + 8);
        bfl[j][0] = *(const u32*)(Bl + n0*BKP + ks + qd);
        bfl[j][1] = *(const u32*)(Bl + n0*BKP + ks + qd + 8);
      }
      #pragma unroll
      for (int i = 0; i < 2; ++i)
        #pragma unroll
        for (int j = 0; j < 8; ++j) {
          mma16816(acc[i][j], afh[i], bfh[j]);
          mma16816(acc[i][j], afh[i], bfl[j]);
          mma16816(acc[i][j], afl[i], bfh[j]);
        }
    }
    if (kt + 1 < nk) {
      __syncthreads();
      storeA(buf ^ 1, av); storeB(buf ^ 1, bh, bl);
      __syncthreads();
    }
  }

  // epilogue
  int rb = blockIdx.y*128 + warpRow + grp;
  int cb = blockIdx.x*128 + warpCol + qd;
  #pragma unroll
  for (int i = 0; i < 2; ++i) {
    #pragma unroll
    for (int half = 0; half < 2; ++half) {
      int row = rb + i*16 + half*8;
      float* cr = C + (size_t)row*N + cb;
      if (mode == 0) {
        #pragma unroll
        for (int j = 0; j < 8; ++j) {
          float2 v = make_float2(acc[i][j][half*2], acc[i][j][half*2+1]);
          *(float2*)(cr + j*8) = v;
        }
      } else if (mode == 1) {
        #pragma unroll
        for (int j = 0; j < 8; ++j) {
          float2 v = make_float2(geluf(acc[i][j][half*2]), geluf(acc[i][j][half*2+1]));
          *(float2*)(cr + j*8) = v;
        }
      } else {
        int b = row >> 8;
        const float* g = gate + (size_t)b*6*Hd;
        #pragma unroll
        for (int j = 0; j < 8; ++j) {
          int col = cb + j*8;
          float2 old = *(float2*)(cr + j*8);
          old.x += g[col]   * acc[i][j][half*2];
          old.y += g[col+1] * acc[i][j][half*2+1];
          *(float2*)(cr + j*8) = old;
        }
      }
    }
  }
}

// ---------------- attention: one CTA per (head, batch), flash over K ----------------
__global__ void __launch_bounds__(256) k_attn(const float* __restrict__ QKV,
                                              float* __restrict__ O)
{
  extern __shared__ float smf[];
  float* Ks = smf;                 // [256][64]
  float* Vs = smf + 256*64;        // [256][64]
  int hd = blockIdx.x, b = blockIdx.y;
  const float* base = QKV + (size_t)b*SEQ*3*Hd + hd*64;
  for (int i = threadIdx.x; i < 256*16; i += 256) {
    int r = i >> 4, d4 = (i & 15) << 2;
    *(float4*)&Ks[r*64 + d4] = *(const float4*)(base + (size_t)r*3*Hd + d4);        // k @ 0
    *(float4*)&Vs[r*64 + d4] = *(const float4*)(base + (size_t)r*3*Hd + 2*Hd + d4); // v @ 2h
  }
  int qi = threadIdx.x;
  float q[64];
  const float* qp = base + (size_t)qi*3*Hd + Hd;                                    // q @ h
  #pragma unroll
  for (int d = 0; d < 64; ++d) q[d] = qp[d]*0.125f;
  __syncthreads();
  float o[64];
  #pragma unroll
  for (int d = 0; d < 64; ++d) o[d] = 0.f;
  float m = -1e30f, l = 0.f;
  for (int kb = 0; kb < 256; kb += 16) {
    float s[16];
    float bm = -1e30f;
    #pragma unroll
    for (int kk = 0; kk < 16; ++kk) {
      const float* kr = &Ks[(kb+kk)*64];
      float t = 0.f;
      #pragma unroll
      for (int d = 0; d < 64; ++d) t += q[d]*kr[d];
      s[kk] = t;
      bm = fmaxf(bm, t);
    }
    float mn = fmaxf(m, bm);
    float corr = __expf(m - mn);
    l *= corr;
    #pragma unroll
    for (int d = 0; d < 64; ++d) o[d] *= corr;
    #pragma unroll
    for (int kk = 0; kk < 16; ++kk) {
      float p = __expf(s[kk] - mn);
      l += p;
      const float* vr = &Vs[(kb+kk)*64];
      #pragma unroll
      for (int d = 0; d < 64; ++d) o[d] += p*vr[d];
    }
    m = mn;
  }
  float inv = 1.f / l;
  float* op = O + (size_t)(b*SEQ + qi)*Hd + hd*64;
  #pragma unroll
  for (int d = 0; d < 64; ++d) op[d] = o[d]*inv;
}

// ---------------- final: LN+modulate, @ out_W + b, unpatchify ----------------
__global__ void __launch_bounds__(256) k_out(const float* __restrict__ X,
                                             const float* __restrict__ cm2,
                                             const float* __restrict__ oW,
                                             const float* __restrict__ ob,
                                             float* __restrict__ out)
{
  int row = blockIdx.x, b = row >> 8, n = row & 255, tid = threadIdx.x;
  const float* xr = X + (size_t)row*Hd;
  float v[4]; float s = 0.f, s2 = 0.f;
  #pragma unroll
  for (int i = 0; i < 4; ++i) { float t = xr[tid + i*256]; v[i] = t; s += t; s2 += t*t; }
  #pragma unroll
  for (int o = 16; o; o >>= 1) {
    s  += __shfl_xor_sync(0xffffffffu, s,  o);
    s2 += __shfl_xor_sync(0xffffffffu, s2, o);
  }
  __shared__ float ss[8], ss2[8];
  if ((tid & 31) == 0) { ss[tid>>5] = s; ss2[tid>>5] = s2; }
  __syncthreads();
  s = 0.f; s2 = 0.f;
  #pragma unroll
  for (int w = 0; w < 8; ++w) { s += ss[w]; s2 += ss2[w]; }
  float mean = s*(1.f/1024.f), var = s2*(1.f/1024.f) - mean*mean;
  float r = rsqrtf(var + 1e-6f);
  __shared__ float xm[Hd];
  const float* c2 = cm2 + b*2*Hd;
  #pragma unroll
  for (int i = 0; i < 4; ++i) {
    int col = tid + i*256;
    xm[col] = (v[i]-mean)*r*c2[Hd+col] + c2[col];
  }
  __syncthreads();
  int oi = tid >> 4, part = tid & 15;
  float acc = 0.f;
  const float* xp = xm + part*64;
  #pragma unroll
  for (int k = 0; k < 64; ++k) acc += xp[k]*oW[(part*64 + k)*16 + oi];
  __shared__ float red[256];
  red[tid] = acc;
  __syncthreads();
  if (part == 0) {
    float sum = 0.f;
    #pragma unroll
    for (int p = 0; p < 16; ++p) sum += red[oi*16 + p];
    sum += ob[oi];
    int ph = n >> 4, pw = n & 15;
    int p1 = oi >> 3, p2 = (oi >> 2) & 1, c = oi & 3;
    out[((b*32 + ph*2 + p1)*32 + (pw*2 + p2))*4 + c] = sum;
  }
}

// ---------------- host ----------------
extern "C" void kernel_launch(void* const* d_in, const int* in_sizes, int n_in,
                              void* d_out, int out_size)
{
  const float* x        = (const float*)d_in[0];
  const float* t        = (const float*)d_in[1];
  const int*   y        = (const int*)  d_in[2];
  const float* patch_W  = (const float*)d_in[3];
  const float* y_table  = (const float*)d_in[4];
  const float* t_W1     = (const float*)d_in[5];
  const float* t_W2     = (const float*)d_in[6];
  const float* adaln_W  = (const float*)d_in[7];
  const float* qkv_W    = (const float*)d_in[8];
  const float* proj_W   = (const float*)d_in[9];
  const float* mlp1_W   = (const float*)d_in[10];
  const float* mlp2_W   = (const float*)d_in[11];
  const float* out_mod_W= (const float*)d_in[12];
  const float* out_mod_b= (const float*)d_in[13];
  const float* out_W    = (const float*)d_in[14];
  const float* out_b    = (const float*)d_in[15];
  float* out = (float*)d_out;

  float *px, *pxm, *pqkv, *pattn, *pmlp, *pcm, *pcm2, *pte1, *psc;
  bf16 *pWh, *pWl;
  cudaGetSymbolAddress((void**)&px,   g_x);
  cudaGetSymbolAddress((void**)&pxm,  g_xm);
  cudaGetSymbolAddress((void**)&pqkv, g_qkv);
  cudaGetSymbolAddress((void**)&pattn,g_attn);
  cudaGetSymbolAddress((void**)&pmlp, g_mlp);
  cudaGetSymbolAddress((void**)&pcm,  g_cm);
  cudaGetSymbolAddress((void**)&pcm2, g_cm2);
  cudaGetSymbolAddress((void**)&pte1, g_te1);
  cudaGetSymbolAddress((void**)&psc,  g_sc);
  cudaGetSymbolAddress((void**)&pWh,  g_Wh);
  cudaGetSymbolAddress((void**)&pWl,  g_Wl);

  cudaFuncSetAttribute(k_attn, cudaFuncAttributeMaxDynamicSharedMemorySize, 131072);
  cudaFuncSetAttribute(k_gemm, cudaFuncAttributeMaxDynamicSharedMemorySize, 81920);

  // pre-split all block weights (once per launch; deterministic)
  for (int L = 0; L < DEPTH; ++L) {
    size_t base = (size_t)L * PER_L;
    k_wsplit<<<dim3(3*Hd/32, Hd/32), dim3(32,8)>>>(qkv_W + (size_t)L*Hd*3*Hd,
        pWh + base + OFF_QKV,  pWl + base + OFF_QKV,  Hd, 3*Hd);
    k_wsplit<<<dim3(Hd/32, Hd/32), dim3(32,8)>>>(proj_W + (size_t)L*Hd*Hd,
        pWh + base + OFF_PROJ, pWl + base + OFF_PROJ, Hd, Hd);
    k_wsplit<<<dim3(MHID/32, Hd/32), dim3(32,8)>>>(mlp1_W + (size_t)L*Hd*MHID,
        pWh + base + OFF_MLP1, pWl + base + OFF_MLP1, Hd, MHID);
    k_wsplit<<<dim3(Hd/32, MHID/32), dim3(32,8)>>>(mlp2_W + (size_t)L*MHID*Hd,
        pWh + base + OFF_MLP2, pWl + base + OFF_MLP2, MHID, Hd);
  }

  k_patch <<<NROWS, 256>>>(x, patch_W, px);
  k_temb  <<<NB, 256>>>(t, t_W1, pte1);
  k_cfinal<<<NB, 256>>>(pte1, t_W2, y_table, y, psc);

  for (int L = 0; L < DEPTH; ++L) {
    size_t base = (size_t)L * PER_L;
    k_cond <<<dim3(6*Hd/256, 4), 256>>>(psc, adaln_W + (size_t)L*Hd*6*Hd, nullptr, pcm, 6*Hd);
    k_lnmod<<<NROWS, 256>>>(px, pxm, pcm, 0, Hd);
    k_gemm <<<dim3(3*Hd/128, NROWS/128), 256, 81920>>>(pxm,
        pWh + base + OFF_QKV, pWl + base + OFF_QKV, pqkv, Hd, 3*Hd, 0, nullptr);
    k_attn <<<dim3(16, NB), 256, 131072>>>(pqkv, pattn);
    k_gemm <<<dim3(Hd/128, NROWS/128), 256, 81920>>>(pattn,
        pWh + base + OFF_PROJ, pWl + base + OFF_PROJ, px, Hd, Hd, 2, pcm + 2*Hd);
    k_lnmod<<<NROWS, 256>>>(px, pxm, pcm, 3*Hd, 4*Hd);
    k_gemm <<<dim3(MHID/128, NROWS/128), 256, 81920>>>(pxm,
        pWh + base + OFF_MLP1, pWl + base + OFF_MLP1, pmlp, Hd, MHID, 1, nullptr);
    k_gemm <<<dim3(Hd/128, NROWS/128), 256, 81920>>>(pmlp,
        pWh + base + OFF_MLP2, pWl + base + OFF_MLP2, px, MHID, Hd, 2, pcm + 5*Hd);
  }

  k_cond<<<dim3(2*Hd/256, 4), 256>>>(psc, out_mod_W, out_mod_b, pcm2, 2*Hd);
  k_out <<<NROWS, 256>>>(px, pcm2, out_W, out_b, out);
}

// round 10
// speedup vs baseline: 2.2105x; 1.1589x over previous
#include <cuda_runtime.h>
#include <cuda_bf16.h>
#include <math.h>

#define Hd    1024
#define SEQ   256
#define NB    32
#define NROWS (NB*SEQ)     // 8192
#define MHID  4096
#define DEPTH 12

typedef unsigned int u32;
typedef __nv_bfloat16 bf16;

// ---------------- device scratch (no allocations allowed) ----------------
__device__ float g_x   [NROWS*Hd];
__device__ float g_xm  [NROWS*Hd];
__device__ float g_qkv [NROWS*3*Hd];
__device__ float g_attn[NROWS*Hd];
__device__ float g_mlp [NROWS*MHID];
__device__ float g_cm  [NB*6*Hd];
__device__ float g_cm2 [NB*2*Hd];
__device__ float g_te1 [NB*Hd];
__device__ float g_sc  [NB*Hd];

// split/transposed weight arenas: per layer, [N][K] bf16, hi and lo
#define PER_L   (12582912ULL)
#define OFF_QKV (0ULL)
#define OFF_PROJ (3145728ULL)
#define OFF_MLP1 (4194304ULL)
#define OFF_MLP2 (8388608ULL)
__device__ bf16 g_Wh[PER_L*DEPTH];
__device__ bf16 g_Wl[PER_L*DEPTH];

__device__ __forceinline__ float geluf(float x){
  float t = 0.7978845608028654f * (x + 0.044715f * x*x*x);
  return x / (1.f + __expf(-2.f * t));
}

__device__ __forceinline__ u32 s2u(const void* p){
  u32 a;
  asm("{ .reg .u64 t; cvta.to.shared.u64 t, %1; cvt.u32.u64 %0, t; }" : "=r"(a) : "l"(p));
  return a;
}
__device__ __forceinline__ void mma16816(float* c, const u32* a, const u32* b){
  asm volatile("mma.sync.aligned.m16n8k16.row.col.f32.bf16.bf16.f32 "
    "{%0,%1,%2,%3},{%4,%5,%6,%7},{%8,%9},{%0,%1,%2,%3};"
    : "+f"(c[0]), "+f"(c[1]), "+f"(c[2]), "+f"(c[3])
    : "r"(a[0]), "r"(a[1]), "r"(a[2]), "r"(a[3]), "r"(b[0]), "r"(b[1]));
}
__device__ __forceinline__ void ldsm4(u32* r, u32 addr){
  asm volatile("ldmatrix.sync.aligned.m8n8.x4.shared.b16 {%0,%1,%2,%3}, [%4];"
    : "=r"(r[0]), "=r"(r[1]), "=r"(r[2]), "=r"(r[3]) : "r"(addr));
}
__device__ __forceinline__ void cp16(u32 dst, const void* src){
  asm volatile("cp.async.cg.shared.global [%0], [%1], 16;" :: "r"(dst), "l"(src) : "memory");
}
__device__ __forceinline__ void cp_commit(){ asm volatile("cp.async.commit_group;" ::: "memory"); }
__device__ __forceinline__ void cp_wait0(){ asm volatile("cp.async.wait_group 0;" ::: "memory"); }

// ---------------- weight split + transpose: W[K][N] f32 -> Wt[N][K] bf16 hi/lo ----------------
__global__ void __launch_bounds__(256) k_wsplit(const float* __restrict__ W,
                                                bf16* __restrict__ Wh,
                                                bf16* __restrict__ Wl,
                                                int K, int N)
{
  __shared__ float tile[32][33];
  int tx = threadIdx.x, ty = threadIdx.y;
  int n0 = blockIdx.x*32, k0 = blockIdx.y*32;
  #pragma unroll
  for (int i = 0; i < 4; ++i)
    tile[ty + i*8][tx] = W[(size_t)(k0 + ty + i*8)*N + n0 + tx];
  __syncthreads();
  #pragma unroll
  for (int i = 0; i < 4; ++i) {
    float v = tile[tx][ty + i*8];
    bf16 h = __float2bfloat16_rn(v);
    bf16 l = __float2bfloat16_rn(v - __bfloat162float(h));
    size_t o = (size_t)(n0 + ty + i*8)*K + k0 + tx;
    Wh[o] = h; Wl[o] = l;
  }
}

// ---------------- patch embed + 2D sincos pos ----------------
__global__ void __launch_bounds__(256) k_patch(const float* __restrict__ x,
                                               const float* __restrict__ pW,
                                               float* __restrict__ XT)
{
  int row = blockIdx.x;
  int b = row >> 8, n = row & 255;
  int ph = n >> 4, pw = n & 15;
  __shared__ float xp[16];
  if (threadIdx.x < 16) {
    int f = threadIdx.x;
    int dy = f >> 3, dx = (f >> 2) & 1, c = f & 3;
    xp[f] = x[((b*32 + ph*2 + dy)*32 + (pw*2 + dx))*4 + c];
  }
  __syncthreads();
  #pragma unroll
  for (int i = 0; i < 4; ++i) {
    int col = threadIdx.x + i*256;
    float acc = 0.f;
    #pragma unroll
    for (int k = 0; k < 16; ++k) acc += xp[k] * pW[k*Hd + col];
    int j = col & 255, seg = col >> 8;
    float fr = expf(-logf(10000.f) * (float)j * (1.f/256.f));
    float a  = (seg < 2 ? (float)pw : (float)ph) * fr;
    float pos = ((seg & 1) == 0) ? sinf(a) : cosf(a);
    XT[(size_t)row*Hd + col] = acc + pos;
  }
}

// ---------------- timestep embed ----------------
__global__ void __launch_bounds__(256) k_temb(const float* __restrict__ t,
                                              const float* __restrict__ W1,
                                              float* __restrict__ TE1)
{
  int b = blockIdx.x, tid = threadIdx.x;
  __shared__ float e[256];
  {
    int j = tid & 127;
    float fr = expf(-logf(10000.f) * (float)j * (1.f/128.f));
    float a = t[b] * fr;
    e[tid] = (tid < 128 ? cosf(a) : sinf(a)) * 1.41421356237f;
  }
  __syncthreads();
  #pragma unroll
  for (int i = 0; i < 4; ++i) {
    int col = tid + i*256;
    float acc = 0.f;
    for (int k = 0; k < 256; ++k) acc += e[k] * W1[k*Hd + col];
    TE1[b*Hd + col] = acc / (1.f + expf(-acc));
  }
}

__global__ void __launch_bounds__(256) k_cfinal(const float* __restrict__ TE1,
                                                const float* __restrict__ W2,
                                                const float* __restrict__ ytab,
                                                const int* __restrict__ y,
                                                float* __restrict__ SCout)
{
  int b = blockIdx.x, tid = threadIdx.x;
  __shared__ float a[Hd];
  for (int k = tid; k < Hd; k += 256) a[k] = TE1[b*Hd + k];
  __syncthreads();
  int yi = y[b];
  #pragma unroll
  for (int i = 0; i < 4; ++i) {
    int col = tid + i*256;
    float acc = 0.f;
    for (int k = 0; k < Hd; ++k) acc += a[k] * W2[k*Hd + col];
    float c = acc + ytab[(size_t)yi*Hd + col];
    SCout[b*Hd + col] = c / (1.f + expf(-c));
  }
}

// ---------------- conditioning GEMM (batch-grouped) ----------------
__global__ void __launch_bounds__(256) k_cond(const float* __restrict__ SC,
                                              const float* __restrict__ W,
                                              const float* __restrict__ bias,
                                              float* __restrict__ OUT, int N)
{
  __shared__ float a[8][Hd];
  int tid = threadIdx.x;
  int bg = blockIdx.y * 8;
  for (int idx = tid; idx < 8*Hd; idx += 256)
    a[idx >> 10][idx & 1023] = SC[(bg + (idx >> 10))*Hd + (idx & 1023)];
  __syncthreads();
  int c = blockIdx.x*256 + tid;
  float acc[8];
  #pragma unroll
  for (int b = 0; b < 8; ++b) acc[b] = 0.f;
  #pragma unroll 4
  for (int k = 0; k < Hd; ++k) {
    float w = W[(size_t)k*N + c];
    #pragma unroll
    for (int b = 0; b < 8; ++b) acc[b] += a[b][k]*w;
  }
  float bv = bias ? bias[c] : 0.f;
  #pragma unroll
  for (int b = 0; b < 8; ++b)
    OUT[(size_t)(bg + b)*N + c] = acc[b] + bv;
}

// ---------------- LN + modulate ----------------
__global__ void __launch_bounds__(256) k_lnmod(const float* __restrict__ X,
                                               float* __restrict__ Y,
                                               const float* __restrict__ cm,
                                               int shOff, int scOff)
{
  int row = blockIdx.x, b = row >> 8, tid = threadIdx.x;
  const float* x = X + (size_t)row*Hd;
  float v[4]; float s = 0.f, s2 = 0.f;
  #pragma unroll
  for (int i = 0; i < 4; ++i) { float t = x[tid + i*256]; v[i] = t; s += t; s2 += t*t; }
  #pragma unroll
  for (int o = 16; o; o >>= 1) {
    s  += __shfl_xor_sync(0xffffffffu, s,  o);
    s2 += __shfl_xor_sync(0xffffffffu, s2, o);
  }
  __shared__ float ss[8], ss2[8];
  if ((tid & 31) == 0) { ss[tid>>5] = s; ss2[tid>>5] = s2; }
  __syncthreads();
  s = 0.f; s2 = 0.f;
  #pragma unroll
  for (int w = 0; w < 8; ++w) { s += ss[w]; s2 += ss2[w]; }
  float mean = s * (1.f/1024.f);
  float var  = s2 * (1.f/1024.f) - mean*mean;
  float r = rsqrtf(var + 1e-6f);
  const float* cb = cm + b*6*Hd;
  #pragma unroll
  for (int i = 0; i < 4; ++i) {
    int col = tid + i*256;
    Y[(size_t)row*Hd + col] = (v[i]-mean)*r*cb[scOff+col] + cb[shOff+col];
  }
}

// ---------------- bf16x3 mma.sync GEMM with ldmatrix + cp.async ----------------
// C[8192,N](+epi) = A[8192,K]f32 @ Wt[N][K](hi+lo bf16). Tile 128x128, K-chunk 64.
// mode 0: C=acc   1: C=gelu(acc)   2: C += gate[b,col]*acc
#define ROWB  144              // padded row stride bytes (72 bf16)
#define MATSZ (128*ROWB)       // 18432 B per matrix
#define BUFSZ (4*MATSZ)        // Ah|Al|Bh|Bl = 73728 B
__global__ void __launch_bounds__(256) k_gemm(const float* __restrict__ A,
                                              const bf16* __restrict__ Wh,
                                              const bf16* __restrict__ Wl,
                                              float* __restrict__ C, int K, int N,
                                              int mode, const float* __restrict__ gate)
{
  extern __shared__ __align__(128) char smem[];
  const int tid = threadIdx.x, lane = tid & 31, wid = tid >> 5;
  const u32 sb = s2u(smem);

  const int warpM = wid >> 2;          // 0..1 -> M base 0/64
  const int warpN = wid & 3;           // 0..3 -> N base 0/32/64/96
  const int mbase = warpM * 64;
  const int nbase = warpN * 32;
  const int grp = lane >> 3, lr = lane & 7;

  // ldmatrix lane offsets (bytes, within a matrix)
  const u32 aOff = (u32)(mbase + (grp & 1)*8 + lr) * ROWB + (grp >> 1)*16;
  const u32 bOff = (u32)(nbase + (grp >> 1)*8 + lr) * ROWB + (grp & 1)*16;

  const float* Ag  = A  + (size_t)blockIdx.y * 128 * K;
  const bf16*  Bh0 = Wh + (size_t)blockIdx.x * 128 * K;
  const bf16*  Bl0 = Wl + (size_t)blockIdx.x * 128 * K;
  const int nk = K >> 6;

  float acc[4][4][4];
  #pragma unroll
  for (int i = 0; i < 4; ++i)
    #pragma unroll
    for (int j = 0; j < 4; ++j)
      #pragma unroll
      for (int q = 0; q < 4; ++q) acc[i][j][q] = 0.f;

  float4 av[8];
  auto ldgA = [&](int kt){
    #pragma unroll
    for (int i = 0; i < 8; ++i) {
      int j = tid + i*256;                  // 0..2047
      int r = j >> 4, c4 = (j & 15) << 2;   // 16 float4 per 64-float row
      av[i] = *(const float4*)(Ag + (size_t)r*K + (kt << 6) + c4);
    }
  };
  auto stA = [&](int buf){
    char* ah = smem + buf*BUFSZ;
    char* al = ah + MATSZ;
    #pragma unroll
    for (int i = 0; i < 8; ++i) {
      int j = tid + i*256;
      int r = j >> 4, c4 = (j & 15) << 2;
      int off = r*ROWB + c4*2;
      float vx = av[i].x, vy = av[i].y, vz = av[i].z, vw = av[i].w;
      __nv_bfloat162 h0 = __floats2bfloat162_rn(vx, vy);
      __nv_bfloat162 h1 = __floats2bfloat162_rn(vz, vw);
      *(uint2*)(ah + off) = make_uint2(*(u32*)&h0, *(u32*)&h1);
      float rx = vx - __bfloat162float(h0.x), ry = vy - __bfloat162float(h0.y);
      float rz = vz - __bfloat162float(h1.x), rw = vw - __bfloat162float(h1.y);
      __nv_bfloat162 l0 = __floats2bfloat162_rn(rx, ry);
      __nv_bfloat162 l1 = __floats2bfloat162_rn(rz, rw);
      *(uint2*)(al + off) = make_uint2(*(u32*)&l0, *(u32*)&l1);
    }
  };
  auto cpB = [&](int kt, int buf){
    u32 bh = sb + buf*BUFSZ + 2*MATSZ;
    u32 bl = bh + MATSZ;
    #pragma unroll
    for (int i = 0; i < 4; ++i) {
      int j = tid + i*256;                  // 0..1023
      int r = j >> 3, c8 = (j & 7) << 3;    // 8 x 16B per 128B row
      u32 off = (u32)r*ROWB + c8*2;
      const bf16* sh = Bh0 + (size_t)r*K + (kt << 6) + c8;
      const bf16* sl = Bl0 + (size_t)r*K + (kt << 6) + c8;
      cp16(bh + off, sh);
      cp16(bl + off, sl);
    }
    cp_commit();
  };

  // prologue
  ldgA(0);
  cpB(0, 0);
  stA(0);
  cp_wait0();
  __syncthreads();

  for (int c = 0; c < nk; ++c) {
    int buf = c & 1;
    if (c + 1 < nk) { ldgA(c + 1); cpB(c + 1, buf ^ 1); }

    u32 baseA = sb + buf*BUFSZ;
    u32 baseB = baseA + 2*MATSZ;
    #pragma unroll
    for (int ks = 0; ks < 4; ++ks) {
      u32 ah[4][4], alr[4][4], bh[4][2], bl[4][2];
      #pragma unroll
      for (int mt = 0; mt < 4; ++mt) {
        u32 ad = baseA + aOff + mt*(16*ROWB) + ks*32;
        ldsm4(ah[mt], ad);
        ldsm4(alr[mt], ad + MATSZ);
      }
      #pragma unroll
      for (int np = 0; np < 2; ++np) {
        u32 r4[4], l4[4];
        u32 bd = baseB + bOff + np*(16*ROWB) + ks*32;
        ldsm4(r4, bd);
        ldsm4(l4, bd + MATSZ);
        bh[np*2][0]   = r4[0]; bh[np*2][1]   = r4[1];
        bh[np*2+1][0] = r4[2]; bh[np*2+1][1] = r4[3];
        bl[np*2][0]   = l4[0]; bl[np*2][1]   = l4[1];
        bl[np*2+1][0] = l4[2]; bl[np*2+1][1] = l4[3];
      }
      #pragma unroll
      for (int mt = 0; mt < 4; ++mt)
        #pragma unroll
        for (int nt = 0; nt < 4; ++nt) {
          mma16816(acc[mt][nt], ah[mt],  bh[nt]);
          mma16816(acc[mt][nt], ah[mt],  bl[nt]);
          mma16816(acc[mt][nt], alr[mt], bh[nt]);
        }
    }

    if (c + 1 < nk) {
      stA(buf ^ 1);
      cp_wait0();
      __syncthreads();
    }
  }

  // epilogue: C fragment m16n8 -> rows (lane>>2, +8), cols (lane&3)*2
  int rbase = blockIdx.y*128 + mbase + (lane >> 2);
  int cbase = blockIdx.x*128 + nbase + (lane & 3)*2;
  #pragma unroll
  for (int mt = 0; mt < 4; ++mt) {
    #pragma unroll
    for (int half = 0; half < 2; ++half) {
      int row = rbase + mt*16 + half*8;
      float* cr = C + (size_t)row*N;
      if (mode == 0) {
        #pragma unroll
        for (int nt = 0; nt < 4; ++nt)
          *(float2*)(cr + cbase + nt*8) = make_float2(acc[mt][nt][half*2], acc[mt][nt][half*2+1]);
      } else if (mode == 1) {
        #pragma unroll
        for (int nt = 0; nt < 4; ++nt)
          *(float2*)(cr + cbase + nt*8) = make_float2(geluf(acc[mt][nt][half*2]), geluf(acc[mt][nt][half*2+1]));
      } else {
        int b = row >> 8;
        const float* g = gate + (size_t)b*6*Hd;
        #pragma unroll
        for (int nt = 0; nt < 4; ++nt) {
          int col = cbase + nt*8;
          float2 old = *(float2*)(cr + col);
          old.x += g[col]   * acc[mt][nt][half*2];
          old.y += g[col+1] * acc[mt][nt][half*2+1];
          *(float2*)(cr + col) = old;
        }
      }
    }
  }
}

// ---------------- attention: one CTA per (head, batch), flash over K ----------------
__global__ void __launch_bounds__(256) k_attn(const float* __restrict__ QKV,
                                              float* __restrict__ O)
{
  extern __shared__ float smf[];
  float* Ks = smf;                 // [256][64]
  float* Vs = smf + 256*64;        // [256][64]
  int hd = blockIdx.x, b = blockIdx.y;
  const float* base = QKV + (size_t)b*SEQ*3*Hd + hd*64;
  for (int i = threadIdx.x; i < 256*16; i += 256) {
    int r = i >> 4, d4 = (i & 15) << 2;
    *(float4*)&Ks[r*64 + d4] = *(const float4*)(base + (size_t)r*3*Hd + d4);
    *(float4*)&Vs[r*64 + d4] = *(const float4*)(base + (size_t)r*3*Hd + 2*Hd + d4);
  }
  int qi = threadIdx.x;
  float q[64];
  const float* qp = base + (size_t)qi*3*Hd + Hd;
  #pragma unroll
  for (int d = 0; d < 64; ++d) q[d] = qp[d]*0.125f;
  __syncthreads();
  float o[64];
  #pragma unroll
  for (int d = 0; d < 64; ++d) o[d] = 0.f;
  float m = -1e30f, l = 0.f;
  for (int kb = 0; kb < 256; kb += 16) {
    float s[16];
    float bm = -1e30f;
    #pragma unroll
    for (int kk = 0; kk < 16; ++kk) {
      const float* kr = &Ks[(kb+kk)*64];
      float t = 0.f;
      #pragma unroll
      for (int d = 0; d < 64; ++d) t += q[d]*kr[d];
      s[kk] = t;
      bm = fmaxf(bm, t);
    }
    float mn = fmaxf(m, bm);
    float corr = __expf(m - mn);
    l *= corr;
    #pragma unroll
    for (int d = 0; d < 64; ++d) o[d] *= corr;
    #pragma unroll
    for (int kk = 0; kk < 16; ++kk) {
      float p = __expf(s[kk] - mn);
      l += p;
      const float* vr = &Vs[(kb+kk)*64];
      #pragma unroll
      for (int d = 0; d < 64; ++d) o[d] += p*vr[d];
    }
    m = mn;
  }
  float inv = 1.f / l;
  float* op = O + (size_t)(b*SEQ + qi)*Hd + hd*64;
  #pragma unroll
  for (int d = 0; d < 64; ++d) op[d] = o[d]*inv;
}

// ---------------- final: LN+modulate, @ out_W + b, unpatchify ----------------
__global__ void __launch_bounds__(256) k_out(const float* __restrict__ X,
                                             const float* __restrict__ cm2,
                                             const float* __restrict__ oW,
                                             const float* __restrict__ ob,
                                             float* __restrict__ out)
{
  int row = blockIdx.x, b = row >> 8, n = row & 255, tid = threadIdx.x;
  const float* xr = X + (size_t)row*Hd;
  float v[4]; float s = 0.f, s2 = 0.f;
  #pragma unroll
  for (int i = 0; i < 4; ++i) { float t = xr[tid + i*256]; v[i] = t; s += t; s2 += t*t; }
  #pragma unroll
  for (int o = 16; o; o >>= 1) {
    s  += __shfl_xor_sync(0xffffffffu, s,  o);
    s2 += __shfl_xor_sync(0xffffffffu, s2, o);
  }
  __shared__ float ss[8], ss2[8];
  if ((tid & 31) == 0) { ss[tid>>5] = s; ss2[tid>>5] = s2; }
  __syncthreads();
  s = 0.f; s2 = 0.f;
  #pragma unroll
  for (int w = 0; w < 8; ++w) { s += ss[w]; s2 += ss2[w]; }
  float mean = s*(1.f/1024.f), var = s2*(1.f/1024.f) - mean*mean;
  float r = rsqrtf(var + 1e-6f);
  __shared__ float xm[Hd];
  const float* c2 = cm2 + b*2*Hd;
  #pragma unroll
  for (int i = 0; i < 4; ++i) {
    int col = tid + i*256;
    xm[col] = (v[i]-mean)*r*c2[Hd+col] + c2[col];
  }
  __syncthreads();
  int oi = tid >> 4, part = tid & 15;
  float acc = 0.f;
  const float* xp = xm + part*64;
  #pragma unroll
  for (int k = 0; k < 64; ++k) acc += xp[k]*oW[(part*64 + k)*16 + oi];
  __shared__ float red[256];
  red[tid] = acc;
  __syncthreads();
  if (part == 0) {
    float sum = 0.f;
    #pragma unroll
    for (int p = 0; p < 16; ++p) sum += red[oi*16 + p];
    sum += ob[oi];
    int ph = n >> 4, pw = n & 15;
    int p1 = oi >> 3, p2 = (oi >> 2) & 1, c = oi & 3;
    out[((b*32 + ph*2 + p1)*32 + (pw*2 + p2))*4 + c] = sum;
  }
}

// ---------------- host ----------------
extern "C" void kernel_launch(void* const* d_in, const int* in_sizes, int n_in,
                              void* d_out, int out_size)
{
  const float* x        = (const float*)d_in[0];
  const float* t        = (const float*)d_in[1];
  const int*   y        = (const int*)  d_in[2];
  const float* patch_W  = (const float*)d_in[3];
  const float* y_table  = (const float*)d_in[4];
  const float* t_W1     = (const float*)d_in[5];
  const float* t_W2     = (const float*)d_in[6];
  const float* adaln_W  = (const float*)d_in[7];
  const float* qkv_W    = (const float*)d_in[8];
  const float* proj_W   = (const float*)d_in[9];
  const float* mlp1_W   = (const float*)d_in[10];
  const float* mlp2_W   = (const float*)d_in[11];
  const float* out_mod_W= (const float*)d_in[12];
  const float* out_mod_b= (const float*)d_in[13];
  const float* out_W    = (const float*)d_in[14];
  const float* out_b    = (const float*)d_in[15];
  float* out = (float*)d_out;

  float *px, *pxm, *pqkv, *pattn, *pmlp, *pcm, *pcm2, *pte1, *psc;
  bf16 *pWh, *pWl;
  cudaGetSymbolAddress((void**)&px,   g_x);
  cudaGetSymbolAddress((void**)&pxm,  g_xm);
  cudaGetSymbolAddress((void**)&pqkv, g_qkv);
  cudaGetSymbolAddress((void**)&pattn,g_attn);
  cudaGetSymbolAddress((void**)&pmlp, g_mlp);
  cudaGetSymbolAddress((void**)&pcm,  g_cm);
  cudaGetSymbolAddress((void**)&pcm2, g_cm2);
  cudaGetSymbolAddress((void**)&pte1, g_te1);
  cudaGetSymbolAddress((void**)&psc,  g_sc);
  cudaGetSymbolAddress((void**)&pWh,  g_Wh);
  cudaGetSymbolAddress((void**)&pWl,  g_Wl);

  cudaFuncSetAttribute(k_attn, cudaFuncAttributeMaxDynamicSharedMemorySize, 131072);
  cudaFuncSetAttribute(k_gemm, cudaFuncAttributeMaxDynamicSharedMemorySize, 2*BUFSZ);

  for (int L = 0; L < DEPTH; ++L) {
    size_t base = (size_t)L * PER_L;
    k_wsplit<<<dim3(3*Hd/32, Hd/32), dim3(32,8)>>>(qkv_W + (size_t)L*Hd*3*Hd,
        pWh + base + OFF_QKV,  pWl + base + OFF_QKV,  Hd, 3*Hd);
    k_wsplit<<<dim3(Hd/32, Hd/32), dim3(32,8)>>>(proj_W + (size_t)L*Hd*Hd,
        pWh + base + OFF_PROJ, pWl + base + OFF_PROJ, Hd, Hd);
    k_wsplit<<<dim3(MHID/32, Hd/32), dim3(32,8)>>>(mlp1_W + (size_t)L*Hd*MHID,
        pWh + base + OFF_MLP1, pWl + base + OFF_MLP1, Hd, MHID);
    k_wsplit<<<dim3(Hd/32, MHID/32), dim3(32,8)>>>(mlp2_W + (size_t)L*MHID*Hd,
        pWh + base + OFF_MLP2, pWl + base + OFF_MLP2, MHID, Hd);
  }

  k_patch <<<NROWS, 256>>>(x, patch_W, px);
  k_temb  <<<NB, 256>>>(t, t_W1, pte1);
  k_cfinal<<<NB, 256>>>(pte1, t_W2, y_table, y, psc);

  for (int L = 0; L < DEPTH; ++L) {
    size_t base = (size_t)L * PER_L;
    k_cond <<<dim3(6*Hd/256, 4), 256>>>(psc, adaln_W + (size_t)L*Hd*6*Hd, nullptr, pcm, 6*Hd);
    k_lnmod<<<NROWS, 256>>>(px, pxm, pcm, 0, Hd);
    k_gemm <<<dim3(3*Hd/128, NROWS/128), 256, 2*BUFSZ>>>(pxm,
        pWh + base + OFF_QKV, pWl + base + OFF_QKV, pqkv, Hd, 3*Hd, 0, nullptr);
    k_attn <<<dim3(16, NB), 256, 131072>>>(pqkv, pattn);
    k_gemm <<<dim3(Hd/128, NROWS/128), 256, 2*BUFSZ>>>(pattn,
        pWh + base + OFF_PROJ, pWl + base + OFF_PROJ, px, Hd, Hd, 2, pcm + 2*Hd);
    k_lnmod<<<NROWS, 256>>>(px, pxm, pcm, 3*Hd, 4*Hd);
    k_gemm <<<dim3(MHID/128, NROWS/128), 256, 2*BUFSZ>>>(pxm,
        pWh + base + OFF_MLP1, pWl + base + OFF_MLP1, pmlp, Hd, MHID, 1, nullptr);
    k_gemm <<<dim3(Hd/128, NROWS/128), 256, 2*BUFSZ>>>(pmlp,
        pWh + base + OFF_MLP2, pWl + base + OFF_MLP2, px, MHID, Hd, 2, pcm + 5*Hd);
  }

  k_cond<<<dim3(2*Hd/256, 4), 256>>>(psc, out_mod_W, out_mod_b, pcm2, 2*Hd);
  k_out <<<NROWS, 256>>>(px, pcm2, out_W, out_b, out);
}

// round 12
// speedup vs baseline: 2.2666x; 1.0254x over previous
#include <cuda_runtime.h>
#include <cuda_bf16.h>
#include <math.h>

#define Hd    1024
#define SEQ   256
#define NB    32
#define NROWS (NB*SEQ)     // 8192
#define MHID  4096
#define DEPTH 12

typedef unsigned int u32;
typedef __nv_bfloat16 bf16;

// ---------------- device scratch (no allocations allowed) ----------------
__device__ float g_x   [NROWS*Hd];
__device__ float g_qkv [NROWS*3*Hd];
__device__ float g_cm  [NB*6*Hd];
__device__ float g_cm2 [NB*2*Hd];
__device__ float g_sc  [NB*Hd];
// bf16 hi/lo activation pairs
__device__ bf16 g_xmh[NROWS*Hd];
__device__ bf16 g_xml[NROWS*Hd];
__device__ bf16 g_ath[NROWS*Hd];
__device__ bf16 g_atl[NROWS*Hd];
__device__ bf16 g_mh [NROWS*MHID];
__device__ bf16 g_ml [NROWS*MHID];

// split/transposed weight arenas: per layer, [N][K] bf16, hi and lo
#define PER_L   (12582912ULL)
#define OFF_QKV (0ULL)
#define OFF_PROJ (3145728ULL)
#define OFF_MLP1 (4194304ULL)
#define OFF_MLP2 (8388608ULL)
__device__ bf16 g_Wh[PER_L*DEPTH];
__device__ bf16 g_Wl[PER_L*DEPTH];

__device__ __forceinline__ float geluf(float x){
  float t = 0.7978845608028654f * (x + 0.044715f * x*x*x);
  return x / (1.f + __expf(-2.f * t));
}

__device__ __forceinline__ u32 s2u(const void* p){
  u32 a;
  asm("{ .reg .u64 t; cvta.to.shared.u64 t, %1; cvt.u32.u64 %0, t; }" : "=r"(a) : "l"(p));
  return a;
}
__device__ __forceinline__ void mma16816(float* c, const u32* a, const u32* b){
  asm volatile("mma.sync.aligned.m16n8k16.row.col.f32.bf16.bf16.f32 "
    "{%0,%1,%2,%3},{%4,%5,%6,%7},{%8,%9},{%0,%1,%2,%3};"
    : "+f"(c[0]), "+f"(c[1]), "+f"(c[2]), "+f"(c[3])
    : "r"(a[0]), "r"(a[1]), "r"(a[2]), "r"(a[3]), "r"(b[0]), "r"(b[1]));
}
__device__ __forceinline__ void ldsm4(u32* r, u32 addr){
  asm volatile("ldmatrix.sync.aligned.m8n8.x4.shared.b16 {%0,%1,%2,%3}, [%4];"
    : "=r"(r[0]), "=r"(r[1]), "=r"(r[2]), "=r"(r[3]) : "r"(addr));
}
__device__ __forceinline__ void cp16(u32 dst, const void* src){
  asm volatile("cp.async.cg.shared.global [%0], [%1], 16;" :: "r"(dst), "l"(src) : "memory");
}
__device__ __forceinline__ void cp_commit(){ asm volatile("cp.async.commit_group;" ::: "memory"); }
__device__ __forceinline__ void cp_wait0(){ asm volatile("cp.async.wait_group 0;" ::: "memory"); }

__device__ __forceinline__ void split2(float a, float b, u32& hi, u32& lo){
  __nv_bfloat162 h = __floats2bfloat162_rn(a, b);
  float ra = a - __bfloat162float(h.x);
  float rb = b - __bfloat162float(h.y);
  __nv_bfloat162 l = __floats2bfloat162_rn(ra, rb);
  hi = *(u32*)&h; lo = *(u32*)&l;
}

// ---------------- weight split + transpose ----------------
__global__ void __launch_bounds__(256) k_wsplit(const float* __restrict__ W,
                                                bf16* __restrict__ Wh,
                                                bf16* __restrict__ Wl,
                                                int K, int N)
{
  __shared__ float tile[32][33];
  int tx = threadIdx.x, ty = threadIdx.y;
  int n0 = blockIdx.x*32, k0 = blockIdx.y*32;
  #pragma unroll
  for (int i = 0; i < 4; ++i)
    tile[ty + i*8][tx] = W[(size_t)(k0 + ty + i*8)*N + n0 + tx];
  __syncthreads();
  #pragma unroll
  for (int i = 0; i < 4; ++i) {
    float v = tile[tx][ty + i*8];
    bf16 h = __float2bfloat16_rn(v);
    bf16 l = __float2bfloat16_rn(v - __bfloat162float(h));
    size_t o = (size_t)(n0 + ty + i*8)*K + k0 + tx;
    Wh[o] = h; Wl[o] = l;
  }
}

// ---------------- patch embed + 2D sincos pos ----------------
__global__ void __launch_bounds__(256) k_patch(const float* __restrict__ x,
                                               const float* __restrict__ pW,
                                               float* __restrict__ XT)
{
  int row = blockIdx.x;
  int b = row >> 8, n = row & 255;
  int ph = n >> 4, pw = n & 15;
  __shared__ float xp[16];
  if (threadIdx.x < 16) {
    int f = threadIdx.x;
    int dy = f >> 3, dx = (f >> 2) & 1, c = f & 3;
    xp[f] = x[((b*32 + ph*2 + dy)*32 + (pw*2 + dx))*4 + c];
  }
  __syncthreads();
  #pragma unroll
  for (int i = 0; i < 4; ++i) {
    int col = threadIdx.x + i*256;
    float acc = 0.f;
    #pragma unroll
    for (int k = 0; k < 16; ++k) acc += xp[k] * pW[k*Hd + col];
    int j = col & 255, seg = col >> 8;
    float fr = expf(-logf(10000.f) * (float)j * (1.f/256.f));
    float a  = (seg < 2 ? (float)pw : (float)ph) * fr;
    float pos = ((seg & 1) == 0) ? sinf(a) : cosf(a);
    XT[(size_t)row*Hd + col] = acc + pos;
  }
}

// ---------------- fused timestep embed + conditioning vector ----------------
__global__ void __launch_bounds__(256) k_tembc(const float* __restrict__ t,
                                               const float* __restrict__ W1,
                                               const float* __restrict__ W2,
                                               const float* __restrict__ ytab,
                                               const int* __restrict__ y,
                                               float* __restrict__ SCout)
{
  int b = blockIdx.x, tid = threadIdx.x;
  __shared__ float e[256];
  __shared__ float te[Hd];
  {
    int j = tid & 127;
    float fr = expf(-logf(10000.f) * (float)j * (1.f/128.f));
    float a = t[b] * fr;
    e[tid] = (tid < 128 ? cosf(a) : sinf(a)) * 1.41421356237f;
  }
  __syncthreads();
  #pragma unroll
  for (int i = 0; i < 4; ++i) {
    int col = tid + i*256;
    float acc = 0.f;
    for (int k = 0; k < 256; ++k) acc += e[k] * W1[k*Hd + col];
    te[col] = acc / (1.f + expf(-acc));
  }
  __syncthreads();
  int yi = y[b];
  #pragma unroll
  for (int i = 0; i < 4; ++i) {
    int col = tid + i*256;
    float acc = 0.f;
    for (int k = 0; k < Hd; ++k) acc += te[k] * W2[k*Hd + col];
    float c = acc + ytab[(size_t)yi*Hd + col];
    SCout[b*Hd + col] = c / (1.f + expf(-c));
  }
}

// ---------------- conditioning GEMM (batch-grouped) ----------------
__global__ void __launch_bounds__(256) k_cond(const float* __restrict__ SC,
                                              const float* __restrict__ W,
                                              const float* __restrict__ bias,
                                              float* __restrict__ OUT, int N)
{
  __shared__ float a[8][Hd];
  int tid = threadIdx.x;
  int bg = blockIdx.y * 8;
  for (int idx = tid; idx < 8*Hd; idx += 256)
    a[idx >> 10][idx & 1023] = SC[(bg + (idx >> 10))*Hd + (idx & 1023)];
  __syncthreads();
  int c = blockIdx.x*256 + tid;
  float acc[8];
  #pragma unroll
  for (int b = 0; b < 8; ++b) acc[b] = 0.f;
  #pragma unroll 4
  for (int k = 0; k < Hd; ++k) {
    float w = W[(size_t)k*N + c];
    #pragma unroll
    for (int b = 0; b < 8; ++b) acc[b] += a[b][k]*w;
  }
  float bv = bias ? bias[c] : 0.f;
  #pragma unroll
  for (int b = 0; b < 8; ++b)
    OUT[(size_t)(bg + b)*N + c] = acc[b] + bv;
}

// ---------------- LN + modulate -> bf16 hi/lo ----------------
__global__ void __launch_bounds__(256) k_lnmod(const float* __restrict__ X,
                                               bf16* __restrict__ Yh,
                                               bf16* __restrict__ Yl,
                                               const float* __restrict__ cm,
                                               int shOff, int scOff)
{
  int row = blockIdx.x, b = row >> 8, tid = threadIdx.x;
  float4 v = *(const float4*)(X + (size_t)row*Hd + tid*4);
  float s = v.x + v.y + v.z + v.w;
  float s2 = v.x*v.x + v.y*v.y + v.z*v.z + v.w*v.w;
  #pragma unroll
  for (int o = 16; o; o >>= 1) {
    s  += __shfl_xor_sync(0xffffffffu, s,  o);
    s2 += __shfl_xor_sync(0xffffffffu, s2, o);
  }
  __shared__ float ss[8], ss2[8];
  if ((tid & 31) == 0) { ss[tid>>5] = s; ss2[tid>>5] = s2; }
  __syncthreads();
  s = 0.f; s2 = 0.f;
  #pragma unroll
  for (int w = 0; w < 8; ++w) { s += ss[w]; s2 += ss2[w]; }
  float mean = s * (1.f/1024.f);
  float var  = s2 * (1.f/1024.f) - mean*mean;
  float r = rsqrtf(var + 1e-6f);
  const float* cb = cm + b*6*Hd;
  int c0 = tid*4;
  float m0 = (v.x-mean)*r*cb[scOff+c0+0] + cb[shOff+c0+0];
  float m1 = (v.y-mean)*r*cb[scOff+c0+1] + cb[shOff+c0+1];
  float m2 = (v.z-mean)*r*cb[scOff+c0+2] + cb[shOff+c0+2];
  float m3 = (v.w-mean)*r*cb[scOff+c0+3] + cb[shOff+c0+3];
  u32 h01, l01, h23, l23;
  split2(m0, m1, h01, l01);
  split2(m2, m3, h23, l23);
  *(uint2*)(Yh + (size_t)row*Hd + c0) = make_uint2(h01, h23);
  *(uint2*)(Yl + (size_t)row*Hd + c0) = make_uint2(l01, l23);
}

// ---------------- bf16x3 mma.sync GEMM, all-cp.async ----------------
// mode 0: C=acc (fp32)  1: Ch/Cl = split(gelu(acc))  2: C += gate[b,col]*acc
#define ROWB  144              // padded row stride bytes (72 bf16)
#define MATSZ (128*ROWB)       // 18432 B per matrix
#define BUFSZ (4*MATSZ)        // Ah|Al|Bh|Bl = 73728 B
__global__ void __launch_bounds__(256) k_gemm(const bf16* __restrict__ Ah0,
                                              const bf16* __restrict__ Al0,
                                              const bf16* __restrict__ Wh,
                                              const bf16* __restrict__ Wl,
                                              float* __restrict__ C,
                                              bf16* __restrict__ Ch,
                                              bf16* __restrict__ Cl,
                                              int K, int N,
                                              int mode, const float* __restrict__ gate)
{
  extern __shared__ __align__(128) char smem[];
  const int tid = threadIdx.x, lane = tid & 31, wid = tid >> 5;
  const u32 sb = s2u(smem);

  const int mbase = (wid >> 2) * 64;
  const int nbase = (wid & 3) * 32;
  const int grp = lane >> 3, lr = lane & 7;
  const u32 aOff = (u32)(mbase + (grp & 1)*8 + lr) * ROWB + (grp >> 1)*16;
  const u32 bOff = (u32)(nbase + (grp >> 1)*8 + lr) * ROWB + (grp & 1)*16;

  const bf16* Ahg = Ah0 + (size_t)blockIdx.y * 128 * K;
  const bf16* Alg = Al0 + (size_t)blockIdx.y * 128 * K;
  const bf16* Bhg = Wh  + (size_t)blockIdx.x * 128 * K;
  const bf16* Blg = Wl  + (size_t)blockIdx.x * 128 * K;
  const int nk = K >> 6;

  float acc[4][4][4];
  #pragma unroll
  for (int i = 0; i < 4; ++i)
    #pragma unroll
    for (int j = 0; j < 4; ++j)
      #pragma unroll
      for (int q = 0; q < 4; ++q) acc[i][j][q] = 0.f;

  // per-thread load slot: row r (0..127), 16B col group c8 (0..7)
  const int lr8 = tid >> 3, lc8 = (tid & 7) << 3;
  auto cpAll = [&](int kt, int buf){
    u32 base = sb + buf*BUFSZ;
    #pragma unroll
    for (int i = 0; i < 4; ++i) {
      int r = lr8 + i*32;
      u32 off = (u32)r*ROWB + lc8*2;
      size_t go = (size_t)r*K + (kt << 6) + lc8;
      cp16(base + off,           Ahg + go);
      cp16(base + MATSZ + off,   Alg + go);
      cp16(base + 2*MATSZ + off, Bhg + go);
      cp16(base + 3*MATSZ + off, Blg + go);
    }
    cp_commit();
  };

  cpAll(0, 0);
  cp_wait0();
  __syncthreads();

  for (int c = 0; c < nk; ++c) {
    int buf = c & 1;
    if (c + 1 < nk) cpAll(c + 1, buf ^ 1);

    u32 baseA = sb + buf*BUFSZ;
    u32 baseB = baseA + 2*MATSZ;
    #pragma unroll
    for (int ks = 0; ks < 4; ++ks) {
      u32 ah[4][4], alr[4][4], bh[4][2], bl[4][2];
      #pragma unroll
      for (int mt = 0; mt < 4; ++mt) {
        u32 ad = baseA + aOff + mt*(16*ROWB) + ks*32;
        ldsm4(ah[mt], ad);
        ldsm4(alr[mt], ad + MATSZ);
      }
      #pragma unroll
      for (int np = 0; np < 2; ++np) {
        u32 r4[4], l4[4];
        u32 bd = baseB + bOff + np*(16*ROWB) + ks*32;
        ldsm4(r4, bd);
        ldsm4(l4, bd + MATSZ);
        bh[np*2][0]   = r4[0]; bh[np*2][1]   = r4[1];
        bh[np*2+1][0] = r4[2]; bh[np*2+1][1] = r4[3];
        bl[np*2][0]   = l4[0]; bl[np*2][1]   = l4[1];
        bl[np*2+1][0] = l4[2]; bl[np*2+1][1] = l4[3];
      }
      #pragma unroll
      for (int mt = 0; mt < 4; ++mt)
        #pragma unroll
        for (int nt = 0; nt < 4; ++nt) {
          mma16816(acc[mt][nt], ah[mt],  bh[nt]);
          mma16816(acc[mt][nt], ah[mt],  bl[nt]);
          mma16816(acc[mt][nt], alr[mt], bh[nt]);
        }
    }

    if (c + 1 < nk) {
      cp_wait0();
      __syncthreads();
    }
  }

  int rbase = blockIdx.y*128 + mbase + (lane >> 2);
  int cbase = blockIdx.x*128 + nbase + (lane & 3)*2;
  #pragma unroll
  for (int mt = 0; mt < 4; ++mt) {
    #pragma unroll
    for (int half = 0; half < 2; ++half) {
      int row = rbase + mt*16 + half*8;
      if (mode == 0) {
        float* cr = C + (size_t)row*N;
        #pragma unroll
        for (int nt = 0; nt < 4; ++nt)
          *(float2*)(cr + cbase + nt*8) = make_float2(acc[mt][nt][half*2], acc[mt][nt][half*2+1]);
      } else if (mode == 1) {
        bf16* crh = Ch + (size_t)row*N;
        bf16* crl = Cl + (size_t)row*N;
        #pragma unroll
        for (int nt = 0; nt < 4; ++nt) {
          float gx = geluf(acc[mt][nt][half*2]);
          float gy = geluf(acc[mt][nt][half*2+1]);
          u32 h, l;
          split2(gx, gy, h, l);
          *(u32*)(crh + cbase + nt*8) = h;
          *(u32*)(crl + cbase + nt*8) = l;
        }
      } else {
        int b = row >> 8;
        const float* g = gate + (size_t)b*6*Hd;
        float* cr = C + (size_t)row*N;
        #pragma unroll
        for (int nt = 0; nt < 4; ++nt) {
          int col = cbase + nt*8;
          float2 old = *(float2*)(cr + col);
          old.x += g[col]   * acc[mt][nt][half*2];
          old.y += g[col+1] * acc[mt][nt][half*2+1];
          *(float2*)(cr + col) = old;
        }
      }
    }
  }
}

// ---------------- attention -> bf16 hi/lo output ----------------
__global__ void __launch_bounds__(256) k_attn(const float* __restrict__ QKV,
                                              bf16* __restrict__ Oh,
                                              bf16* __restrict__ Ol)
{
  extern __shared__ float smf[];
  float* Ks = smf;                 // [256][64]
  float* Vs = smf + 256*64;        // [256][64]
  int hd = blockIdx.x, b = blockIdx.y;
  const float* base = QKV + (size_t)b*SEQ*3*Hd + hd*64;
  for (int i = threadIdx.x; i < 256*16; i += 256) {
    int r = i >> 4, d4 = (i & 15) << 2;
    *(float4*)&Ks[r*64 + d4] = *(const float4*)(base + (size_t)r*3*Hd + d4);
    *(float4*)&Vs[r*64 + d4] = *(const float4*)(base + (size_t)r*3*Hd + 2*Hd + d4);
  }
  int qi = threadIdx.x;
  float q[64];
  const float* qp = base + (size_t)qi*3*Hd + Hd;
  #pragma unroll
  for (int d = 0; d < 64; ++d) q[d] = qp[d]*0.125f;
  __syncthreads();
  float o[64];
  #pragma unroll
  for (int d = 0; d < 64; ++d) o[d] = 0.f;
  float m = -1e30f, l = 0.f;
  for (int kb = 0; kb < 256; kb += 16) {
    float s[16];
    float bm = -1e30f;
    #pragma unroll
    for (int kk = 0; kk < 16; ++kk) {
      const float* kr = &Ks[(kb+kk)*64];
      float t = 0.f;
      #pragma unroll
      for (int d = 0; d < 64; ++d) t += q[d]*kr[d];
      s[kk] = t;
      bm = fmaxf(bm, t);
    }
    float mn = fmaxf(m, bm);
    float corr = __expf(m - mn);
    l *= corr;
    #pragma unroll
    for (int d = 0; d < 64; ++d) o[d] *= corr;
    #pragma unroll
    for (int kk = 0; kk < 16; ++kk) {
      float p = __expf(s[kk] - mn);
      l += p;
      const float* vr = &Vs[(kb+kk)*64];
      #pragma unroll
      for (int d = 0; d < 64; ++d) o[d] += p*vr[d];
    }
    m = mn;
  }
  float inv = 1.f / l;
  size_t ob = (size_t)(b*SEQ + qi)*Hd + hd*64;
  #pragma unroll
  for (int d = 0; d < 64; d += 2) {
    u32 h, lo;
    split2(o[d]*inv, o[d+1]*inv, h, lo);
    *(u32*)(Oh + ob + d) = h;
    *(u32*)(Ol + ob + d) = lo;
  }
}

// ---------------- final: LN+modulate, @ out_W + b, unpatchify ----------------
__global__ void __launch_bounds__(256) k_out(const float* __restrict__ X,
                                             const float* __restrict__ cm2,
                                             const float* __restrict__ oW,
                                             const float* __restrict__ ob,
                                             float* __restrict__ out)
{
  int row = blockIdx.x, b = row >> 8, n = row & 255, tid = threadIdx.x;
  float4 v = *(const float4*)(X + (size_t)row*Hd + tid*4);
  float s = v.x + v.y + v.z + v.w;
  float s2 = v.x*v.x + v.y*v.y + v.z*v.z + v.w*v.w;
  #pragma unroll
  for (int o = 16; o; o >>= 1) {
    s  += __shfl_xor_sync(0xffffffffu, s,  o);
    s2 += __shfl_xor_sync(0xffffffffu, s2, o);
  }
  __shared__ float ss[8], ss2[8];
  if ((tid & 31) == 0) { ss[tid>>5] = s; ss2[tid>>5] = s2; }
  __syncthreads();
  s = 0.f; s2 = 0.f;
  #pragma unroll
  for (int w = 0; w < 8; ++w) { s += ss[w]; s2 += ss2[w]; }
  float mean = s*(1.f/1024.f), var = s2*(1.f/1024.f) - mean*mean;
  float r = rsqrtf(var + 1e-6f);
  __shared__ float xm[Hd];
  const float* c2 = cm2 + b*2*Hd;
  int c0 = tid*4;
  xm[c0+0] = (v.x-mean)*r*c2[Hd+c0+0] + c2[c0+0];
  xm[c0+1] = (v.y-mean)*r*c2[Hd+c0+1] + c2[c0+1];
  xm[c0+2] = (v.z-mean)*r*c2[Hd+c0+2] + c2[c0+2];
  xm[c0+3] = (v.w-mean)*r*c2[Hd+c0+3] + c2[c0+3];
  __syncthreads();
  int oi = tid >> 4, part = tid & 15;
  float acc = 0.f;
  const float* xp = xm + part*64;
  #pragma unroll
  for (int k = 0; k < 64; ++k) acc += xp[k]*oW[(part*64 + k)*16 + oi];
  __shared__ float red[256];
  red[tid] = acc;
  __syncthreads();
  if (part == 0) {
    float sum = 0.f;
    #pragma unroll
    for (int p = 0; p < 16; ++p) sum += red[oi*16 + p];
    sum += ob[oi];
    int ph = n >> 4, pw = n & 15;
    int p1 = oi >> 3, p2 = (oi >> 2) & 1, c = oi & 3;
    out[((b*32 + ph*2 + p1)*32 + (pw*2 + p2))*4 + c] = sum;
  }
}

// ---------------- host ----------------
extern "C" void kernel_launch(void* const* d_in, const int* in_sizes, int n_in,
                              void* d_out, int out_size)
{
  const float* x        = (const float*)d_in[0];
  const float* t        = (const float*)d_in[1];
  const int*   y        = (const int*)  d_in[2];
  const float* patch_W  = (const float*)d_in[3];
  const float* y_table  = (const float*)d_in[4];
  const float* t_W1     = (const float*)d_in[5];
  const float* t_W2     = (const float*)d_in[6];
  const float* adaln_W  = (const float*)d_in[7];
  const float* qkv_W    = (const float*)d_in[8];
  const float* proj_W   = (const float*)d_in[9];
  const float* mlp1_W   = (const float*)d_in[10];
  const float* mlp2_W   = (const float*)d_in[11];
  const float* out_mod_W= (const float*)d_in[12];
  const float* out_mod_b= (const float*)d_in[13];
  const float* out_W    = (const float*)d_in[14];
  const float* out_b    = (const float*)d_in[15];
  float* out = (float*)d_out;

  float *px, *pqkv, *pcm, *pcm2, *psc;
  bf16 *pxmh, *pxml, *path, *patl, *pmh, *pml, *pWh, *pWl;
  cudaGetSymbolAddress((void**)&px,   g_x);
  cudaGetSymbolAddress((void**)&pqkv, g_qkv);
  cudaGetSymbolAddress((void**)&pcm,  g_cm);
  cudaGetSymbolAddress((void**)&pcm2, g_cm2);
  cudaGetSymbolAddress((void**)&psc,  g_sc);
  cudaGetSymbolAddress((void**)&pxmh, g_xmh);
  cudaGetSymbolAddress((void**)&pxml, g_xml);
  cudaGetSymbolAddress((void**)&path, g_ath);
  cudaGetSymbolAddress((void**)&patl, g_atl);
  cudaGetSymbolAddress((void**)&pmh,  g_mh);
  cudaGetSymbolAddress((void**)&pml,  g_ml);
  cudaGetSymbolAddress((void**)&pWh,  g_Wh);
  cudaGetSymbolAddress((void**)&pWl,  g_Wl);

  cudaFuncSetAttribute(k_attn, cudaFuncAttributeMaxDynamicSharedMemorySize, 131072);
  cudaFuncSetAttribute(k_gemm, cudaFuncAttributeMaxDynamicSharedMemorySize, 2*BUFSZ);

  // ---- first 6 launches arranged so ncu (-s 5 -c 1) profiles k_gemm ----
  k_patch <<<NROWS, 256>>>(x, patch_W, px);
  {
    size_t base0 = 0;
    k_wsplit<<<dim3(3*Hd/32, Hd/32), dim3(32,8)>>>(qkv_W,
        pWh + base0 + OFF_QKV, pWl + base0 + OFF_QKV, Hd, 3*Hd);
  }
  k_tembc <<<NB, 256>>>(t, t_W1, t_W2, y_table, y, psc);
  k_cond  <<<dim3(6*Hd/256, 4), 256>>>(psc, adaln_W, nullptr, pcm, 6*Hd);
  k_lnmod <<<NROWS, 256>>>(px, pxmh, pxml, pcm, 0, Hd);
  k_gemm  <<<dim3(3*Hd/128, NROWS/128), 256, 2*BUFSZ>>>(pxmh, pxml,
      pWh + OFF_QKV, pWl + OFF_QKV, pqkv, nullptr, nullptr, Hd, 3*Hd, 0, nullptr);

  // remaining weight splits
  k_wsplit<<<dim3(Hd/32, Hd/32), dim3(32,8)>>>(proj_W,
      pWh + OFF_PROJ, pWl + OFF_PROJ, Hd, Hd);
  k_wsplit<<<dim3(MHID/32, Hd/32), dim3(32,8)>>>(mlp1_W,
      pWh + OFF_MLP1, pWl + OFF_MLP1, Hd, MHID);
  k_wsplit<<<dim3(Hd/32, MHID/32), dim3(32,8)>>>(mlp2_W,
      pWh + OFF_MLP2, pWl + OFF_MLP2, MHID, Hd);
  for (int L = 1; L < DEPTH; ++L) {
    size_t base = (size_t)L * PER_L;
    k_wsplit<<<dim3(3*Hd/32, Hd/32), dim3(32,8)>>>(qkv_W + (size_t)L*Hd*3*Hd,
        pWh + base + OFF_QKV,  pWl + base + OFF_QKV,  Hd, 3*Hd);
    k_wsplit<<<dim3(Hd/32, Hd/32), dim3(32,8)>>>(proj_W + (size_t)L*Hd*Hd,
        pWh + base + OFF_PROJ, pWl + base + OFF_PROJ, Hd, Hd);
    k_wsplit<<<dim3(MHID/32, Hd/32), dim3(32,8)>>>(mlp1_W + (size_t)L*Hd*MHID,
        pWh + base + OFF_MLP1, pWl + base + OFF_MLP1, Hd, MHID);
    k_wsplit<<<dim3(Hd/32, MHID/32), dim3(32,8)>>>(mlp2_W + (size_t)L*MHID*Hd,
        pWh + base + OFF_MLP2, pWl + base + OFF_MLP2, MHID, Hd);
  }

  // finish layer 0
  k_attn <<<dim3(16, NB), 256, 131072>>>(pqkv, path, patl);
  k_gemm <<<dim3(Hd/128, NROWS/128), 256, 2*BUFSZ>>>(path, patl,
      pWh + OFF_PROJ, pWl + OFF_PROJ, px, nullptr, nullptr, Hd, Hd, 2, pcm + 2*Hd);
  k_lnmod<<<NROWS, 256>>>(px, pxmh, pxml, pcm, 3*Hd, 4*Hd);
  k_gemm <<<dim3(MHID/128, NROWS/128), 256, 2*BUFSZ>>>(pxmh, pxml,
      pWh + OFF_MLP1, pWl + OFF_MLP1, nullptr, pmh, pml, Hd, MHID, 1, nullptr);
  k_gemm <<<dim3(Hd/128, NROWS/128), 256, 2*BUFSZ>>>(pmh, pml,
      pWh + OFF_MLP2, pWl + OFF_MLP2, px, nullptr, nullptr, MHID, Hd, 2, pcm + 5*Hd);

  // layers 1..11
  for (int L = 1; L < DEPTH; ++L) {
    size_t base = (size_t)L * PER_L;
    k_cond <<<dim3(6*Hd/256, 4), 256>>>(psc, adaln_W + (size_t)L*Hd*6*Hd, nullptr, pcm, 6*Hd);
    k_lnmod<<<NROWS, 256>>>(px, pxmh, pxml, pcm, 0, Hd);
    k_gemm <<<dim3(3*Hd/128, NROWS/128), 256, 2*BUFSZ>>>(pxmh, pxml,
        pWh + base + OFF_QKV, pWl + base + OFF_QKV, pqkv, nullptr, nullptr, Hd, 3*Hd, 0, nullptr);
    k_attn <<<dim3(16, NB), 256, 131072>>>(pqkv, path, patl);
    k_gemm <<<dim3(Hd/128, NROWS/128), 256, 2*BUFSZ>>>(path, patl,
        pWh + base + OFF_PROJ, pWl + base + OFF_PROJ, px, nullptr, nullptr, Hd, Hd, 2, pcm + 2*Hd);
    k_lnmod<<<NROWS, 256>>>(px, pxmh, pxml, pcm, 3*Hd, 4*Hd);
    k_gemm <<<dim3(MHID/128, NROWS/128), 256, 2*BUFSZ>>>(pxmh, pxml,
        pWh + base + OFF_MLP1, pWl + base + OFF_MLP1, nullptr, pmh, pml, Hd, MHID, 1, nullptr);
    k_gemm <<<dim3(Hd/128, NROWS/128), 256, 2*BUFSZ>>>(pmh, pml,
        pWh + base + OFF_MLP2, pWl + base + OFF_MLP2, px, nullptr, nullptr, MHID, Hd, 2, pcm + 5*Hd);
  }

  k_cond<<<dim3(2*Hd/256, 4), 256>>>(psc, out_mod_W, out_mod_b, pcm2, 2*Hd);
  k_out <<<NROWS, 256>>>(px, pcm2, out_W, out_b, out);
}

// round 13
// speedup vs baseline: 3.0089x; 1.3275x over previous
#include <cuda_runtime.h>
#include <cuda_fp16.h>
#include <math.h>

#define Hd    1024
#define SEQ   256
#define NB    32
#define NROWS (NB*SEQ)     // 8192
#define MHID  4096
#define DEPTH 12

typedef unsigned int u32;
typedef __half hlf;

// scales: weights x256, activations x16 -> acc = 4096 x true
#define WSCALE 256.0f
#define ASCALE 16.0f
#define OSCALE (1.0f/4096.0f)

// ---------------- device scratch (no allocations allowed) ----------------
__device__ float g_x   [NROWS*Hd];
__device__ float g_qkv [NROWS*3*Hd];
__device__ float g_cm  [NB*6*Hd];
__device__ float g_cm2 [NB*2*Hd];
__device__ float g_sc  [NB*Hd];
// fp16 hi/lo activation pairs (scaled x16)
__device__ hlf g_xmh[NROWS*Hd];
__device__ hlf g_xml[NROWS*Hd];
__device__ hlf g_ath[NROWS*Hd];
__device__ hlf g_atl[NROWS*Hd];
__device__ hlf g_mh [NROWS*MHID];
__device__ hlf g_ml [NROWS*MHID];

// weight arena: per layer [N][K] fp16 (hi only), scaled x256
#define PER_L   (12582912ULL)
#define OFF_QKV (0ULL)
#define OFF_PROJ (3145728ULL)
#define OFF_MLP1 (4194304ULL)
#define OFF_MLP2 (8388608ULL)
__device__ hlf g_Wh[PER_L*DEPTH];

__device__ __forceinline__ float geluf(float x){
  float t = 0.7978845608028654f * (x + 0.044715f * x*x*x);
  return x / (1.f + __expf(-2.f * t));
}
__device__ __forceinline__ u32 s2u(const void* p){
  u32 a;
  asm("{ .reg .u64 t; cvta.to.shared.u64 t, %1; cvt.u32.u64 %0, t; }" : "=r"(a) : "l"(p));
  return a;
}
__device__ __forceinline__ void mma16816(float* c, const u32* a, const u32* b){
  asm volatile("mma.sync.aligned.m16n8k16.row.col.f32.f16.f16.f32 "
    "{%0,%1,%2,%3},{%4,%5,%6,%7},{%8,%9},{%0,%1,%2,%3};"
    : "+f"(c[0]), "+f"(c[1]), "+f"(c[2]), "+f"(c[3])
    : "r"(a[0]), "r"(a[1]), "r"(a[2]), "r"(a[3]), "r"(b[0]), "r"(b[1]));
}
__device__ __forceinline__ void ldsm4(u32* r, u32 addr){
  asm volatile("ldmatrix.sync.aligned.m8n8.x4.shared.b16 {%0,%1,%2,%3}, [%4];"
    : "=r"(r[0]), "=r"(r[1]), "=r"(r[2]), "=r"(r[3]) : "r"(addr));
}
__device__ __forceinline__ void cp16(u32 dst, const void* src){
  asm volatile("cp.async.cg.shared.global [%0], [%1], 16;" :: "r"(dst), "l"(src) : "memory");
}
__device__ __forceinline__ void cp_commit(){ asm volatile("cp.async.commit_group;" ::: "memory"); }
__device__ __forceinline__ void cp_wait0(){ asm volatile("cp.async.wait_group 0;" ::: "memory"); }

// split scaled value pair into fp16 hi/lo
__device__ __forceinline__ void split2h(float a, float b, u32& hi, u32& lo){
  __half2 h = __floats2half2_rn(a, b);
  float ra = a - __half2float(__low2half(h));
  float rb = b - __half2float(__high2half(h));
  __half2 l = __floats2half2_rn(ra, rb);
  hi = *(u32*)&h; lo = *(u32*)&l;
}

// ---------------- weight convert + transpose (all layers, grid.z) ----------------
__global__ void __launch_bounds__(256) k_wsplit(const float* __restrict__ W,
                                                hlf* __restrict__ Wh,
                                                int K, int N, size_t wstride, size_t dstride)
{
  __shared__ float tile[32][33];
  int tx = threadIdx.x, ty = threadIdx.y;
  int n0 = blockIdx.x*32, k0 = blockIdx.y*32;
  const float* Wp = W + (size_t)blockIdx.z*wstride;
  hlf* Whp = Wh + (size_t)blockIdx.z*dstride;
  #pragma unroll
  for (int i = 0; i < 4; ++i)
    tile[ty + i*8][tx] = Wp[(size_t)(k0 + ty + i*8)*N + n0 + tx];
  __syncthreads();
  #pragma unroll
  for (int i = 0; i < 4; ++i) {
    float v = tile[tx][ty + i*8] * WSCALE;
    Whp[(size_t)(n0 + ty + i*8)*K + k0 + tx] = __float2half_rn(v);
  }
}

// ---------------- patch embed + 2D sincos pos ----------------
__global__ void __launch_bounds__(256) k_patch(const float* __restrict__ x,
                                               const float* __restrict__ pW,
                                               float* __restrict__ XT)
{
  int row = blockIdx.x;
  int b = row >> 8, n = row & 255;
  int ph = n >> 4, pw = n & 15;
  __shared__ float xp[16];
  if (threadIdx.x < 16) {
    int f = threadIdx.x;
    int dy = f >> 3, dx = (f >> 2) & 1, c = f & 3;
    xp[f] = x[((b*32 + ph*2 + dy)*32 + (pw*2 + dx))*4 + c];
  }
  __syncthreads();
  #pragma unroll
  for (int i = 0; i < 4; ++i) {
    int col = threadIdx.x + i*256;
    float acc = 0.f;
    #pragma unroll
    for (int k = 0; k < 16; ++k) acc += xp[k] * pW[k*Hd + col];
    int j = col & 255, seg = col >> 8;
    float fr = expf(-logf(10000.f) * (float)j * (1.f/256.f));
    float a  = (seg < 2 ? (float)pw : (float)ph) * fr;
    float pos = ((seg & 1) == 0) ? sinf(a) : cosf(a);
    XT[(size_t)row*Hd + col] = acc + pos;
  }
}

// ---------------- fused timestep embed + conditioning vector ----------------
__global__ void __launch_bounds__(256) k_tembc(const float* __restrict__ t,
                                               const float* __restrict__ W1,
                                               const float* __restrict__ W2,
                                               const float* __restrict__ ytab,
                                               const int* __restrict__ y,
                                               float* __restrict__ SCout)
{
  int b = blockIdx.x, tid = threadIdx.x;
  __shared__ float e[256];
  __shared__ float te[Hd];
  {
    int j = tid & 127;
    float fr = expf(-logf(10000.f) * (float)j * (1.f/128.f));
    float a = t[b] * fr;
    e[tid] = (tid < 128 ? cosf(a) : sinf(a)) * 1.41421356237f;
  }
  __syncthreads();
  #pragma unroll
  for (int i = 0; i < 4; ++i) {
    int col = tid + i*256;
    float acc = 0.f;
    for (int k = 0; k < 256; ++k) acc += e[k] * W1[k*Hd + col];
    te[col] = acc / (1.f + expf(-acc));
  }
  __syncthreads();
  int yi = y[b];
  #pragma unroll
  for (int i = 0; i < 4; ++i) {
    int col = tid + i*256;
    float acc = 0.f;
    for (int k = 0; k < Hd; ++k) acc += te[k] * W2[k*Hd + col];
    float c = acc + ytab[(size_t)yi*Hd + col];
    SCout[b*Hd + col] = c / (1.f + expf(-c));
  }
}

// ---------------- conditioning GEMM: one CTA per (batch, 256 cols) ----------------
__global__ void __launch_bounds__(256) k_cond(const float* __restrict__ SC,
                                              const float* __restrict__ W,
                                              const float* __restrict__ bias,
                                              float* __restrict__ OUT, int N)
{
  __shared__ float a[Hd];
  int tid = threadIdx.x, b = blockIdx.y;
  {
    float4 v = *(const float4*)(SC + (size_t)b*Hd + tid*4);
    *(float4*)(a + tid*4) = v;
  }
  __syncthreads();
  int c = blockIdx.x*256 + tid;
  const float* wp = W + c;
  float acc = 0.f;
  #pragma unroll 8
  for (int k = 0; k < Hd; ++k)
    acc += a[k] * wp[(size_t)k*N];
  OUT[(size_t)b*N + c] = acc + (bias ? bias[c] : 0.f);
}

// ---------------- LN + modulate -> fp16 hi/lo (x16) ----------------
__global__ void __launch_bounds__(256) k_lnmod(const float* __restrict__ X,
                                               hlf* __restrict__ Yh,
                                               hlf* __restrict__ Yl,
                                               const float* __restrict__ cm,
                                               int shOff, int scOff)
{
  int row = blockIdx.x, b = row >> 8, tid = threadIdx.x;
  float4 v = *(const float4*)(X + (size_t)row*Hd + tid*4);
  float s = v.x + v.y + v.z + v.w;
  float s2 = v.x*v.x + v.y*v.y + v.z*v.z + v.w*v.w;
  #pragma unroll
  for (int o = 16; o; o >>= 1) {
    s  += __shfl_xor_sync(0xffffffffu, s,  o);
    s2 += __shfl_xor_sync(0xffffffffu, s2, o);
  }
  __shared__ float ss[8], ss2[8];
  if ((tid & 31) == 0) { ss[tid>>5] = s; ss2[tid>>5] = s2; }
  __syncthreads();
  s = 0.f; s2 = 0.f;
  #pragma unroll
  for (int w = 0; w < 8; ++w) { s += ss[w]; s2 += ss2[w]; }
  float mean = s * (1.f/1024.f);
  float var  = s2 * (1.f/1024.f) - mean*mean;
  float r = rsqrtf(var + 1e-6f);
  const float* cb = cm + b*6*Hd;
  int c0 = tid*4;
  float m0 = ((v.x-mean)*r*cb[scOff+c0+0] + cb[shOff+c0+0]) * ASCALE;
  float m1 = ((v.y-mean)*r*cb[scOff+c0+1] + cb[shOff+c0+1]) * ASCALE;
  float m2 = ((v.z-mean)*r*cb[scOff+c0+2] + cb[shOff+c0+2]) * ASCALE;
  float m3 = ((v.w-mean)*r*cb[scOff+c0+3] + cb[shOff+c0+3]) * ASCALE;
  u32 h01, l01, h23, l23;
  split2h(m0, m1, h01, l01);
  split2h(m2, m3, h23, l23);
  *(uint2*)(Yh + (size_t)row*Hd + c0) = make_uint2(h01, h23);
  *(uint2*)(Yl + (size_t)row*Hd + c0) = make_uint2(l01, l23);
}

// ---------------- fp16x2 mma.sync GEMM ----------------
// acc = (Ah+Al) @ Bh, scaled 4096x; 2 MMAs per tile
// mode 0: C=acc/4096  1: Ch/Cl = split16(gelu(acc/4096))  2: C += gate*(acc/4096)
#define ROWB  144              // padded row stride bytes (72 halves)
#define MATSZ (128*ROWB)       // 18432 B per matrix
#define BUFSZ (3*MATSZ)        // Ah|Al|Bh = 55296 B
__global__ void __launch_bounds__(256) k_gemm(const hlf* __restrict__ Ah0,
                                              const hlf* __restrict__ Al0,
                                              const hlf* __restrict__ Wh,
                                              float* __restrict__ C,
                                              hlf* __restrict__ Ch,
                                              hlf* __restrict__ Cl,
                                              int K, int N,
                                              int mode, const float* __restrict__ gate)
{
  extern __shared__ __align__(128) char smem[];
  const int tid = threadIdx.x, lane = tid & 31, wid = tid >> 5;
  const u32 sb = s2u(smem);

  const int mbase = (wid >> 2) * 64;
  const int nbase = (wid & 3) * 32;
  const int grp = lane >> 3, lr = lane & 7;
  const u32 aOff = (u32)(mbase + (grp & 1)*8 + lr) * ROWB + (grp >> 1)*16;
  const u32 bOff = (u32)(nbase + (grp >> 1)*8 + lr) * ROWB + (grp & 1)*16;

  const hlf* Ahg = Ah0 + (size_t)blockIdx.y * 128 * K;
  const hlf* Alg = Al0 + (size_t)blockIdx.y * 128 * K;
  const hlf* Bhg = Wh  + (size_t)blockIdx.x * 128 * K;
  const int nk = K >> 6;

  float acc[4][4][4];
  #pragma unroll
  for (int i = 0; i < 4; ++i)
    #pragma unroll
    for (int j = 0; j < 4; ++j)
      #pragma unroll
      for (int q = 0; q < 4; ++q) acc[i][j][q] = 0.f;

  const int lr8 = tid >> 3, lc8 = (tid & 7) << 3;
  auto cpAll = [&](int kt, int buf){
    u32 base = sb + buf*BUFSZ;
    #pragma unroll
    for (int i = 0; i < 4; ++i) {
      int r = lr8 + i*32;
      u32 off = (u32)r*ROWB + lc8*2;
      size_t go = (size_t)r*K + (kt << 6) + lc8;
      cp16(base + off,           Ahg + go);
      cp16(base + MATSZ + off,   Alg + go);
      cp16(base + 2*MATSZ + off, Bhg + go);
    }
    cp_commit();
  };

  cpAll(0, 0);
  cp_wait0();
  __syncthreads();

  for (int c = 0; c < nk; ++c) {
    int buf = c & 1;
    if (c + 1 < nk) cpAll(c + 1, buf ^ 1);

    u32 baseA = sb + buf*BUFSZ;
    u32 baseB = baseA + 2*MATSZ;
    #pragma unroll
    for (int ks = 0; ks < 4; ++ks) {
      u32 ah[4][4], al[4][4], bh[4][2];
      #pragma unroll
      for (int mt = 0; mt < 4; ++mt) {
        u32 ad = baseA + aOff + mt*(16*ROWB) + ks*32;
        ldsm4(ah[mt], ad);
        ldsm4(al[mt], ad + MATSZ);
      }
      #pragma unroll
      for (int np = 0; np < 2; ++np) {
        u32 r4[4];
        ldsm4(r4, baseB + bOff + np*(16*ROWB) + ks*32);
        bh[np*2][0]   = r4[0]; bh[np*2][1]   = r4[1];
        bh[np*2+1][0] = r4[2]; bh[np*2+1][1] = r4[3];
      }
      #pragma unroll
      for (int mt = 0; mt < 4; ++mt)
        #pragma unroll
        for (int nt = 0; nt < 4; ++nt) {
          mma16816(acc[mt][nt], ah[mt], bh[nt]);
          mma16816(acc[mt][nt], al[mt], bh[nt]);
        }
    }

    if (c + 1 < nk) {
      cp_wait0();
      __syncthreads();
    }
  }

  int rbase = blockIdx.y*128 + mbase + (lane >> 2);
  int cbase = blockIdx.x*128 + nbase + (lane & 3)*2;
  #pragma unroll
  for (int mt = 0; mt < 4; ++mt) {
    #pragma unroll
    for (int half = 0; half < 2; ++half) {
      int row = rbase + mt*16 + half*8;
      if (mode == 0) {
        float* cr = C + (size_t)row*N;
        #pragma unroll
        for (int nt = 0; nt < 4; ++nt)
          *(float2*)(cr + cbase + nt*8) = make_float2(acc[mt][nt][half*2]*OSCALE,
                                                      acc[mt][nt][half*2+1]*OSCALE);
      } else if (mode == 1) {
        hlf* crh = Ch + (size_t)row*N;
        hlf* crl = Cl + (size_t)row*N;
        #pragma unroll
        for (int nt = 0; nt < 4; ++nt) {
          float gx = geluf(acc[mt][nt][half*2]*OSCALE) * ASCALE;
          float gy = geluf(acc[mt][nt][half*2+1]*OSCALE) * ASCALE;
          u32 h, l;
          split2h(gx, gy, h, l);
          *(u32*)(crh + cbase + nt*8) = h;
          *(u32*)(crl + cbase + nt*8) = l;
        }
      } else {
        int b = row >> 8;
        const float* g = gate + (size_t)b*6*Hd;
        float* cr = C + (size_t)row*N;
        #pragma unroll
        for (int nt = 0; nt < 4; ++nt) {
          int col = cbase + nt*8;
          float2 old = *(float2*)(cr + col);
          old.x += g[col]   * acc[mt][nt][half*2]  * OSCALE;
          old.y += g[col+1] * acc[mt][nt][half*2+1]* OSCALE;
          *(float2*)(cr + col) = old;
        }
      }
    }
  }
}

// ---------------- attention -> fp16 hi/lo output (x16) ----------------
__global__ void __launch_bounds__(256) k_attn(const float* __restrict__ QKV,
                                              hlf* __restrict__ Oh,
                                              hlf* __restrict__ Ol)
{
  extern __shared__ float smf[];
  float* Ks = smf;                 // [256][64]
  float* Vs = smf + 256*64;        // [256][64]
  int hd = blockIdx.x, b = blockIdx.y;
  const float* base = QKV + (size_t)b*SEQ*3*Hd + hd*64;
  for (int i = threadIdx.x; i < 256*16; i += 256) {
    int r = i >> 4, d4 = (i & 15) << 2;
    *(float4*)&Ks[r*64 + d4] = *(const float4*)(base + (size_t)r*3*Hd + d4);
    *(float4*)&Vs[r*64 + d4] = *(const float4*)(base + (size_t)r*3*Hd + 2*Hd + d4);
  }
  int qi = threadIdx.x;
  float q[64];
  const float* qp = base + (size_t)qi*3*Hd + Hd;
  #pragma unroll
  for (int d = 0; d < 64; ++d) q[d] = qp[d]*0.125f;
  __syncthreads();
  float o[64];
  #pragma unroll
  for (int d = 0; d < 64; ++d) o[d] = 0.f;
  float m = -1e30f, l = 0.f;
  for (int kb = 0; kb < 256; kb += 16) {
    float s[16];
    float bm = -1e30f;
    #pragma unroll
    for (int kk = 0; kk < 16; ++kk) {
      const float* kr = &Ks[(kb+kk)*64];
      float t = 0.f;
      #pragma unroll
      for (int d = 0; d < 64; ++d) t += q[d]*kr[d];
      s[kk] = t;
      bm = fmaxf(bm, t);
    }
    float mn = fmaxf(m, bm);
    float corr = __expf(m - mn);
    l *= corr;
    #pragma unroll
    for (int d = 0; d < 64; ++d) o[d] *= corr;
    #pragma unroll
    for (int kk = 0; kk < 16; ++kk) {
      float p = __expf(s[kk] - mn);
      l += p;
      const float* vr = &Vs[(kb+kk)*64];
      #pragma unroll
      for (int d = 0; d < 64; ++d) o[d] += p*vr[d];
    }
    m = mn;
  }
  float inv = ASCALE / l;
  size_t ob = (size_t)(b*SEQ + qi)*Hd + hd*64;
  #pragma unroll
  for (int d = 0; d < 64; d += 2) {
    u32 h, lo;
    split2h(o[d]*inv, o[d+1]*inv, h, lo);
    *(u32*)(Oh + ob + d) = h;
    *(u32*)(Ol + ob + d) = lo;
  }
}

// ---------------- final: LN+modulate, @ out_W + b, unpatchify ----------------
__global__ void __launch_bounds__(256) k_out(const float* __restrict__ X,
                                             const float* __restrict__ cm2,
                                             const float* __restrict__ oW,
                                             const float* __restrict__ ob,
                                             float* __restrict__ out)
{
  int row = blockIdx.x, b = row >> 8, n = row & 255, tid = threadIdx.x;
  float4 v = *(const float4*)(X + (size_t)row*Hd + tid*4);
  float s = v.x + v.y + v.z + v.w;
  float s2 = v.x*v.x + v.y*v.y + v.z*v.z + v.w*v.w;
  #pragma unroll
  for (int o = 16; o; o >>= 1) {
    s  += __shfl_xor_sync(0xffffffffu, s,  o);
    s2 += __shfl_xor_sync(0xffffffffu, s2, o);
  }
  __shared__ float ss[8], ss2[8];
  if ((tid & 31) == 0) { ss[tid>>5] = s; ss2[tid>>5] = s2; }
  __syncthreads();
  s = 0.f; s2 = 0.f;
  #pragma unroll
  for (int w = 0; w < 8; ++w) { s += ss[w]; s2 += ss2[w]; }
  float mean = s*(1.f/1024.f), var = s2*(1.f/1024.f) - mean*mean;
  float r = rsqrtf(var + 1e-6f);
  __shared__ float xm[Hd];
  const float* c2 = cm2 + b*2*Hd;
  int c0 = tid*4;
  xm[c0+0] = (v.x-mean)*r*c2[Hd+c0+0] + c2[c0+0];
  xm[c0+1] = (v.y-mean)*r*c2[Hd+c0+1] + c2[c0+1];
  xm[c0+2] = (v.z-mean)*r*c2[Hd+c0+2] + c2[c0+2];
  xm[c0+3] = (v.w-mean)*r*c2[Hd+c0+3] + c2[c0+3];
  __syncthreads();
  int oi = tid >> 4, part = tid & 15;
  float acc = 0.f;
  const float* xp = xm + part*64;
  #pragma unroll
  for (int k = 0; k < 64; ++k) acc += xp[k]*oW[(part*64 + k)*16 + oi];
  __shared__ float red[256];
  red[tid] = acc;
  __syncthreads();
  if (part == 0) {
    float sum = 0.f;
    #pragma unroll
    for (int p = 0; p < 16; ++p) sum += red[oi*16 + p];
    sum += ob[oi];
    int ph = n >> 4, pw = n & 15;
    int p1 = oi >> 3, p2 = (oi >> 2) & 1, c = oi & 3;
    out[((b*32 + ph*2 + p1)*32 + (pw*2 + p2))*4 + c] = sum;
  }
}

// ---------------- host ----------------
extern "C" void kernel_launch(void* const* d_in, const int* in_sizes, int n_in,
                              void* d_out, int out_size)
{
  const float* x        = (const float*)d_in[0];
  const float* t        = (const float*)d_in[1];
  const int*   y        = (const int*)  d_in[2];
  const float* patch_W  = (const float*)d_in[3];
  const float* y_table  = (const float*)d_in[4];
  const float* t_W1     = (const float*)d_in[5];
  const float* t_W2     = (const float*)d_in[6];
  const float* adaln_W  = (const float*)d_in[7];
  const float* qkv_W    = (const float*)d_in[8];
  const float* proj_W   = (const float*)d_in[9];
  const float* mlp1_W   = (const float*)d_in[10];
  const float* mlp2_W   = (const float*)d_in[11];
  const float* out_mod_W= (const float*)d_in[12];
  const float* out_mod_b= (const float*)d_in[13];
  const float* out_W    = (const float*)d_in[14];
  const float* out_b    = (const float*)d_in[15];
  float* out = (float*)d_out;

  float *px, *pqkv, *pcm, *pcm2, *psc;
  hlf *pxmh, *pxml, *path, *patl, *pmh, *pml, *pWh;
  cudaGetSymbolAddress((void**)&px,   g_x);
  cudaGetSymbolAddress((void**)&pqkv, g_qkv);
  cudaGetSymbolAddress((void**)&pcm,  g_cm);
  cudaGetSymbolAddress((void**)&pcm2, g_cm2);
  cudaGetSymbolAddress((void**)&psc,  g_sc);
  cudaGetSymbolAddress((void**)&pxmh, g_xmh);
  cudaGetSymbolAddress((void**)&pxml, g_xml);
  cudaGetSymbolAddress((void**)&path, g_ath);
  cudaGetSymbolAddress((void**)&patl, g_atl);
  cudaGetSymbolAddress((void**)&pmh,  g_mh);
  cudaGetSymbolAddress((void**)&pml,  g_ml);
  cudaGetSymbolAddress((void**)&pWh,  g_Wh);

  cudaFuncSetAttribute(k_attn, cudaFuncAttributeMaxDynamicSharedMemorySize, 131072);
  cudaFuncSetAttribute(k_gemm, cudaFuncAttributeMaxDynamicSharedMemorySize, 2*BUFSZ);

  // weight conversion, batched over layers via grid.z
  k_wsplit<<<dim3(3*Hd/32, Hd/32, DEPTH), dim3(32,8)>>>(qkv_W,
      pWh + OFF_QKV,  Hd, 3*Hd, (size_t)Hd*3*Hd, PER_L);
  k_wsplit<<<dim3(Hd/32, Hd/32, DEPTH), dim3(32,8)>>>(proj_W,
      pWh + OFF_PROJ, Hd, Hd,   (size_t)Hd*Hd,   PER_L);
  k_wsplit<<<dim3(MHID/32, Hd/32, DEPTH), dim3(32,8)>>>(mlp1_W,
      pWh + OFF_MLP1, Hd, MHID, (size_t)Hd*MHID, PER_L);
  k_wsplit<<<dim3(Hd/32, MHID/32, DEPTH), dim3(32,8)>>>(mlp2_W,
      pWh + OFF_MLP2, MHID, Hd, (size_t)MHID*Hd, PER_L);

  k_patch <<<NROWS, 256>>>(x, patch_W, px);
  k_tembc <<<NB, 256>>>(t, t_W1, t_W2, y_table, y, psc);

  for (int L = 0; L < DEPTH; ++L) {
    size_t base = (size_t)L * PER_L;
    k_cond <<<dim3(6*Hd/256, NB), 256>>>(psc, adaln_W + (size_t)L*Hd*6*Hd, nullptr, pcm, 6*Hd);
    k_lnmod<<<NROWS, 256>>>(px, pxmh, pxml, pcm, 0, Hd);
    k_gemm <<<dim3(3*Hd/128, NROWS/128), 256, 2*BUFSZ>>>(pxmh, pxml,
        pWh + base + OFF_QKV, pqkv, nullptr, nullptr, Hd, 3*Hd, 0, nullptr);
    k_attn <<<dim3(16, NB), 256, 131072>>>(pqkv, path, patl);
    k_gemm <<<dim3(Hd/128, NROWS/128), 256, 2*BUFSZ>>>(path, patl,
        pWh + base + OFF_PROJ, px, nullptr, nullptr, Hd, Hd, 2, pcm + 2*Hd);
    k_lnmod<<<NROWS, 256>>>(px, pxmh, pxml, pcm, 3*Hd, 4*Hd);
    k_gemm <<<dim3(MHID/128, NROWS/128), 256, 2*BUFSZ>>>(pxmh, pxml,
        pWh + base + OFF_MLP1, nullptr, pmh, pml, Hd, MHID, 1, nullptr);
    k_gemm <<<dim3(Hd/128, NROWS/128), 256, 2*BUFSZ>>>(pmh, pml,
        pWh + base + OFF_MLP2, px, nullptr, nullptr, MHID, Hd, 2, pcm + 5*Hd);
  }

  k_cond<<<dim3(2*Hd/256, NB), 256>>>(psc, out_mod_W, out_mod_b, pcm2, 2*Hd);
  k_out <<<NROWS, 256>>>(px, pcm2, out_W, out_b, out);
}

// round 14
// speedup vs baseline: 4.4611x; 1.4826x over previous
#include <cuda_runtime.h>
#include <cuda_fp16.h>
#include <math.h>

#define Hd    1024
#define SEQ   256
#define NB    32
#define NROWS (NB*SEQ)     // 8192
#define MHID  4096
#define DEPTH 12

typedef unsigned int u32;
typedef __half hlf;

// scales: weights x256, activations x16 -> acc = 4096 x true
#define WSCALE 256.0f
#define ASCALE 16.0f
#define OSCALE (1.0f/4096.0f)

// ---------------- device scratch (no allocations allowed) ----------------
__device__ float g_x   [NROWS*Hd];
__device__ float g_qkv [NROWS*3*Hd];
__device__ float g_cm  [NB*6*Hd];
__device__ float g_cm2 [NB*2*Hd];
__device__ float g_sc  [NB*Hd];
// fp16 activations (scaled x16)
__device__ hlf g_xmh[NROWS*Hd];
__device__ hlf g_ath[NROWS*Hd];
__device__ hlf g_mh [NROWS*MHID];

// weight arena: per layer [N][K] fp16, scaled x256
#define PER_L   (12582912ULL)
#define OFF_QKV (0ULL)
#define OFF_PROJ (3145728ULL)
#define OFF_MLP1 (4194304ULL)
#define OFF_MLP2 (8388608ULL)
__device__ hlf g_Wh[PER_L*DEPTH];

__device__ __forceinline__ float geluf(float x){
  float t = 0.7978845608028654f * (x + 0.044715f * x*x*x);
  return x / (1.f + __expf(-2.f * t));
}
__device__ __forceinline__ u32 s2u(const void* p){
  u32 a;
  asm("{ .reg .u64 t; cvta.to.shared.u64 t, %1; cvt.u32.u64 %0, t; }" : "=r"(a) : "l"(p));
  return a;
}
__device__ __forceinline__ void mma16816(float* c, const u32* a, const u32* b){
  asm volatile("mma.sync.aligned.m16n8k16.row.col.f32.f16.f16.f32 "
    "{%0,%1,%2,%3},{%4,%5,%6,%7},{%8,%9},{%0,%1,%2,%3};"
    : "+f"(c[0]), "+f"(c[1]), "+f"(c[2]), "+f"(c[3])
    : "r"(a[0]), "r"(a[1]), "r"(a[2]), "r"(a[3]), "r"(b[0]), "r"(b[1]));
}
__device__ __forceinline__ void ldsm4(u32* r, u32 addr){
  asm volatile("ldmatrix.sync.aligned.m8n8.x4.shared.b16 {%0,%1,%2,%3}, [%4];"
    : "=r"(r[0]), "=r"(r[1]), "=r"(r[2]), "=r"(r[3]) : "r"(addr));
}
__device__ __forceinline__ void cp16(u32 dst, const void* src){
  asm volatile("cp.async.cg.shared.global [%0], [%1], 16;" :: "r"(dst), "l"(src) : "memory");
}
__device__ __forceinline__ void cp_commit(){ asm volatile("cp.async.commit_group;" ::: "memory"); }
__device__ __forceinline__ void cp_wait0(){ asm volatile("cp.async.wait_group 0;" ::: "memory"); }

// ---------------- weight convert + transpose (all layers, grid.z) ----------------
__global__ void __launch_bounds__(256) k_wsplit(const float* __restrict__ W,
                                                hlf* __restrict__ Wh,
                                                int K, int N, size_t wstride, size_t dstride)
{
  __shared__ float tile[32][33];
  int tx = threadIdx.x, ty = threadIdx.y;
  int n0 = blockIdx.x*32, k0 = blockIdx.y*32;
  const float* Wp = W + (size_t)blockIdx.z*wstride;
  hlf* Whp = Wh + (size_t)blockIdx.z*dstride;
  #pragma unroll
  for (int i = 0; i < 4; ++i)
    tile[ty + i*8][tx] = Wp[(size_t)(k0 + ty + i*8)*N + n0 + tx];
  __syncthreads();
  #pragma unroll
  for (int i = 0; i < 4; ++i) {
    float v = tile[tx][ty + i*8] * WSCALE;
    Whp[(size_t)(n0 + ty + i*8)*K + k0 + tx] = __float2half_rn(v);
  }
}

// ---------------- patch embed + 2D sincos pos ----------------
__global__ void __launch_bounds__(256) k_patch(const float* __restrict__ x,
                                               const float* __restrict__ pW,
                                               float* __restrict__ XT)
{
  int row = blockIdx.x;
  int b = row >> 8, n = row & 255;
  int ph = n >> 4, pw = n & 15;
  __shared__ float xp[16];
  if (threadIdx.x < 16) {
    int f = threadIdx.x;
    int dy = f >> 3, dx = (f >> 2) & 1, c = f & 3;
    xp[f] = x[((b*32 + ph*2 + dy)*32 + (pw*2 + dx))*4 + c];
  }
  __syncthreads();
  #pragma unroll
  for (int i = 0; i < 4; ++i) {
    int col = threadIdx.x + i*256;
    float acc = 0.f;
    #pragma unroll
    for (int k = 0; k < 16; ++k) acc += xp[k] * pW[k*Hd + col];
    int j = col & 255, seg = col >> 8;
    float fr = expf(-logf(10000.f) * (float)j * (1.f/256.f));
    float a  = (seg < 2 ? (float)pw : (float)ph) * fr;
    float pos = ((seg & 1) == 0) ? sinf(a) : cosf(a);
    XT[(size_t)row*Hd + col] = acc + pos;
  }
}

// ---------------- fused timestep embed + conditioning vector ----------------
__global__ void __launch_bounds__(256) k_tembc(const float* __restrict__ t,
                                               const float* __restrict__ W1,
                                               const float* __restrict__ W2,
                                               const float* __restrict__ ytab,
                                               const int* __restrict__ y,
                                               float* __restrict__ SCout)
{
  int b = blockIdx.x, tid = threadIdx.x;
  __shared__ float e[256];
  __shared__ float te[Hd];
  {
    int j = tid & 127;
    float fr = expf(-logf(10000.f) * (float)j * (1.f/128.f));
    float a = t[b] * fr;
    e[tid] = (tid < 128 ? cosf(a) : sinf(a)) * 1.41421356237f;
  }
  __syncthreads();
  #pragma unroll
  for (int i = 0; i < 4; ++i) {
    int col = tid + i*256;
    float acc = 0.f;
    for (int k = 0; k < 256; ++k) acc += e[k] * W1[k*Hd + col];
    te[col] = acc / (1.f + expf(-acc));
  }
  __syncthreads();
  int yi = y[b];
  #pragma unroll
  for (int i = 0; i < 4; ++i) {
    int col = tid + i*256;
    float acc = 0.f;
    for (int k = 0; k < Hd; ++k) acc += te[k] * W2[k*Hd + col];
    float c = acc + ytab[(size_t)yi*Hd + col];
    SCout[b*Hd + col] = c / (1.f + expf(-c));
  }
}

// ---------------- conditioning GEMM: one CTA per (batch, 256 cols) ----------------
__global__ void __launch_bounds__(256) k_cond(const float* __restrict__ SC,
                                              const float* __restrict__ W,
                                              const float* __restrict__ bias,
                                              float* __restrict__ OUT, int N)
{
  __shared__ float a[Hd];
  int tid = threadIdx.x, b = blockIdx.y;
  {
    float4 v = *(const float4*)(SC + (size_t)b*Hd + tid*4);
    *(float4*)(a + tid*4) = v;
  }
  __syncthreads();
  int c = blockIdx.x*256 + tid;
  const float* wp = W + c;
  float acc = 0.f;
  #pragma unroll 8
  for (int k = 0; k < Hd; ++k)
    acc += a[k] * wp[(size_t)k*N];
  OUT[(size_t)b*N + c] = acc + (bias ? bias[c] : 0.f);
}

// ---------------- LN + modulate -> fp16 (x16) ----------------
__global__ void __launch_bounds__(256) k_lnmod(const float* __restrict__ X,
                                               hlf* __restrict__ Yh,
                                               const float* __restrict__ cm,
                                               int shOff, int scOff)
{
  int row = blockIdx.x, b = row >> 8, tid = threadIdx.x;
  float4 v = *(const float4*)(X + (size_t)row*Hd + tid*4);
  float s = v.x + v.y + v.z + v.w;
  float s2 = v.x*v.x + v.y*v.y + v.z*v.z + v.w*v.w;
  #pragma unroll
  for (int o = 16; o; o >>= 1) {
    s  += __shfl_xor_sync(0xffffffffu, s,  o);
    s2 += __shfl_xor_sync(0xffffffffu, s2, o);
  }
  __shared__ float ss[8], ss2[8];
  if ((tid & 31) == 0) { ss[tid>>5] = s; ss2[tid>>5] = s2; }
  __syncthreads();
  s = 0.f; s2 = 0.f;
  #pragma unroll
  for (int w = 0; w < 8; ++w) { s += ss[w]; s2 += ss2[w]; }
  float mean = s * (1.f/1024.f);
  float var  = s2 * (1.f/1024.f) - mean*mean;
  float r = rsqrtf(var + 1e-6f);
  const float* cb = cm + b*6*Hd;
  int c0 = tid*4;
  float m0 = ((v.x-mean)*r*cb[scOff+c0+0] + cb[shOff+c0+0]) * ASCALE;
  float m1 = ((v.y-mean)*r*cb[scOff+c0+1] + cb[shOff+c0+1]) * ASCALE;
  float m2 = ((v.z-mean)*r*cb[scOff+c0+2] + cb[shOff+c0+2]) * ASCALE;
  float m3 = ((v.w-mean)*r*cb[scOff+c0+3] + cb[shOff+c0+3]) * ASCALE;
  __half2 h0 = __floats2half2_rn(m0, m1);
  __half2 h1 = __floats2half2_rn(m2, m3);
  *(uint2*)(Yh + (size_t)row*Hd + c0) = make_uint2(*(u32*)&h0, *(u32*)&h1);
}

// ---------------- fp16 mma.sync GEMM, tile 256x128, 1 MMA/tile ----------------
// acc = A @ B, scaled 4096x
// mode 0: C=acc/4096  1: Ch = f16(gelu(acc/4096)*16)  2: C += gate*(acc/4096)
#define ROWB   144              // padded row stride bytes (72 halves)
#define AMATSZ (256*ROWB)       // 36864 B
#define BMATSZ (128*ROWB)       // 18432 B
#define BUFSZ  (AMATSZ+BMATSZ)  // 55296 B
__global__ void __launch_bounds__(256) k_gemm(const hlf* __restrict__ Ah0,
                                              const hlf* __restrict__ Wh,
                                              float* __restrict__ C,
                                              hlf* __restrict__ Ch,
                                              int K, int N,
                                              int mode, const float* __restrict__ gate)
{
  extern __shared__ __align__(128) char smem[];
  const int tid = threadIdx.x, lane = tid & 31, wid = tid >> 5;
  const u32 sb = s2u(smem);

  const int mbase = (wid & 3) * 64;    // 4 M-warps x 64 rows
  const int nbase = (wid >> 2) * 64;   // 2 N-warps x 64 cols
  const int grp = lane >> 3, lr = lane & 7;
  const u32 aOff = (u32)(mbase + (grp & 1)*8 + lr) * ROWB + (grp >> 1)*16;
  const u32 bOff = (u32)(nbase + (grp >> 1)*8 + lr) * ROWB + (grp & 1)*16;

  const hlf* Ahg = Ah0 + (size_t)blockIdx.y * 256 * K;
  const hlf* Bhg = Wh  + (size_t)blockIdx.x * 128 * K;
  const int nk = K >> 6;

  float acc[4][8][4];
  #pragma unroll
  for (int i = 0; i < 4; ++i)
    #pragma unroll
    for (int j = 0; j < 8; ++j)
      #pragma unroll
      for (int q = 0; q < 4; ++q) acc[i][j][q] = 0.f;

  const int lr8 = tid >> 3, lc8 = (tid & 7) << 3;
  auto cpAll = [&](int kt, int buf){
    u32 base = sb + buf*BUFSZ;
    #pragma unroll
    for (int i = 0; i < 8; ++i) {            // A: 256 rows
      int r = lr8 + i*32;
      cp16(base + (u32)r*ROWB + lc8*2, Ahg + (size_t)r*K + (kt << 6) + lc8);
    }
    #pragma unroll
    for (int i = 0; i < 4; ++i) {            // B: 128 rows
      int r = lr8 + i*32;
      cp16(base + AMATSZ + (u32)r*ROWB + lc8*2, Bhg + (size_t)r*K + (kt << 6) + lc8);
    }
    cp_commit();
  };

  cpAll(0, 0);
  cp_wait0();
  __syncthreads();

  for (int c = 0; c < nk; ++c) {
    int buf = c & 1;
    if (c + 1 < nk) cpAll(c + 1, buf ^ 1);

    u32 baseA = sb + buf*BUFSZ;
    u32 baseB = baseA + AMATSZ;
    #pragma unroll
    for (int ks = 0; ks < 4; ++ks) {
      u32 ah[4][4], bh[8][2];
      #pragma unroll
      for (int mt = 0; mt < 4; ++mt)
        ldsm4(ah[mt], baseA + aOff + mt*(16*ROWB) + ks*32);
      #pragma unroll
      for (int np = 0; np < 4; ++np) {
        u32 r4[4];
        ldsm4(r4, baseB + bOff + np*(16*ROWB) + ks*32);
        bh[np*2][0]   = r4[0]; bh[np*2][1]   = r4[1];
        bh[np*2+1][0] = r4[2]; bh[np*2+1][1] = r4[3];
      }
      #pragma unroll
      for (int mt = 0; mt < 4; ++mt)
        #pragma unroll
        for (int nt = 0; nt < 8; ++nt)
          mma16816(acc[mt][nt], ah[mt], bh[nt]);
    }

    if (c + 1 < nk) {
      cp_wait0();
      __syncthreads();
    }
  }

  // epilogue: batch index == blockIdx.y (256 rows per batch per CTA)
  int rbase = blockIdx.y*256 + mbase + (lane >> 2);
  int cbase = blockIdx.x*128 + nbase + (lane & 3)*2;
  const float* g = (mode == 2) ? (gate + (size_t)blockIdx.y*6*Hd) : nullptr;
  #pragma unroll
  for (int mt = 0; mt < 4; ++mt) {
    #pragma unroll
    for (int half = 0; half < 2; ++half) {
      int row = rbase + mt*16 + half*8;
      if (mode == 0) {
        float* cr = C + (size_t)row*N;
        #pragma unroll
        for (int nt = 0; nt < 8; ++nt)
          *(float2*)(cr + cbase + nt*8) = make_float2(acc[mt][nt][half*2]*OSCALE,
                                                      acc[mt][nt][half*2+1]*OSCALE);
      } else if (mode == 1) {
        hlf* crh = Ch + (size_t)row*N;
        #pragma unroll
        for (int nt = 0; nt < 8; ++nt) {
          float gx = geluf(acc[mt][nt][half*2]*OSCALE) * ASCALE;
          float gy = geluf(acc[mt][nt][half*2+1]*OSCALE) * ASCALE;
          __half2 h = __floats2half2_rn(gx, gy);
          *(u32*)(crh + cbase + nt*8) = *(u32*)&h;
        }
      } else {
        float* cr = C + (size_t)row*N;
        #pragma unroll
        for (int nt = 0; nt < 8; ++nt) {
          int col = cbase + nt*8;
          float2 old = *(float2*)(cr + col);
          old.x += g[col]   * acc[mt][nt][half*2]  * OSCALE;
          old.y += g[col+1] * acc[mt][nt][half*2+1]* OSCALE;
          *(float2*)(cr + col) = old;
        }
      }
    }
  }
}

// ---------------- attention -> fp16 output (x16) ----------------
__global__ void __launch_bounds__(256) k_attn(const float* __restrict__ QKV,
                                              hlf* __restrict__ Oh)
{
  extern __shared__ float smf[];
  float* Ks = smf;                 // [256][64]
  float* Vs = smf + 256*64;        // [256][64]
  int hd = blockIdx.x, b = blockIdx.y;
  const float* base = QKV + (size_t)b*SEQ*3*Hd + hd*64;
  for (int i = threadIdx.x; i < 256*16; i += 256) {
    int r = i >> 4, d4 = (i & 15) << 2;
    *(float4*)&Ks[r*64 + d4] = *(const float4*)(base + (size_t)r*3*Hd + d4);
    *(float4*)&Vs[r*64 + d4] = *(const float4*)(base + (size_t)r*3*Hd + 2*Hd + d4);
  }
  int qi = threadIdx.x;
  float q[64];
  const float* qp = base + (size_t)qi*3*Hd + Hd;
  #pragma unroll
  for (int d = 0; d < 64; ++d) q[d] = qp[d]*0.125f;
  __syncthreads();
  float o[64];
  #pragma unroll
  for (int d = 0; d < 64; ++d) o[d] = 0.f;
  float m = -1e30f, l = 0.f;
  for (int kb = 0; kb < 256; kb += 16) {
    float s[16];
    float bm = -1e30f;
    #pragma unroll
    for (int kk = 0; kk < 16; ++kk) {
      const float* kr = &Ks[(kb+kk)*64];
      float t = 0.f;
      #pragma unroll
      for (int d = 0; d < 64; ++d) t += q[d]*kr[d];
      s[kk] = t;
      bm = fmaxf(bm, t);
    }
    float mn = fmaxf(m, bm);
    float corr = __expf(m - mn);
    l *= corr;
    #pragma unroll
    for (int d = 0; d < 64; ++d) o[d] *= corr;
    #pragma unroll
    for (int kk = 0; kk < 16; ++kk) {
      float p = __expf(s[kk] - mn);
      l += p;
      const float* vr = &Vs[(kb+kk)*64];
      #pragma unroll
      for (int d = 0; d < 64; ++d) o[d] += p*vr[d];
    }
    m = mn;
  }
  float inv = ASCALE / l;
  size_t ob = (size_t)(b*SEQ + qi)*Hd + hd*64;
  #pragma unroll
  for (int d = 0; d < 64; d += 2) {
    __half2 h = __floats2half2_rn(o[d]*inv, o[d+1]*inv);
    *(u32*)(Oh + ob + d) = *(u32*)&h;
  }
}

// ---------------- final: LN+modulate, @ out_W + b, unpatchify ----------------
__global__ void __launch_bounds__(256) k_out(const float* __restrict__ X,
                                             const float* __restrict__ cm2,
                                             const float* __restrict__ oW,
                                             const float* __restrict__ ob,
                                             float* __restrict__ out)
{
  int row = blockIdx.x, b = row >> 8, n = row & 255, tid = threadIdx.x;
  float4 v = *(const float4*)(X + (size_t)row*Hd + tid*4);
  float s = v.x + v.y + v.z + v.w;
  float s2 = v.x*v.x + v.y*v.y + v.z*v.z + v.w*v.w;
  #pragma unroll
  for (int o = 16; o; o >>= 1) {
    s  += __shfl_xor_sync(0xffffffffu, s,  o);
    s2 += __shfl_xor_sync(0xffffffffu, s2, o);
  }
  __shared__ float ss[8], ss2[8];
  if ((tid & 31) == 0) { ss[tid>>5] = s; ss2[tid>>5] = s2; }
  __syncthreads();
  s = 0.f; s2 = 0.f;
  #pragma unroll
  for (int w = 0; w < 8; ++w) { s += ss[w]; s2 += ss2[w]; }
  float mean = s*(1.f/1024.f), var = s2*(1.f/1024.f) - mean*mean;
  float r = rsqrtf(var + 1e-6f);
  __shared__ float xm[Hd];
  const float* c2 = cm2 + b*2*Hd;
  int c0 = tid*4;
  xm[c0+0] = (v.x-mean)*r*c2[Hd+c0+0] + c2[c0+0];
  xm[c0+1] = (v.y-mean)*r*c2[Hd+c0+1] + c2[c0+1];
  xm[c0+2] = (v.z-mean)*r*c2[Hd+c0+2] + c2[c0+2];
  xm[c0+3] = (v.w-mean)*r*c2[Hd+c0+3] + c2[c0+3];
  __syncthreads();
  int oi = tid >> 4, part = tid & 15;
  float acc = 0.f;
  const float* xp = xm + part*64;
  #pragma unroll
  for (int k = 0; k < 64; ++k) acc += xp[k]*oW[(part*64 + k)*16 + oi];
  __shared__ float red[256];
  red[tid] = acc;
  __syncthreads();
  if (part == 0) {
    float sum = 0.f;
    #pragma unroll
    for (int p = 0; p < 16; ++p) sum += red[oi*16 + p];
    sum += ob[oi];
    int ph = n >> 4, pw = n & 15;
    int p1 = oi >> 3, p2 = (oi >> 2) & 1, c = oi & 3;
    out[((b*32 + ph*2 + p1)*32 + (pw*2 + p2))*4 + c] = sum;
  }
}

// ---------------- host ----------------
extern "C" void kernel_launch(void* const* d_in, const int* in_sizes, int n_in,
                              void* d_out, int out_size)
{
  const float* x        = (const float*)d_in[0];
  const float* t        = (const float*)d_in[1];
  const int*   y        = (const int*)  d_in[2];
  const float* patch_W  = (const float*)d_in[3];
  const float* y_table  = (const float*)d_in[4];
  const float* t_W1     = (const float*)d_in[5];
  const float* t_W2     = (const float*)d_in[6];
  const float* adaln_W  = (const float*)d_in[7];
  const float* qkv_W    = (const float*)d_in[8];
  const float* proj_W   = (const float*)d_in[9];
  const float* mlp1_W   = (const float*)d_in[10];
  const float* mlp2_W   = (const float*)d_in[11];
  const float* out_mod_W= (const float*)d_in[12];
  const float* out_mod_b= (const float*)d_in[13];
  const float* out_W    = (const float*)d_in[14];
  const float* out_b    = (const float*)d_in[15];
  float* out = (float*)d_out;

  float *px, *pqkv, *pcm, *pcm2, *psc;
  hlf *pxmh, *path, *pmh, *pWh;
  cudaGetSymbolAddress((void**)&px,   g_x);
  cudaGetSymbolAddress((void**)&pqkv, g_qkv);
  cudaGetSymbolAddress((void**)&pcm,  g_cm);
  cudaGetSymbolAddress((void**)&pcm2, g_cm2);
  cudaGetSymbolAddress((void**)&psc,  g_sc);
  cudaGetSymbolAddress((void**)&pxmh, g_xmh);
  cudaGetSymbolAddress((void**)&path, g_ath);
  cudaGetSymbolAddress((void**)&pmh,  g_mh);
  cudaGetSymbolAddress((void**)&pWh,  g_Wh);

  cudaFuncSetAttribute(k_attn, cudaFuncAttributeMaxDynamicSharedMemorySize, 131072);
  cudaFuncSetAttribute(k_gemm, cudaFuncAttributeMaxDynamicSharedMemorySize, 2*BUFSZ);

  // weight conversion, batched over layers via grid.z
  k_wsplit<<<dim3(3*Hd/32, Hd/32, DEPTH), dim3(32,8)>>>(qkv_W,
      pWh + OFF_QKV,  Hd, 3*Hd, (size_t)Hd*3*Hd, PER_L);
  k_wsplit<<<dim3(Hd/32, Hd/32, DEPTH), dim3(32,8)>>>(proj_W,
      pWh + OFF_PROJ, Hd, Hd,   (size_t)Hd*Hd,   PER_L);
  k_wsplit<<<dim3(MHID/32, Hd/32, DEPTH), dim3(32,8)>>>(mlp1_W,
      pWh + OFF_MLP1, Hd, MHID, (size_t)Hd*MHID, PER_L);
  k_wsplit<<<dim3(Hd/32, MHID/32, DEPTH), dim3(32,8)>>>(mlp2_W,
      pWh + OFF_MLP2, MHID, Hd, (size_t)MHID*Hd, PER_L);

  k_patch <<<NROWS, 256>>>(x, patch_W, px);
  k_tembc <<<NB, 256>>>(t, t_W1, t_W2, y_table, y, psc);

  for (int L = 0; L < DEPTH; ++L) {
    size_t base = (size_t)L * PER_L;
    k_cond <<<dim3(6*Hd/256, NB), 256>>>(psc, adaln_W + (size_t)L*Hd*6*Hd, nullptr, pcm, 6*Hd);
    k_lnmod<<<NROWS, 256>>>(px, pxmh, pcm, 0, Hd);
    k_gemm <<<dim3(3*Hd/128, NROWS/256), 256, 2*BUFSZ>>>(pxmh,
        pWh + base + OFF_QKV, pqkv, nullptr, Hd, 3*Hd, 0, nullptr);
    k_attn <<<dim3(16, NB), 256, 131072>>>(pqkv, path);
    k_gemm <<<dim3(Hd/128, NROWS/256), 256, 2*BUFSZ>>>(path,
        pWh + base + OFF_PROJ, px, nullptr, Hd, Hd, 2, pcm + 2*Hd);
    k_lnmod<<<NROWS, 256>>>(px, pxmh, pcm, 3*Hd, 4*Hd);
    k_gemm <<<dim3(MHID/128, NROWS/256), 256, 2*BUFSZ>>>(pxmh,
        pWh + base + OFF_MLP1, nullptr, pmh, Hd, MHID, 1, nullptr);
    k_gemm <<<dim3(Hd/128, NROWS/256), 256, 2*BUFSZ>>>(pmh,
        pWh + base + OFF_MLP2, px, nullptr, MHID, Hd, 2, pcm + 5*Hd);
  }

  k_cond<<<dim3(2*Hd/256, NB), 256>>>(psc, out_mod_W, out_mod_b, pcm2, 2*Hd);
  k_out <<<NROWS, 256>>>(px, pcm2, out_W, out_b, out);
}

// round 15
// speedup vs baseline: 4.5331x; 1.0161x over previous
#include <cuda_runtime.h>
#include <cuda_fp16.h>
#include <math.h>

#define Hd    1024
#define SEQ   256
#define NB    32
#define NROWS (NB*SEQ)     // 8192
#define MHID  4096
#define DEPTH 12

typedef unsigned int u32;
typedef __half hlf;

// scales: weights x256, activations x16 -> acc = 4096 x true
#define WSCALE 256.0f
#define ASCALE 16.0f
#define OSCALE (1.0f/4096.0f)

// ---------------- device scratch (no allocations allowed) ----------------
__device__ float g_x   [NROWS*Hd];
__device__ float g_cm  [NB*6*Hd];
__device__ float g_cm2 [NB*2*Hd];
__device__ float g_sc  [NB*Hd];
// fp16 activations
__device__ hlf g_qkvh[NROWS*3*Hd];   // true values
__device__ hlf g_xmh [NROWS*Hd];     // x16
__device__ hlf g_ath [NROWS*Hd];     // x16
__device__ hlf g_mh  [NROWS*MHID];   // x16

// weight arena: per layer [N][K] fp16, scaled x256
#define PER_L   (12582912ULL)
#define OFF_QKV (0ULL)
#define OFF_PROJ (3145728ULL)
#define OFF_MLP1 (4194304ULL)
#define OFF_MLP2 (8388608ULL)
__device__ hlf g_Wh[PER_L*DEPTH];

__device__ __forceinline__ float geluf(float x){
  float t = 0.7978845608028654f * (x + 0.044715f * x*x*x);
  return x / (1.f + __expf(-2.f * t));
}
// fast exp for x <= 0 (softmax): 2^n * poly(f), no MUFU
__device__ __forceinline__ float fexp(float x){
  float t = fmaxf(x * 1.44269504089f, -100.f);
  int n = __float2int_rn(t);
  float f = t - (float)n;
  float p = 1.333355815e-3f;
  p = p*f + 9.618129107e-3f;
  p = p*f + 5.550410866e-2f;
  p = p*f + 2.402265069e-1f;
  p = p*f + 6.931471806e-1f;
  p = p*f + 1.0f;
  return __int_as_float(__float_as_int(p) + (n << 23));
}
__device__ __forceinline__ u32 s2u(const void* p){
  u32 a;
  asm("{ .reg .u64 t; cvta.to.shared.u64 t, %1; cvt.u32.u64 %0, t; }" : "=r"(a) : "l"(p));
  return a;
}
__device__ __forceinline__ void mma16816(float* c, const u32* a, const u32* b){
  asm volatile("mma.sync.aligned.m16n8k16.row.col.f32.f16.f16.f32 "
    "{%0,%1,%2,%3},{%4,%5,%6,%7},{%8,%9},{%0,%1,%2,%3};"
    : "+f"(c[0]), "+f"(c[1]), "+f"(c[2]), "+f"(c[3])
    : "r"(a[0]), "r"(a[1]), "r"(a[2]), "r"(a[3]), "r"(b[0]), "r"(b[1]));
}
__device__ __forceinline__ void ldsm4(u32* r, u32 addr){
  asm volatile("ldmatrix.sync.aligned.m8n8.x4.shared.b16 {%0,%1,%2,%3}, [%4];"
    : "=r"(r[0]), "=r"(r[1]), "=r"(r[2]), "=r"(r[3]) : "r"(addr));
}
__device__ __forceinline__ void cp16(u32 dst, const void* src){
  asm volatile("cp.async.cg.shared.global [%0], [%1], 16;" :: "r"(dst), "l"(src) : "memory");
}
__device__ __forceinline__ void cp_commit(){ asm volatile("cp.async.commit_group;" ::: "memory"); }

// ---------------- weight convert + transpose (all layers, grid.z) ----------------
__global__ void __launch_bounds__(256) k_wsplit(const float* __restrict__ W,
                                                hlf* __restrict__ Wh,
                                                int K, int N, size_t wstride, size_t dstride)
{
  __shared__ float tile[32][33];
  int tx = threadIdx.x, ty = threadIdx.y;
  int n0 = blockIdx.x*32, k0 = blockIdx.y*32;
  const float* Wp = W + (size_t)blockIdx.z*wstride;
  hlf* Whp = Wh + (size_t)blockIdx.z*dstride;
  #pragma unroll
  for (int i = 0; i < 4; ++i)
    tile[ty + i*8][tx] = Wp[(size_t)(k0 + ty + i*8)*N + n0 + tx];
  __syncthreads();
  #pragma unroll
  for (int i = 0; i < 4; ++i) {
    float v = tile[tx][ty + i*8] * WSCALE;
    Whp[(size_t)(n0 + ty + i*8)*K + k0 + tx] = __float2half_rn(v);
  }
}

// ---------------- patch embed + 2D sincos pos ----------------
__global__ void __launch_bounds__(256) k_patch(const float* __restrict__ x,
                                               const float* __restrict__ pW,
                                               float* __restrict__ XT)
{
  int row = blockIdx.x;
  int b = row >> 8, n = row & 255;
  int ph = n >> 4, pw = n & 15;
  __shared__ float xp[16];
  if (threadIdx.x < 16) {
    int f = threadIdx.x;
    int dy = f >> 3, dx = (f >> 2) & 1, c = f & 3;
    xp[f] = x[((b*32 + ph*2 + dy)*32 + (pw*2 + dx))*4 + c];
  }
  __syncthreads();
  #pragma unroll
  for (int i = 0; i < 4; ++i) {
    int col = threadIdx.x + i*256;
    float acc = 0.f;
    #pragma unroll
    for (int k = 0; k < 16; ++k) acc += xp[k] * pW[k*Hd + col];
    int j = col & 255, seg = col >> 8;
    float fr = expf(-logf(10000.f) * (float)j * (1.f/256.f));
    float a  = (seg < 2 ? (float)pw : (float)ph) * fr;
    float pos = ((seg & 1) == 0) ? sinf(a) : cosf(a);
    XT[(size_t)row*Hd + col] = acc + pos;
  }
}

// ---------------- fused timestep embed + conditioning vector ----------------
__global__ void __launch_bounds__(256) k_tembc(const float* __restrict__ t,
                                               const float* __restrict__ W1,
                                               const float* __restrict__ W2,
                                               const float* __restrict__ ytab,
                                               const int* __restrict__ y,
                                               float* __restrict__ SCout)
{
  int b = blockIdx.x, tid = threadIdx.x;
  __shared__ float e[256];
  __shared__ float te[Hd];
  {
    int j = tid & 127;
    float fr = expf(-logf(10000.f) * (float)j * (1.f/128.f));
    float a = t[b] * fr;
    e[tid] = (tid < 128 ? cosf(a) : sinf(a)) * 1.41421356237f;
  }
  __syncthreads();
  #pragma unroll
  for (int i = 0; i < 4; ++i) {
    int col = tid + i*256;
    float acc = 0.f;
    for (int k = 0; k < 256; ++k) acc += e[k] * W1[k*Hd + col];
    te[col] = acc / (1.f + expf(-acc));
  }
  __syncthreads();
  int yi = y[b];
  #pragma unroll
  for (int i = 0; i < 4; ++i) {
    int col = tid + i*256;
    float acc = 0.f;
    for (int k = 0; k < Hd; ++k) acc += te[k] * W2[k*Hd + col];
    float c = acc + ytab[(size_t)yi*Hd + col];
    SCout[b*Hd + col] = c / (1.f + expf(-c));
  }
}

// ---------------- conditioning GEMM: one CTA per (batch, 256 cols) ----------------
__global__ void __launch_bounds__(256) k_cond(const float* __restrict__ SC,
                                              const float* __restrict__ W,
                                              const float* __restrict__ bias,
                                              float* __restrict__ OUT, int N)
{
  __shared__ float a[Hd];
  int tid = threadIdx.x, b = blockIdx.y;
  {
    float4 v = *(const float4*)(SC + (size_t)b*Hd + tid*4);
    *(float4*)(a + tid*4) = v;
  }
  __syncthreads();
  int c = blockIdx.x*256 + tid;
  const float* wp = W + c;
  float acc = 0.f;
  #pragma unroll 8
  for (int k = 0; k < Hd; ++k)
    acc += a[k] * wp[(size_t)k*N];
  OUT[(size_t)b*N + c] = acc + (bias ? bias[c] : 0.f);
}

// ---------------- LN + modulate -> fp16 (x16) ----------------
__global__ void __launch_bounds__(256) k_lnmod(const float* __restrict__ X,
                                               hlf* __restrict__ Yh,
                                               const float* __restrict__ cm,
                                               int shOff, int scOff)
{
  int row = blockIdx.x, b = row >> 8, tid = threadIdx.x;
  float4 v = *(const float4*)(X + (size_t)row*Hd + tid*4);
  float s = v.x + v.y + v.z + v.w;
  float s2 = v.x*v.x + v.y*v.y + v.z*v.z + v.w*v.w;
  #pragma unroll
  for (int o = 16; o; o >>= 1) {
    s  += __shfl_xor_sync(0xffffffffu, s,  o);
    s2 += __shfl_xor_sync(0xffffffffu, s2, o);
  }
  __shared__ float ss[8], ss2[8];
  if ((tid & 31) == 0) { ss[tid>>5] = s; ss2[tid>>5] = s2; }
  __syncthreads();
  s = 0.f; s2 = 0.f;
  #pragma unroll
  for (int w = 0; w < 8; ++w) { s += ss[w]; s2 += ss2[w]; }
  float mean = s * (1.f/1024.f);
  float var  = s2 * (1.f/1024.f) - mean*mean;
  float r = rsqrtf(var + 1e-6f);
  const float* cb = cm + b*6*Hd;
  int c0 = tid*4;
  float m0 = ((v.x-mean)*r*cb[scOff+c0+0] + cb[shOff+c0+0]) * ASCALE;
  float m1 = ((v.y-mean)*r*cb[scOff+c0+1] + cb[shOff+c0+1]) * ASCALE;
  float m2 = ((v.z-mean)*r*cb[scOff+c0+2] + cb[shOff+c0+2]) * ASCALE;
  float m3 = ((v.w-mean)*r*cb[scOff+c0+3] + cb[shOff+c0+3]) * ASCALE;
  __half2 h0 = __floats2half2_rn(m0, m1);
  __half2 h1 = __floats2half2_rn(m2, m3);
  *(uint2*)(Yh + (size_t)row*Hd + c0) = make_uint2(*(u32*)&h0, *(u32*)&h1);
}

// ---------------- fp16 mma.sync GEMM, tile 256x128, 3-stage pipeline ----------------
// acc = A @ B, scaled 4096x
// mode 0: Ch=f16(acc/4096)  1: Ch=f16(gelu(acc/4096)*16)  2: C += gate*(acc/4096)
#define ROWB   144              // padded row stride bytes (72 halves)
#define AMATSZ (256*ROWB)       // 36864 B
#define BMATSZ (128*ROWB)       // 18432 B
#define BUFSZ  (AMATSZ+BMATSZ)  // 55296 B
__global__ void __launch_bounds__(256) k_gemm(const hlf* __restrict__ Ah0,
                                              const hlf* __restrict__ Wh,
                                              float* __restrict__ C,
                                              hlf* __restrict__ Ch,
                                              int K, int N,
                                              int mode, const float* __restrict__ gate)
{
  extern __shared__ __align__(128) char smem[];
  const int tid = threadIdx.x, lane = tid & 31, wid = tid >> 5;
  const u32 sb = s2u(smem);

  const int mbase = (wid & 3) * 64;    // 4 M-warps x 64 rows
  const int nbase = (wid >> 2) * 64;   // 2 N-warps x 64 cols
  const int grp = lane >> 3, lr = lane & 7;
  const u32 aOff = (u32)(mbase + (grp & 1)*8 + lr) * ROWB + (grp >> 1)*16;
  const u32 bOff = (u32)(nbase + (grp >> 1)*8 + lr) * ROWB + (grp & 1)*16;

  const hlf* Ahg = Ah0 + (size_t)blockIdx.y * 256 * K;
  const hlf* Bhg = Wh  + (size_t)blockIdx.x * 128 * K;
  const int nk = K >> 6;

  float acc[4][8][4];
  #pragma unroll
  for (int i = 0; i < 4; ++i)
    #pragma unroll
    for (int j = 0; j < 8; ++j)
      #pragma unroll
      for (int q = 0; q < 4; ++q) acc[i][j][q] = 0.f;

  const int lr8 = tid >> 3, lc8 = (tid & 7) << 3;
  auto cpAll = [&](int kt, int buf){
    u32 base = sb + buf*BUFSZ;
    #pragma unroll
    for (int i = 0; i < 8; ++i) {            // A: 256 rows
      int r = lr8 + i*32;
      cp16(base + (u32)r*ROWB + lc8*2, Ahg + (size_t)r*K + (kt << 6) + lc8);
    }
    #pragma unroll
    for (int i = 0; i < 4; ++i) {            // B: 128 rows
      int r = lr8 + i*32;
      cp16(base + AMATSZ + (u32)r*ROWB + lc8*2, Bhg + (size_t)r*K + (kt << 6) + lc8);
    }
    cp_commit();
  };

  cpAll(0, 0);
  cpAll(1, 1);
  asm volatile("cp.async.wait_group 1;" ::: "memory");
  __syncthreads();

  for (int c = 0; c < nk; ++c) {
    int buf = c % 3;
    if (c + 2 < nk) cpAll(c + 2, (c + 2) % 3);

    u32 baseA = sb + buf*BUFSZ;
    u32 baseB = baseA + AMATSZ;
    #pragma unroll
    for (int ks = 0; ks < 4; ++ks) {
      u32 ah[4][4], bh[8][2];
      #pragma unroll
      for (int mt = 0; mt < 4; ++mt)
        ldsm4(ah[mt], baseA + aOff + mt*(16*ROWB) + ks*32);
      #pragma unroll
      for (int np = 0; np < 4; ++np) {
        u32 r4[4];
        ldsm4(r4, baseB + bOff + np*(16*ROWB) + ks*32);
        bh[np*2][0]   = r4[0]; bh[np*2][1]   = r4[1];
        bh[np*2+1][0] = r4[2]; bh[np*2+1][1] = r4[3];
      }
      #pragma unroll
      for (int mt = 0; mt < 4; ++mt)
        #pragma unroll
        for (int nt = 0; nt < 8; ++nt)
          mma16816(acc[mt][nt], ah[mt], bh[nt]);
    }

    if (c + 1 < nk) {
      if (c + 2 < nk) asm volatile("cp.async.wait_group 1;" ::: "memory");
      else            asm volatile("cp.async.wait_group 0;" ::: "memory");
      __syncthreads();
    }
  }

  // epilogue: batch index == blockIdx.y (256 rows per batch per CTA)
  int rbase = blockIdx.y*256 + mbase + (lane >> 2);
  int cbase = blockIdx.x*128 + nbase + (lane & 3)*2;
  const float* g = (mode == 2) ? (gate + (size_t)blockIdx.y*6*Hd) : nullptr;
  #pragma unroll
  for (int mt = 0; mt < 4; ++mt) {
    #pragma unroll
    for (int half = 0; half < 2; ++half) {
      int row = rbase + mt*16 + half*8;
      if (mode == 0) {
        hlf* crh = Ch + (size_t)row*N;
        #pragma unroll
        for (int nt = 0; nt < 8; ++nt) {
          __half2 h = __floats2half2_rn(acc[mt][nt][half*2]*OSCALE,
                                        acc[mt][nt][half*2+1]*OSCALE);
          *(u32*)(crh + cbase + nt*8) = *(u32*)&h;
        }
      } else if (mode == 1) {
        hlf* crh = Ch + (size_t)row*N;
        #pragma unroll
        for (int nt = 0; nt < 8; ++nt) {
          float gx = geluf(acc[mt][nt][half*2]*OSCALE) * ASCALE;
          float gy = geluf(acc[mt][nt][half*2+1]*OSCALE) * ASCALE;
          __half2 h = __floats2half2_rn(gx, gy);
          *(u32*)(crh + cbase + nt*8) = *(u32*)&h;
        }
      } else {
        float* cr = C + (size_t)row*N;
        #pragma unroll
        for (int nt = 0; nt < 8; ++nt) {
          int col = cbase + nt*8;
          float2 old = *(float2*)(cr + col);
          old.x += g[col]   * acc[mt][nt][half*2]  * OSCALE;
          old.y += g[col+1] * acc[mt][nt][half*2+1]* OSCALE;
          *(float2*)(cr + col) = old;
        }
      }
    }
  }
}

// ---------------- attention (fp16 qkv in, fp16 x16 out), poly-exp softmax ----------------
__global__ void __launch_bounds__(256) k_attn(const hlf* __restrict__ QKV,
                                              hlf* __restrict__ Oh)
{
  extern __shared__ float smf[];
  float* Ks = smf;                 // [256][64]
  float* Vs = smf + 256*64;        // [256][64]
  int hd = blockIdx.x, b = blockIdx.y;
  const hlf* base = QKV + (size_t)b*SEQ*3*Hd + hd*64;
  for (int i = threadIdx.x; i < 256*16; i += 256) {
    int r = i >> 4, d4 = (i & 15) << 2;
    uint2 kv = *(const uint2*)(base + (size_t)r*3*Hd + d4);
    float2 f0 = __half22float2(*(__half2*)&kv.x);
    float2 f1 = __half22float2(*(__half2*)&kv.y);
    *(float4*)&Ks[r*64 + d4] = make_float4(f0.x, f0.y, f1.x, f1.y);
    uint2 vv = *(const uint2*)(base + (size_t)r*3*Hd + 2*Hd + d4);
    float2 g0 = __half22float2(*(__half2*)&vv.x);
    float2 g1 = __half22float2(*(__half2*)&vv.y);
    *(float4*)&Vs[r*64 + d4] = make_float4(g0.x, g0.y, g1.x, g1.y);
  }
  int qi = threadIdx.x;
  float q[64];
  const hlf* qp = base + (size_t)qi*3*Hd + Hd;
  #pragma unroll
  for (int d = 0; d < 64; d += 2) {
    float2 f = __half22float2(*(const __half2*)(qp + d));
    q[d] = f.x*0.125f; q[d+1] = f.y*0.125f;
  }
  __syncthreads();
  float o[64];
  #pragma unroll
  for (int d = 0; d < 64; ++d) o[d] = 0.f;
  float m = -1e30f, l = 0.f;
  for (int kb = 0; kb < 256; kb += 16) {
    float s[16];
    float bm = -1e30f;
    #pragma unroll
    for (int kk = 0; kk < 16; ++kk) {
      const float* kr = &Ks[(kb+kk)*64];
      float t = 0.f;
      #pragma unroll
      for (int d = 0; d < 64; ++d) t += q[d]*kr[d];
      s[kk] = t;
      bm = fmaxf(bm, t);
    }
    float mn = fmaxf(m, bm);
    float corr = fexp(m - mn);
    l *= corr;
    #pragma unroll
    for (int d = 0; d < 64; ++d) o[d] *= corr;
    #pragma unroll
    for (int kk = 0; kk < 16; ++kk) {
      float p = fexp(s[kk] - mn);
      l += p;
      const float* vr = &Vs[(kb+kk)*64];
      #pragma unroll
      for (int d = 0; d < 64; ++d) o[d] += p*vr[d];
    }
    m = mn;
  }
  float inv = ASCALE / l;
  size_t ob = (size_t)(b*SEQ + qi)*Hd + hd*64;
  #pragma unroll
  for (int d = 0; d < 64; d += 2) {
    __half2 h = __floats2half2_rn(o[d]*inv, o[d+1]*inv);
    *(u32*)(Oh + ob + d) = *(u32*)&h;
  }
}

// ---------------- final: LN+modulate, @ out_W + b, unpatchify ----------------
__global__ void __launch_bounds__(256) k_out(const float* __restrict__ X,
                                             const float* __restrict__ cm2,
                                             const float* __restrict__ oW,
                                             const float* __restrict__ ob,
                                             float* __restrict__ out)
{
  int row = blockIdx.x, b = row >> 8, n = row & 255, tid = threadIdx.x;
  float4 v = *(const float4*)(X + (size_t)row*Hd + tid*4);
  float s = v.x + v.y + v.z + v.w;
  float s2 = v.x*v.x + v.y*v.y + v.z*v.z + v.w*v.w;
  #pragma unroll
  for (int o = 16; o; o >>= 1) {
    s  += __shfl_xor_sync(0xffffffffu, s,  o);
    s2 += __shfl_xor_sync(0xffffffffu, s2, o);
  }
  __shared__ float ss[8], ss2[8];
  if ((tid & 31) == 0) { ss[tid>>5] = s; ss2[tid>>5] = s2; }
  __syncthreads();
  s = 0.f; s2 = 0.f;
  #pragma unroll
  for (int w = 0; w < 8; ++w) { s += ss[w]; s2 += ss2[w]; }
  float mean = s*(1.f/1024.f), var = s2*(1.f/1024.f) - mean*mean;
  float r = rsqrtf(var + 1e-6f);
  __shared__ float xm[Hd];
  const float* c2 = cm2 + b*2*Hd;
  int c0 = tid*4;
  xm[c0+0] = (v.x-mean)*r*c2[Hd+c0+0] + c2[c0+0];
  xm[c0+1] = (v.y-mean)*r*c2[Hd+c0+1] + c2[c0+1];
  xm[c0+2] = (v.z-mean)*r*c2[Hd+c0+2] + c2[c0+2];
  xm[c0+3] = (v.w-mean)*r*c2[Hd+c0+3] + c2[c0+3];
  __syncthreads();
  int oi = tid >> 4, part = tid & 15;
  float acc = 0.f;
  const float* xp = xm + part*64;
  #pragma unroll
  for (int k = 0; k < 64; ++k) acc += xp[k]*oW[(part*64 + k)*16 + oi];
  __shared__ float red[256];
  red[tid] = acc;
  __syncthreads();
  if (part == 0) {
    float sum = 0.f;
    #pragma unroll
    for (int p = 0; p < 16; ++p) sum += red[oi*16 + p];
    sum += ob[oi];
    int ph = n >> 4, pw = n & 15;
    int p1 = oi >> 3, p2 = (oi >> 2) & 1, c = oi & 3;
    out[((b*32 + ph*2 + p1)*32 + (pw*2 + p2))*4 + c] = sum;
  }
}

// ---------------- host ----------------
extern "C" void kernel_launch(void* const* d_in, const int* in_sizes, int n_in,
                              void* d_out, int out_size)
{
  const float* x        = (const float*)d_in[0];
  const float* t        = (const float*)d_in[1];
  const int*   y        = (const int*)  d_in[2];
  const float* patch_W  = (const float*)d_in[3];
  const float* y_table  = (const float*)d_in[4];
  const float* t_W1     = (const float*)d_in[5];
  const float* t_W2     = (const float*)d_in[6];
  const float* adaln_W  = (const float*)d_in[7];
  const float* qkv_W    = (const float*)d_in[8];
  const float* proj_W   = (const float*)d_in[9];
  const float* mlp1_W   = (const float*)d_in[10];
  const float* mlp2_W   = (const float*)d_in[11];
  const float* out_mod_W= (const float*)d_in[12];
  const float* out_mod_b= (const float*)d_in[13];
  const float* out_W    = (const float*)d_in[14];
  const float* out_b    = (const float*)d_in[15];
  float* out = (float*)d_out;

  float *px, *pcm, *pcm2, *psc;
  hlf *pqkvh, *pxmh, *path, *pmh, *pWh;
  cudaGetSymbolAddress((void**)&px,    g_x);
  cudaGetSymbolAddress((void**)&pcm,   g_cm);
  cudaGetSymbolAddress((void**)&pcm2,  g_cm2);
  cudaGetSymbolAddress((void**)&psc,   g_sc);
  cudaGetSymbolAddress((void**)&pqkvh, g_qkvh);
  cudaGetSymbolAddress((void**)&pxmh,  g_xmh);
  cudaGetSymbolAddress((void**)&path,  g_ath);
  cudaGetSymbolAddress((void**)&pmh,   g_mh);
  cudaGetSymbolAddress((void**)&pWh,   g_Wh);

  cudaFuncSetAttribute(k_attn, cudaFuncAttributeMaxDynamicSharedMemorySize, 131072);
  cudaFuncSetAttribute(k_gemm, cudaFuncAttributeMaxDynamicSharedMemorySize, 3*BUFSZ);

  // weight conversion, batched over layers via grid.z
  k_wsplit<<<dim3(3*Hd/32, Hd/32, DEPTH), dim3(32,8)>>>(qkv_W,
      pWh + OFF_QKV,  Hd, 3*Hd, (size_t)Hd*3*Hd, PER_L);
  k_wsplit<<<dim3(Hd/32, Hd/32, DEPTH), dim3(32,8)>>>(proj_W,
      pWh + OFF_PROJ, Hd, Hd,   (size_t)Hd*Hd,   PER_L);
  k_wsplit<<<dim3(MHID/32, Hd/32, DEPTH), dim3(32,8)>>>(mlp1_W,
      pWh + OFF_MLP1, Hd, MHID, (size_t)Hd*MHID, PER_L);
  k_wsplit<<<dim3(Hd/32, MHID/32, DEPTH), dim3(32,8)>>>(mlp2_W,
      pWh + OFF_MLP2, MHID, Hd, (size_t)MHID*Hd, PER_L);

  k_patch <<<NROWS, 256>>>(x, patch_W, px);
  k_tembc <<<NB, 256>>>(t, t_W1, t_W2, y_table, y, psc);

  for (int L = 0; L < DEPTH; ++L) {
    size_t base = (size_t)L * PER_L;
    k_cond <<<dim3(6*Hd/256, NB), 256>>>(psc, adaln_W + (size_t)L*Hd*6*Hd, nullptr, pcm, 6*Hd);
    k_lnmod<<<NROWS, 256>>>(px, pxmh, pcm, 0, Hd);
    k_gemm <<<dim3(3*Hd/128, NROWS/256), 256, 3*BUFSZ>>>(pxmh,
        pWh + base + OFF_QKV, nullptr, pqkvh, Hd, 3*Hd, 0, nullptr);
    k_attn <<<dim3(16, NB), 256, 131072>>>(pqkvh, path);
    k_gemm <<<dim3(Hd/128, NROWS/256), 256, 3*BUFSZ>>>(path,
        pWh + base + OFF_PROJ, px, nullptr, Hd, Hd, 2, pcm + 2*Hd);
    k_lnmod<<<NROWS, 256>>>(px, pxmh, pcm, 3*Hd, 4*Hd);
    k_gemm <<<dim3(MHID/128, NROWS/256), 256, 3*BUFSZ>>>(pxmh,
        pWh + base + OFF_MLP1, nullptr, pmh, Hd, MHID, 1, nullptr);
    k_gemm <<<dim3(Hd/128, NROWS/256), 256, 3*BUFSZ>>>(pmh,
        pWh + base + OFF_MLP2, px, nullptr, MHID, Hd, 2, pcm + 5*Hd);
  }

  k_cond<<<dim3(2*Hd/256, NB), 256>>>(psc, out_mod_W, out_mod_b, pcm2, 2*Hd);
  k_out <<<NROWS, 256>>>(px, pcm2, out_W, out_b, out);
}

// round 17
// speedup vs baseline: 6.0582x; 1.3364x over previous
#include <cuda_runtime.h>
#include <cuda_fp16.h>
#include <math.h>

#define Hd    1024
#define SEQ   256
#define NB    32
#define NROWS (NB*SEQ)     // 8192
#define MHID  4096
#define DEPTH 12

typedef unsigned int u32;
typedef __half hlf;

// scales: weights x256, activations x16 -> acc = 4096 x true
#define WSCALE 256.0f
#define ASCALE 16.0f
#define OSCALE (1.0f/4096.0f)

// ---------------- device scratch (no allocations allowed) ----------------
__device__ float g_x   [NROWS*Hd];
__device__ float g_cm  [NB*6*Hd];
__device__ float g_cm2 [NB*2*Hd];
__device__ float g_sc  [NB*Hd];
// fp16 activations
__device__ hlf g_qkvh[NROWS*3*Hd];   // true values
__device__ hlf g_xmh [NROWS*Hd];     // x16
__device__ hlf g_ath [NROWS*Hd];     // x16
__device__ hlf g_mh  [NROWS*MHID];   // x16

// weight arena: per layer [N][K] fp16, scaled x256
#define PER_L   (12582912ULL)
#define OFF_QKV (0ULL)
#define OFF_PROJ (3145728ULL)
#define OFF_MLP1 (4194304ULL)
#define OFF_MLP2 (8388608ULL)
__device__ hlf g_Wh[PER_L*DEPTH];

__device__ __forceinline__ float geluf(float x){
  float t = 0.7978845608028654f * (x + 0.044715f * x*x*x);
  return x / (1.f + __expf(-2.f * t));
}
// fast exp for x <= 0 (softmax): 2^n * poly(f), no MUFU
__device__ __forceinline__ float fexp(float x){
  float t = fmaxf(x * 1.44269504089f, -100.f);
  int n = __float2int_rn(t);
  float f = t - (float)n;
  float p = 1.333355815e-3f;
  p = p*f + 9.618129107e-3f;
  p = p*f + 5.550410866e-2f;
  p = p*f + 2.402265069e-1f;
  p = p*f + 6.931471806e-1f;
  p = p*f + 1.0f;
  return __int_as_float(__float_as_int(p) + (n << 23));
}
__device__ __forceinline__ u32 s2u(const void* p){
  u32 a;
  asm("{ .reg .u64 t; cvta.to.shared.u64 t, %1; cvt.u32.u64 %0, t; }" : "=r"(a) : "l"(p));
  return a;
}
__device__ __forceinline__ void mma16816(float* c, const u32* a, const u32* b){
  asm volatile("mma.sync.aligned.m16n8k16.row.col.f32.f16.f16.f32 "
    "{%0,%1,%2,%3},{%4,%5,%6,%7},{%8,%9},{%0,%1,%2,%3};"
    : "+f"(c[0]), "+f"(c[1]), "+f"(c[2]), "+f"(c[3])
    : "r"(a[0]), "r"(a[1]), "r"(a[2]), "r"(a[3]), "r"(b[0]), "r"(b[1]));
}
__device__ __forceinline__ void ldsm4(u32* r, u32 addr){
  asm volatile("ldmatrix.sync.aligned.m8n8.x4.shared.b16 {%0,%1,%2,%3}, [%4];"
    : "=r"(r[0]), "=r"(r[1]), "=r"(r[2]), "=r"(r[3]) : "r"(addr));
}
__device__ __forceinline__ void ldsm4t(u32* r, u32 addr){
  asm volatile("ldmatrix.sync.aligned.m8n8.x4.trans.shared.b16 {%0,%1,%2,%3}, [%4];"
    : "=r"(r[0]), "=r"(r[1]), "=r"(r[2]), "=r"(r[3]) : "r"(addr));
}
__device__ __forceinline__ void cp16(u32 dst, const void* src){
  asm volatile("cp.async.cg.shared.global [%0], [%1], 16;" :: "r"(dst), "l"(src) : "memory");
}
__device__ __forceinline__ void cp_commit(){ asm volatile("cp.async.commit_group;" ::: "memory"); }

// ---------------- weight convert + transpose (all layers, grid.z) ----------------
__global__ void __launch_bounds__(256) k_wsplit(const float* __restrict__ W,
                                                hlf* __restrict__ Wh,
                                                int K, int N, size_t wstride, size_t dstride)
{
  __shared__ float tile[32][33];
  int tx = threadIdx.x, ty = threadIdx.y;
  int n0 = blockIdx.x*32, k0 = blockIdx.y*32;
  const float* Wp = W + (size_t)blockIdx.z*wstride;
  hlf* Whp = Wh + (size_t)blockIdx.z*dstride;
  #pragma unroll
  for (int i = 0; i < 4; ++i)
    tile[ty + i*8][tx] = Wp[(size_t)(k0 + ty + i*8)*N + n0 + tx];
  __syncthreads();
  #pragma unroll
  for (int i = 0; i < 4; ++i) {
    float v = tile[tx][ty + i*8] * WSCALE;
    Whp[(size_t)(n0 + ty + i*8)*K + k0 + tx] = __float2half_rn(v);
  }
}

// ---------------- patch embed + 2D sincos pos ----------------
__global__ void __launch_bounds__(256) k_patch(const float* __restrict__ x,
                                               const float* __restrict__ pW,
                                               float* __restrict__ XT)
{
  int row = blockIdx.x;
  int b = row >> 8, n = row & 255;
  int ph = n >> 4, pw = n & 15;
  __shared__ float xp[16];
  if (threadIdx.x < 16) {
    int f = threadIdx.x;
    int dy = f >> 3, dx = (f >> 2) & 1, c = f & 3;
    xp[f] = x[((b*32 + ph*2 + dy)*32 + (pw*2 + dx))*4 + c];
  }
  __syncthreads();
  #pragma unroll
  for (int i = 0; i < 4; ++i) {
    int col = threadIdx.x + i*256;
    float acc = 0.f;
    #pragma unroll
    for (int k = 0; k < 16; ++k) acc += xp[k] * pW[k*Hd + col];
    int j = col & 255, seg = col >> 8;
    float fr = expf(-logf(10000.f) * (float)j * (1.f/256.f));
    float a  = (seg < 2 ? (float)pw : (float)ph) * fr;
    float pos = ((seg & 1) == 0) ? sinf(a) : cosf(a);
    XT[(size_t)row*Hd + col] = acc + pos;
  }
}

// ---------------- fused timestep embed + conditioning vector ----------------
__global__ void __launch_bounds__(256) k_tembc(const float* __restrict__ t,
                                               const float* __restrict__ W1,
                                               const float* __restrict__ W2,
                                               const float* __restrict__ ytab,
                                               const int* __restrict__ y,
                                               float* __restrict__ SCout)
{
  int b = blockIdx.x, tid = threadIdx.x;
  __shared__ float e[256];
  __shared__ float te[Hd];
  {
    int j = tid & 127;
    float fr = expf(-logf(10000.f) * (float)j * (1.f/128.f));
    float a = t[b] * fr;
    e[tid] = (tid < 128 ? cosf(a) : sinf(a)) * 1.41421356237f;
  }
  __syncthreads();
  #pragma unroll
  for (int i = 0; i < 4; ++i) {
    int col = tid + i*256;
    float acc = 0.f;
    for (int k = 0; k < 256; ++k) acc += e[k] * W1[k*Hd + col];
    te[col] = acc / (1.f + expf(-acc));
  }
  __syncthreads();
  int yi = y[b];
  #pragma unroll
  for (int i = 0; i < 4; ++i) {
    int col = tid + i*256;
    float acc = 0.f;
    for (int k = 0; k < Hd; ++k) acc += te[k] * W2[k*Hd + col];
    float c = acc + ytab[(size_t)yi*Hd + col];
    SCout[b*Hd + col] = c / (1.f + expf(-c));
  }
}

// ---------------- conditioning GEMM: one CTA per (batch, 256 cols) ----------------
__global__ void __launch_bounds__(256) k_cond(const float* __restrict__ SC,
                                              const float* __restrict__ W,
                                              const float* __restrict__ bias,
                                              float* __restrict__ OUT, int N)
{
  __shared__ float a[Hd];
  int tid = threadIdx.x, b = blockIdx.y;
  {
    float4 v = *(const float4*)(SC + (size_t)b*Hd + tid*4);
    *(float4*)(a + tid*4) = v;
  }
  __syncthreads();
  int c = blockIdx.x*256 + tid;
  const float* wp = W + c;
  float acc = 0.f;
  #pragma unroll 8
  for (int k = 0; k < Hd; ++k)
    acc += a[k] * wp[(size_t)k*N];
  OUT[(size_t)b*N + c] = acc + (bias ? bias[c] : 0.f);
}

// ---------------- LN + modulate -> fp16 (x16) ----------------
__global__ void __launch_bounds__(256) k_lnmod(const float* __restrict__ X,
                                               hlf* __restrict__ Yh,
                                               const float* __restrict__ cm,
                                               int shOff, int scOff)
{
  int row = blockIdx.x, b = row >> 8, tid = threadIdx.x;
  float4 v = *(const float4*)(X + (size_t)row*Hd + tid*4);
  float s = v.x + v.y + v.z + v.w;
  float s2 = v.x*v.x + v.y*v.y + v.z*v.z + v.w*v.w;
  #pragma unroll
  for (int o = 16; o; o >>= 1) {
    s  += __shfl_xor_sync(0xffffffffu, s,  o);
    s2 += __shfl_xor_sync(0xffffffffu, s2, o);
  }
  __shared__ float ss[8], ss2[8];
  if ((tid & 31) == 0) { ss[tid>>5] = s; ss2[tid>>5] = s2; }
  __syncthreads();
  s = 0.f; s2 = 0.f;
  #pragma unroll
  for (int w = 0; w < 8; ++w) { s += ss[w]; s2 += ss2[w]; }
  float mean = s * (1.f/1024.f);
  float var  = s2 * (1.f/1024.f) - mean*mean;
  float r = rsqrtf(var + 1e-6f);
  const float* cb = cm + b*6*Hd;
  int c0 = tid*4;
  float m0 = ((v.x-mean)*r*cb[scOff+c0+0] + cb[shOff+c0+0]) * ASCALE;
  float m1 = ((v.y-mean)*r*cb[scOff+c0+1] + cb[shOff+c0+1]) * ASCALE;
  float m2 = ((v.z-mean)*r*cb[scOff+c0+2] + cb[shOff+c0+2]) * ASCALE;
  float m3 = ((v.w-mean)*r*cb[scOff+c0+3] + cb[shOff+c0+3]) * ASCALE;
  __half2 h0 = __floats2half2_rn(m0, m1);
  __half2 h1 = __floats2half2_rn(m2, m3);
  *(uint2*)(Yh + (size_t)row*Hd + c0) = make_uint2(*(u32*)&h0, *(u32*)&h1);
}

// ---------------- fp16 mma.sync GEMM, tile 256x128, 3-stage pipeline ----------------
// acc = A @ B, scaled 4096x
// mode 0: Ch=f16(acc/4096)  1: Ch=f16(gelu(acc/4096)*16)  2: C += gate*(acc/4096)
#define ROWB   144              // padded row stride bytes (72 halves)
#define AMATSZ (256*ROWB)       // 36864 B
#define BMATSZ (128*ROWB)       // 18432 B
#define BUFSZ  (AMATSZ+BMATSZ)  // 55296 B
__global__ void __launch_bounds__(256) k_gemm(const hlf* __restrict__ Ah0,
                                              const hlf* __restrict__ Wh,
                                              float* __restrict__ C,
                                              hlf* __restrict__ Ch,
                                              int K, int N,
                                              int mode, const float* __restrict__ gate)
{
  extern __shared__ __align__(128) char smem[];
  const int tid = threadIdx.x, lane = tid & 31, wid = tid >> 5;
  const u32 sb = s2u(smem);

  const int mbase = (wid & 3) * 64;    // 4 M-warps x 64 rows
  const int nbase = (wid >> 2) * 64;   // 2 N-warps x 64 cols
  const int grp = lane >> 3, lr = lane & 7;
  const u32 aOff = (u32)(mbase + (grp & 1)*8 + lr) * ROWB + (grp >> 1)*16;
  const u32 bOff = (u32)(nbase + (grp >> 1)*8 + lr) * ROWB + (grp & 1)*16;

  const hlf* Ahg = Ah0 + (size_t)blockIdx.y * 256 * K;
  const hlf* Bhg = Wh  + (size_t)blockIdx.x * 128 * K;
  const int nk = K >> 6;

  float acc[4][8][4];
  #pragma unroll
  for (int i = 0; i < 4; ++i)
    #pragma unroll
    for (int j = 0; j < 8; ++j)
      #pragma unroll
      for (int q = 0; q < 4; ++q) acc[i][j][q] = 0.f;

  const int lr8 = tid >> 3, lc8 = (tid & 7) << 3;
  auto cpAll = [&](int kt, int buf){
    u32 base = sb + buf*BUFSZ;
    #pragma unroll
    for (int i = 0; i < 8; ++i) {            // A: 256 rows
      int r = lr8 + i*32;
      cp16(base + (u32)r*ROWB + lc8*2, Ahg + (size_t)r*K + (kt << 6) + lc8);
    }
    #pragma unroll
    for (int i = 0; i < 4; ++i) {            // B: 128 rows
      int r = lr8 + i*32;
      cp16(base + AMATSZ + (u32)r*ROWB + lc8*2, Bhg + (size_t)r*K + (kt << 6) + lc8);
    }
    cp_commit();
  };

  cpAll(0, 0);
  cpAll(1, 1);
  asm volatile("cp.async.wait_group 1;" ::: "memory");
  __syncthreads();

  for (int c = 0; c < nk; ++c) {
    int buf = c % 3;
    if (c + 2 < nk) cpAll(c + 2, (c + 2) % 3);

    u32 baseA = sb + buf*BUFSZ;
    u32 baseB = baseA + AMATSZ;
    #pragma unroll
    for (int ks = 0; ks < 4; ++ks) {
      u32 ah[4][4], bh[8][2];
      #pragma unroll
      for (int mt = 0; mt < 4; ++mt)
        ldsm4(ah[mt], baseA + aOff + mt*(16*ROWB) + ks*32);
      #pragma unroll
      for (int np = 0; np < 4; ++np) {
        u32 r4[4];
        ldsm4(r4, baseB + bOff + np*(16*ROWB) + ks*32);
        bh[np*2][0]   = r4[0]; bh[np*2][1]   = r4[1];
        bh[np*2+1][0] = r4[2]; bh[np*2+1][1] = r4[3];
      }
      #pragma unroll
      for (int mt = 0; mt < 4; ++mt)
        #pragma unroll
        for (int nt = 0; nt < 8; ++nt)
          mma16816(acc[mt][nt], ah[mt], bh[nt]);
    }

    if (c + 1 < nk) {
      if (c + 2 < nk) asm volatile("cp.async.wait_group 1;" ::: "memory");
      else            asm volatile("cp.async.wait_group 0;" ::: "memory");
      __syncthreads();
    }
  }

  // epilogue: batch index == blockIdx.y (256 rows per batch per CTA)
  int rbase = blockIdx.y*256 + mbase + (lane >> 2);
  int cbase = blockIdx.x*128 + nbase + (lane & 3)*2;
  const float* g = (mode == 2) ? (gate + (size_t)blockIdx.y*6*Hd) : nullptr;
  #pragma unroll
  for (int mt = 0; mt < 4; ++mt) {
    #pragma unroll
    for (int half = 0; half < 2; ++half) {
      int row = rbase + mt*16 + half*8;
      if (mode == 0) {
        hlf* crh = Ch + (size_t)row*N;
        #pragma unroll
        for (int nt = 0; nt < 8; ++nt) {
          __half2 h = __floats2half2_rn(acc[mt][nt][half*2]*OSCALE,
                                        acc[mt][nt][half*2+1]*OSCALE);
          *(u32*)(crh + cbase + nt*8) = *(u32*)&h;
        }
      } else if (mode == 1) {
        hlf* crh = Ch + (size_t)row*N;
        #pragma unroll
        for (int nt = 0; nt < 8; ++nt) {
          float gx = geluf(acc[mt][nt][half*2]*OSCALE) * ASCALE;
          float gy = geluf(acc[mt][nt][half*2+1]*OSCALE) * ASCALE;
          __half2 h = __floats2half2_rn(gx, gy);
          *(u32*)(crh + cbase + nt*8) = *(u32*)&h;
        }
      } else {
        float* cr = C + (size_t)row*N;
        #pragma unroll
        for (int nt = 0; nt < 8; ++nt) {
          int col = cbase + nt*8;
          float2 old = *(float2*)(cr + col);
          old.x += g[col]   * acc[mt][nt][half*2]  * OSCALE;
          old.y += g[col+1] * acc[mt][nt][half*2+1]* OSCALE;
          *(float2*)(cr + col) = old;
        }
      }
    }
  }
}

// ---------------- tensor-core flash attention ----------------
// one CTA per (head, batch); 8 warps x 32 q-rows; K/V/Q fp16 in smem.
#define AROWB 144
#define AKOFF 0
#define AVOFF (256*AROWB)
#define AQOFF (2*256*AROWB)
#define ASMEM (3*256*AROWB)     // 110592 B
__global__ void __launch_bounds__(256) k_attn(const hlf* __restrict__ QKV,
                                              hlf* __restrict__ Oh)
{
  extern __shared__ __align__(128) char smA[];
  const u32 sb = s2u(smA);
  const int tid = threadIdx.x, lane = tid & 31, w = tid >> 5;
  const int hd = blockIdx.x, b = blockIdx.y;
  const hlf* base = QKV + (size_t)b*SEQ*3*Hd + hd*64;

  // K, V via cp.async; Q scaled by 1/8 manually
  #pragma unroll
  for (int i = 0; i < 8; ++i) {
    int idx = tid + i*256;              // 0..2047
    int r = idx >> 3, c = (idx & 7) << 3;
    cp16(sb + AKOFF + (u32)r*AROWB + c*2, base + (size_t)r*3*Hd + c);
    cp16(sb + AVOFF + (u32)r*AROWB + c*2, base + (size_t)r*3*Hd + 2*Hd + c);
  }
  cp_commit();
  const __half2 qs = __half2half2(__float2half(0.125f));
  #pragma unroll
  for (int i = 0; i < 8; ++i) {
    int idx = tid + i*256;
    int r = idx >> 3, c = (idx & 7) << 3;
    uint4 v = *(const uint4*)(base + (size_t)r*3*Hd + Hd + c);
    __half2* hp = (__half2*)&v;
    hp[0] = __hmul2(hp[0], qs); hp[1] = __hmul2(hp[1], qs);
    hp[2] = __hmul2(hp[2], qs); hp[3] = __hmul2(hp[3], qs);
    *(uint4*)(smA + AQOFF + (u32)r*AROWB + c*2) = v;
  }
  asm volatile("cp.async.wait_group 0;" ::: "memory");
  __syncthreads();

  const int grp = lane >> 3, lr = lane & 7;
  // Q fragments (persist across key blocks): rows w*32 + mt*16
  u32 qf[2][4][4];
  {
    u32 aO = sb + AQOFF + (u32)(w*32 + (grp & 1)*8 + lr)*AROWB + (grp >> 1)*16;
    #pragma unroll
    for (int mt = 0; mt < 2; ++mt)
      #pragma unroll
      for (int ks = 0; ks < 4; ++ks)
        ldsm4(qf[mt][ks], aO + mt*(16*AROWB) + ks*32);
  }

  float o[2][8][4];
  #pragma unroll
  for (int mt = 0; mt < 2; ++mt)
    #pragma unroll
    for (int nt = 0; nt < 8; ++nt)
      #pragma unroll
      for (int q = 0; q < 4; ++q) o[mt][nt][q] = 0.f;
  float mx[4] = {-1e30f, -1e30f, -1e30f, -1e30f};
  float lsum[4] = {0.f, 0.f, 0.f, 0.f};

  for (int kb = 0; kb < 4; ++kb) {
    // ---- scores S = Q @ K^T for 64 keys ----
    float s[2][8][4];
    #pragma unroll
    for (int mt = 0; mt < 2; ++mt)
      #pragma unroll
      for (int nt = 0; nt < 8; ++nt)
        #pragma unroll
        for (int q = 0; q < 4; ++q) s[mt][nt][q] = 0.f;
    u32 bOffK = sb + AKOFF + (u32)(kb*64 + (grp >> 1)*8 + lr)*AROWB + (grp & 1)*16;
    #pragma unroll
    for (int ks = 0; ks < 4; ++ks) {
      u32 bf[8][2];
      #pragma unroll
      for (int np = 0; np < 4; ++np) {
        u32 r4[4];
        ldsm4(r4, bOffK + np*(16*AROWB) + ks*32);
        bf[np*2][0]   = r4[0]; bf[np*2][1]   = r4[1];
        bf[np*2+1][0] = r4[2]; bf[np*2+1][1] = r4[3];
      }
      #pragma unroll
      for (int mt = 0; mt < 2; ++mt)
        #pragma unroll
        for (int nt = 0; nt < 8; ++nt)
          mma16816(s[mt][nt], qf[mt][ks], bf[nt]);
    }
    // ---- online softmax (rows: lane>>2 (+8); row-instance si = mt*2+hf) ----
    #pragma unroll
    for (int mt = 0; mt < 2; ++mt) {
      #pragma unroll
      for (int hf = 0; hf < 2; ++hf) {
        int si = mt*2 + hf;
        float mloc = -1e30f;
        #pragma unroll
        for (int nt = 0; nt < 8; ++nt)
          mloc = fmaxf(mloc, fmaxf(s[mt][nt][hf*2], s[mt][nt][hf*2+1]));
        mloc = fmaxf(mloc, __shfl_xor_sync(0xffffffffu, mloc, 1));
        mloc = fmaxf(mloc, __shfl_xor_sync(0xffffffffu, mloc, 2));
        float mnew = fmaxf(mx[si], mloc);
        float corr = fexp(mx[si] - mnew);
        mx[si] = mnew;
        lsum[si] *= corr;
        #pragma unroll
        for (int nt = 0; nt < 8; ++nt) { o[mt][nt][hf*2] *= corr; o[mt][nt][hf*2+1] *= corr; }
        float ps = 0.f;
        #pragma unroll
        for (int nt = 0; nt < 8; ++nt) {
          float p0 = fexp(s[mt][nt][hf*2]   - mnew);
          float p1 = fexp(s[mt][nt][hf*2+1] - mnew);
          s[mt][nt][hf*2] = p0; s[mt][nt][hf*2+1] = p1;
          ps += p0 + p1;
        }
        lsum[si] += ps;      // per-lane partial; reduced across lanes at the end
      }
    }
    // ---- O += P @ V ----
    #pragma unroll
    for (int ks2 = 0; ks2 < 4; ++ks2) {
      u32 pa[2][4];
      #pragma unroll
      for (int mt = 0; mt < 2; ++mt) {
        __half2 t0 = __floats2half2_rn(s[mt][ks2*2][0],   s[mt][ks2*2][1]);
        __half2 t1 = __floats2half2_rn(s[mt][ks2*2][2],   s[mt][ks2*2][3]);
        __half2 t2 = __floats2half2_rn(s[mt][ks2*2+1][0], s[mt][ks2*2+1][1]);
        __half2 t3 = __floats2half2_rn(s[mt][ks2*2+1][2], s[mt][ks2*2+1][3]);
        pa[mt][0] = *(u32*)&t0; pa[mt][1] = *(u32*)&t1;
        pa[mt][2] = *(u32*)&t2; pa[mt][3] = *(u32*)&t3;
      }
      u32 vO = sb + AVOFF + (u32)(kb*64 + ks2*16 + (lane & 15))*AROWB + (lane >> 4)*16;
      #pragma unroll
      for (int dt = 0; dt < 4; ++dt) {
        u32 r4[4];
        ldsm4t(r4, vO + dt*32);
        u32 b0[2] = {r4[0], r4[1]};
        u32 b1[2] = {r4[2], r4[3]};
        #pragma unroll
        for (int mt = 0; mt < 2; ++mt) {
          mma16816(o[mt][dt*2],   pa[mt], b0);
          mma16816(o[mt][dt*2+1], pa[mt], b1);
        }
      }
    }
  }

  // ---- finalize: reduce l across the 4 lanes of each row, write fp16 x16 ----
  float inv[4];
  #pragma unroll
  for (int si = 0; si < 4; ++si) {
    float l = lsum[si];
    l += __shfl_xor_sync(0xffffffffu, l, 1);
    l += __shfl_xor_sync(0xffffffffu, l, 2);
    inv[si] = ASCALE / l;
  }
  #pragma unroll
  for (int mt = 0; mt < 2; ++mt) {
    #pragma unroll
    for (int hf = 0; hf < 2; ++hf) {
      int r = w*32 + mt*16 + hf*8 + (lane >> 2);
      float iv = inv[mt*2 + hf];
      hlf* op = Oh + (size_t)(b*SEQ + r)*Hd + hd*64 + (lane & 3)*2;
      #pragma unroll
      for (int nt = 0; nt < 8; ++nt) {
        __half2 h = __floats2half2_rn(o[mt][nt][hf*2]*iv, o[mt][nt][hf*2+1]*iv);
        *(u32*)(op + nt*8) = *(u32*)&h;
      }
    }
  }
}

// ---------------- final: LN+modulate, @ out_W + b, unpatchify ----------------
__global__ void __launch_bounds__(256) k_out(const float* __restrict__ X,
                                             const float* __restrict__ cm2,
                                             const float* __restrict__ oW,
                                             const float* __restrict__ ob,
                                             float* __restrict__ out)
{
  int row = blockIdx.x, b = row >> 8, n = row & 255, tid = threadIdx.x;
  float4 v = *(const float4*)(X + (size_t)row*Hd + tid*4);
  float s = v.x + v.y + v.z + v.w;
  float s2 = v.x*v.x + v.y*v.y + v.z*v.z + v.w*v.w;
  #pragma unroll
  for (int o = 16; o; o >>= 1) {
    s  += __shfl_xor_sync(0xffffffffu, s,  o);
    s2 += __shfl_xor_sync(0xffffffffu, s2, o);
  }
  __shared__ float ss[8], ss2[8];
  if ((tid & 31) == 0) { ss[tid>>5] = s; ss2[tid>>5] = s2; }
  __syncthreads();
  s = 0.f; s2 = 0.f;
  #pragma unroll
  for (int w = 0; w < 8; ++w) { s += ss[w]; s2 += ss2[w]; }
  float mean = s*(1.f/1024.f), var = s2*(1.f/1024.f) - mean*mean;
  float r = rsqrtf(var + 1e-6f);
  __shared__ float xm[Hd];
  const float* c2 = cm2 + b*2*Hd;
  int c0 = tid*4;
  xm[c0+0] = (v.x-mean)*r*c2[Hd+c0+0] + c2[c0+0];
  xm[c0+1] = (v.y-mean)*r*c2[Hd+c0+1] + c2[c0+1];
  xm[c0+2] = (v.z-mean)*r*c2[Hd+c0+2] + c2[c0+2];
  xm[c0+3] = (v.w-mean)*r*c2[Hd+c0+3] + c2[c0+3];
  __syncthreads();
  int oi = tid >> 4, part = tid & 15;
  float acc = 0.f;
  const float* xp = xm + part*64;
  #pragma unroll
  for (int k = 0; k < 64; ++k) acc += xp[k]*oW[(part*64 + k)*16 + oi];
  __shared__ float red[256];
  red[tid] = acc;
  __syncthreads();
  if (part == 0) {
    float sum = 0.f;
    #pragma unroll
    for (int p = 0; p < 16; ++p) sum += red[oi*16 + p];
    sum += ob[oi];
    int ph = n >> 4, pw = n & 15;
    int p1 = oi >> 3, p2 = (oi >> 2) & 1, c = oi & 3;
    out[((b*32 + ph*2 + p1)*32 + (pw*2 + p2))*4 + c] = sum;
  }
}

// ---------------- host ----------------
extern "C" void kernel_launch(void* const* d_in, const int* in_sizes, int n_in,
                              void* d_out, int out_size)
{
  const float* x        = (const float*)d_in[0];
  const float* t        = (const float*)d_in[1];
  const int*   y        = (const int*)  d_in[2];
  const float* patch_W  = (const float*)d_in[3];
  const float* y_table  = (const float*)d_in[4];
  const float* t_W1     = (const float*)d_in[5];
  const float* t_W2     = (const float*)d_in[6];
  const float* adaln_W  = (const float*)d_in[7];
  const float* qkv_W    = (const float*)d_in[8];
  const float* proj_W   = (const float*)d_in[9];
  const float* mlp1_W   = (const float*)d_in[10];
  const float* mlp2_W   = (const float*)d_in[11];
  const float* out_mod_W= (const float*)d_in[12];
  const float* out_mod_b= (const float*)d_in[13];
  const float* out_W    = (const float*)d_in[14];
  const float* out_b    = (const float*)d_in[15];
  float* out = (float*)d_out;

  float *px, *pcm, *pcm2, *psc;
  hlf *pqkvh, *pxmh, *path, *pmh, *pWh;
  cudaGetSymbolAddress((void**)&px,    g_x);
  cudaGetSymbolAddress((void**)&pcm,   g_cm);
  cudaGetSymbolAddress((void**)&pcm2,  g_cm2);
  cudaGetSymbolAddress((void**)&psc,   g_sc);
  cudaGetSymbolAddress((void**)&pqkvh, g_qkvh);
  cudaGetSymbolAddress((void**)&pxmh,  g_xmh);
  cudaGetSymbolAddress((void**)&path,  g_ath);
  cudaGetSymbolAddress((void**)&pmh,   g_mh);
  cudaGetSymbolAddress((void**)&pWh,   g_Wh);

  cudaFuncSetAttribute(k_attn, cudaFuncAttributeMaxDynamicSharedMemorySize, ASMEM);
  cudaFuncSetAttribute(k_gemm, cudaFuncAttributeMaxDynamicSharedMemorySize, 3*BUFSZ);

  // weight conversion, batched over layers via grid.z
  k_wsplit<<<dim3(3*Hd/32, Hd/32, DEPTH), dim3(32,8)>>>(qkv_W,
      pWh + OFF_QKV,  Hd, 3*Hd, (size_t)Hd*3*Hd, PER_L);
  k_wsplit<<<dim3(Hd/32, Hd/32, DEPTH), dim3(32,8)>>>(proj_W,
      pWh + OFF_PROJ, Hd, Hd,   (size_t)Hd*Hd,   PER_L);
  k_wsplit<<<dim3(MHID/32, Hd/32, DEPTH), dim3(32,8)>>>(mlp1_W,
      pWh + OFF_MLP1, Hd, MHID, (size_t)Hd*MHID, PER_L);
  k_wsplit<<<dim3(Hd/32, MHID/32, DEPTH), dim3(32,8)>>>(mlp2_W,
      pWh + OFF_MLP2, MHID, Hd, (size_t)MHID*Hd, PER_L);

  k_patch <<<NROWS, 256>>>(x, patch_W, px);
  k_tembc <<<NB, 256>>>(t, t_W1, t_W2, y_table, y, psc);

  for (int L = 0; L < DEPTH; ++L) {
    size_t base = (size_t)L * PER_L;
    k_cond <<<dim3(6*Hd/256, NB), 256>>>(psc, adaln_W + (size_t)L*Hd*6*Hd, nullptr, pcm, 6*Hd);
    k_lnmod<<<NROWS, 256>>>(px, pxmh, pcm, 0, Hd);
    k_gemm <<<dim3(3*Hd/128, NROWS/256), 256, 3*BUFSZ>>>(pxmh,
        pWh + base + OFF_QKV, nullptr, pqkvh, Hd, 3*Hd, 0, nullptr);
    k_attn <<<dim3(16, NB), 256, ASMEM>>>(pqkvh, path);
    k_gemm <<<dim3(Hd/128, NROWS/256), 256, 3*BUFSZ>>>(path,
        pWh + base + OFF_PROJ, px, nullptr, Hd, Hd, 2, pcm + 2*Hd);
    k_lnmod<<<NROWS, 256>>>(px, pxmh, pcm, 3*Hd, 4*Hd);
    k_gemm <<<dim3(MHID/128, NROWS/256), 256, 3*BUFSZ>>>(pxmh,
        pWh + base + OFF_MLP1, nullptr, pmh, Hd, MHID, 1, nullptr);
    k_gemm <<<dim3(Hd/128, NROWS/256), 256, 3*BUFSZ>>>(pmh,
        pWh + base + OFF_MLP2, px, nullptr, MHID, Hd, 2, pcm + 5*Hd);
  }

  k_cond<<<dim3(2*Hd/256, NB), 256>>>(psc, out_mod_W, out_mod_b, pcm2, 2*Hd);
  k_out <<<NROWS, 256>>>(px, pcm2, out_W, out_b, out);
}